// round 2
// baseline (speedup 1.0000x reference)
#include <cuda_runtime.h>
#include <math.h>

typedef unsigned long long ull;

#define DI __device__ __forceinline__

DI ull pk2(float x, float y){ ull r; asm("mov.b64 %0,{%1,%2};" : "=l"(r) : "f"(x), "f"(y)); return r; }
DI void upk2(ull v, float& x, float& y){ asm("mov.b64 {%0,%1},%2;" : "=f"(x), "=f"(y) : "l"(v)); }
DI ull ffma2(ull a, ull b, ull c){ ull d; asm("fma.rn.f32x2 %0,%1,%2,%3;" : "=l"(d) : "l"(a), "l"(b), "l"(c)); return d; }

static constexpr int B    = 32;
static constexpr int L    = 128;
static constexpr int H    = 1024;
static constexpr int EN   = 256;
static constexpr int ET   = 512;
static constexpr int EIN  = 768;     // EN + ET
static constexpr int G4   = 4096;    // 4*H
static constexpr int VOUT = 50003;
static constexpr int LOGN = VOUT + L;       // 50131
static constexpr int F3   = 3072;           // 3*H
static constexpr int NLOG = B * LOGN;       // logits elements
static constexpr int NCHUNK = 49;           // ceil(50003/1024)

// ---------------- scratch (static device memory; no allocations) ----------------
__device__ __align__(16) float g_xhT[(EIN + H) * B];   // [k][b]: emb-concat then h0
__device__ __align__(16) float g_featT[F3 * B];        // [k][b]: context | h_new | h_parent
__device__ __align__(16) float g_gates[G4 * B];        // [j][b]
__device__ __align__(16) float g_qT[H * B];            // [j][b]
__device__ __align__(16) float g_scores[B * L];
__device__ float g_lse[B];
__device__ __align__(16) float g_context[B * H];
__device__ float g_sB[B];
__device__ float g_l1m[B];
__device__ __align__(16) float g_wgout[(VOUT + 32) * B]; // [v][b]
__device__ float g_pmax[NCHUNK * 32];
__device__ float g_psum[NCHUNK * 32];
__device__ float g_wlse[B];

// ---------------- K1: embeddings + transposed staging + score init ----------------
__global__ void k1_prep(const int* __restrict__ n_in, const int* __restrict__ t_in,
                        const float* __restrict__ h0, const float* __restrict__ h_parent,
                        const float* __restrict__ embN, const float* __restrict__ embT,
                        const float* __restrict__ v_b) {
    int b = blockIdx.x;
    int t = threadIdx.x;
    int n  = n_in[b];
    int tt = t_in[b];
    for (int k = t; k < EIN; k += blockDim.x) {
        float v = (k < EN) ? embN[n * EN + k] : embT[(size_t)tt * ET + (k - EN)];
        g_xhT[k * B + b] = v;
    }
    for (int k = t; k < H; k += blockDim.x) {
        g_xhT[(EIN + k) * B + b]     = h0[b * H + k];
        g_featT[(2 * H + k) * B + b] = h_parent[b * H + k];
    }
    if (t < L) g_scores[b * L + t] = v_b[0];
}

// ---------------- generic blocked GEMM: out[row][b] = sum_k A[row][k] * Bmat[k][b] ----------------
// 128 threads, BK=32, per-thread R=BM/16 rows x 4 batches, fma.f32x2 with duplicated-A smem.
// Supports two concatenated A segments (for LSTM: W_ih then W_hh against stacked Bmat).
template<int BM, bool CLAMP>
DI void gemm_accum(const float* __restrict__ A, int ldA, int kBlocks,
                   const float* __restrict__ Bmat, int rows, int r0, int tid,
                   float* AsD, float* Bs, ull (*acc)[2], int tm0, int tb0) {
    constexpr int R = BM / 16;
    for (int kb = 0; kb < kBlocks; kb++) {
        int k0 = kb * 32;
#pragma unroll
        for (int i = 0; i < R; i++) {
            int idx = i * 128 + tid;
            int row = idx >> 3, c4 = idx & 7;
            int rr = r0 + row;
            if (CLAMP && rr > rows - 1) rr = rows - 1;
            float4 v = *(const float4*)&A[(size_t)rr * ldA + k0 + 4 * c4];
            float* p = &AsD[(4 * c4) * (2 * BM) + 2 * row];
            p[0] = v.x;           p[1] = v.x;
            p[2 * BM] = v.y;      p[2 * BM + 1] = v.y;
            p[4 * BM] = v.z;      p[4 * BM + 1] = v.z;
            p[6 * BM] = v.w;      p[6 * BM + 1] = v.w;
        }
#pragma unroll
        for (int i = 0; i < 2; i++) {
            int idx = i * 128 + tid;
            ((float4*)Bs)[idx] = ((const float4*)(Bmat + k0 * 32))[idx];
        }
        __syncthreads();
#pragma unroll 8
        for (int k = 0; k < 32; k++) {
            ulonglong2 b2 = *(const ulonglong2*)&Bs[k * 32 + tb0];
#pragma unroll
            for (int i = 0; i < R; i++) {
                ull a2 = *(const ull*)&AsD[k * 2 * BM + 2 * (tm0 + i)];
                acc[i][0] = ffma2(a2, b2.x, acc[i][0]);
                acc[i][1] = ffma2(a2, b2.y, acc[i][1]);
            }
        }
        __syncthreads();
    }
}

template<int BM, bool CLAMP>
__global__ void __launch_bounds__(128) gemm_k(const float* __restrict__ A1, int ldA1, int kb1,
                                              const float* __restrict__ A2, int ldA2, int kb2,
                                              const float* __restrict__ Bmat,
                                              const float* __restrict__ bias1,
                                              const float* __restrict__ bias2,
                                              float* __restrict__ outT, int rows) {
    constexpr int R = BM / 16;
    __shared__ __align__(16) float AsD[32 * 2 * BM];
    __shared__ __align__(16) float Bs[32 * 32];
    int tid = threadIdx.x;
    int r0 = blockIdx.x * BM;
    int tm0 = (tid >> 3) * R;
    int tb0 = (tid & 7) * 4;
    ull acc[R][2];
    ull z = pk2(0.f, 0.f);
#pragma unroll
    for (int i = 0; i < R; i++) { acc[i][0] = z; acc[i][1] = z; }

    gemm_accum<BM, CLAMP>(A1, ldA1, kb1, Bmat, rows, r0, tid, AsD, Bs, acc, tm0, tb0);
    if (A2)
        gemm_accum<BM, CLAMP>(A2, ldA2, kb2, Bmat + kb1 * 32 * 32, rows, r0, tid, AsD, Bs, acc, tm0, tb0);

#pragma unroll
    for (int i = 0; i < R; i++) {
        int row = r0 + tm0 + i;
        if (!CLAMP || row < rows) {
            float bias = bias1[row];
            if (bias2) bias += bias2[row];
            float4 o;
            upk2(acc[i][0], o.x, o.y);
            upk2(acc[i][1], o.z, o.w);
            o.x += bias; o.y += bias; o.z += bias; o.w += bias;
            *(float4*)&outT[(size_t)row * 32 + tb0] = o;
        }
    }
}

// ---------------- K3: LSTM pointwise ----------------
__global__ void k3_lstm(const float* __restrict__ c0, float* __restrict__ d_out) {
    int idx = blockIdx.x * blockDim.x + threadIdx.x;   // 32768 total
    int b = idx & 31, j = idx >> 5;
    float gi = g_gates[j * B + b];
    float gf = g_gates[(H + j) * B + b];
    float gg = g_gates[(2 * H + j) * B + b];
    float go = g_gates[(3 * H + j) * B + b];
    float cp = c0[b * H + j];
    float si = 1.f / (1.f + expf(-gi));
    float sf = 1.f / (1.f + expf(-gf));
    float so = 1.f / (1.f + expf(-go));
    float cn = sf * cp + si * tanhf(gg);
    float hn = so * tanhf(cn);
    g_featT[(H + j) * B + b] = hn;                       // "out" feature section
    d_out[NLOG + b * H + j] = hn;                        // h_new output
    d_out[NLOG + B * H + b * H + j] = cn;                // c_new output
}

// ---------------- K5: attention GEMM (enc@Wm^T) with fused v*tanh(q+m) epilogue ----------------
__global__ void __launch_bounds__(256) k5_score(const float* __restrict__ enc,
                                                const float* __restrict__ Wm_w,
                                                const float* __restrict__ Wm_b,
                                                const float* __restrict__ v_w) {
    __shared__ __align__(16) float AsD[16 * 256];  // duplicated A: [k][2*row]
    __shared__ __align__(16) float Bs[16 * 64];    // [k][j]
    __shared__ float red[128];
    int tid = threadIdx.x;
    int n0 = blockIdx.x * 64;
    int by = blockIdx.y;                 // batch (BM == L)
    int tm0 = (tid >> 4) * 8;
    int tn0 = (tid & 15) * 4;
    ull z = pk2(0.f, 0.f);
    ull acc[8][2];
#pragma unroll
    for (int i = 0; i < 8; i++) { acc[i][0] = z; acc[i][1] = z; }
    const float* A = enc + (size_t)by * L * H;

    for (int k0 = 0; k0 < H; k0 += 16) {
#pragma unroll
        for (int i = 0; i < 2; i++) {
            int idx = i * 256 + tid;
            int row = idx >> 2, c4 = idx & 3;
            float4 v = *(const float4*)&A[row * H + k0 + 4 * c4];
            float* p = &AsD[(4 * c4) * 256 + 2 * row];
            p[0] = v.x;   p[1] = v.x;
            p[256] = v.y; p[257] = v.y;
            p[512] = v.z; p[513] = v.z;
            p[768] = v.w; p[769] = v.w;
        }
        {
            int row = tid >> 2, c4 = tid & 3;
            float4 v = *(const float4*)&Wm_w[(size_t)(n0 + row) * H + k0 + 4 * c4];
            Bs[(4 * c4) * 64 + row] = v.x;
            Bs[(4 * c4 + 1) * 64 + row] = v.y;
            Bs[(4 * c4 + 2) * 64 + row] = v.z;
            Bs[(4 * c4 + 3) * 64 + row] = v.w;
        }
        __syncthreads();
#pragma unroll 8
        for (int k = 0; k < 16; k++) {
            ulonglong2 b2 = *(const ulonglong2*)&Bs[k * 64 + tn0];
#pragma unroll
            for (int i = 0; i < 8; i++) {
                ull a2 = *(const ull*)&AsD[k * 256 + 2 * (tm0 + i)];
                acc[i][0] = ffma2(a2, b2.x, acc[i][0]);
                acc[i][1] = ffma2(a2, b2.y, acc[i][1]);
            }
        }
        __syncthreads();
    }

    if (tid < 128) red[tid] = 0.f;
    __syncthreads();
    float4 vw = *(const float4*)&v_w[n0 + tn0];
    float4 mb = *(const float4*)&Wm_b[n0 + tn0];
    float qv0 = g_qT[(n0 + tn0 + 0) * B + by];
    float qv1 = g_qT[(n0 + tn0 + 1) * B + by];
    float qv2 = g_qT[(n0 + tn0 + 2) * B + by];
    float qv3 = g_qT[(n0 + tn0 + 3) * B + by];
#pragma unroll
    for (int i = 0; i < 8; i++) {
        float x0, x1, x2, x3;
        upk2(acc[i][0], x0, x1);
        upk2(acc[i][1], x2, x3);
        float p = vw.x * tanhf(x0 + mb.x + qv0) + vw.y * tanhf(x1 + mb.y + qv1)
                + vw.z * tanhf(x2 + mb.z + qv2) + vw.w * tanhf(x3 + mb.w + qv3);
        atomicAdd(&red[tm0 + i], p);
    }
    __syncthreads();
    if (tid < 128) atomicAdd(&g_scores[by * L + tid], red[tid]);
}

// ---------------- K7: softmax over L + context + featT(context) ----------------
__global__ void k7_ctx(const float* __restrict__ enc, const unsigned char* __restrict__ mask) {
    __shared__ float sc[128];
    __shared__ float redm[16];
    int b = blockIdx.x, t = threadIdx.x;
    if (t < 128) {
        float s = g_scores[b * L + t];
        if (mask[b * L + t]) s = -1e20f;
        sc[t] = s;
        g_scores[b * L + t] = s;   // masked scores for copy-logp path
    }
    __syncthreads();
    float m = (t < 128) ? sc[t] : -INFINITY;
#pragma unroll
    for (int o = 16; o > 0; o >>= 1) m = fmaxf(m, __shfl_xor_sync(~0u, m, o));
    if ((t & 31) == 0) redm[t >> 5] = m;
    __syncthreads();
    if (t == 0) {
        float mm = redm[0];
        for (int w = 1; w < 8; w++) mm = fmaxf(mm, redm[w]);
        redm[0] = mm;
    }
    __syncthreads();
    float mx = redm[0];
    float e = (t < 128) ? expf(sc[t] - mx) : 0.f;
    float s = e;
#pragma unroll
    for (int o = 16; o > 0; o >>= 1) s += __shfl_xor_sync(~0u, s, o);
    if ((t & 31) == 0) redm[8 + (t >> 5)] = s;
    __syncthreads();
    if (t == 0) {
        float ss = 0.f;
        for (int w = 0; w < 8; w++) ss += redm[8 + w];
        redm[8] = ss;
    }
    __syncthreads();
    float sum = redm[8];
    if (t < 128) sc[t] = e / sum;           // attention weights
    if (t == 0) g_lse[b] = mx + logf(sum);
    __syncthreads();
    const float* E = enc + (size_t)b * L * H;
#pragma unroll
    for (int jj = 0; jj < 4; jj++) {
        int j = t + jj * 256;
        float a = 0.f;
#pragma unroll 4
        for (int l = 0; l < 128; l++) a += sc[l] * E[l * H + j];
        g_context[b * H + j] = a;
        g_featT[j * B + b] = a;
    }
}

// ---------------- K8: pointer switch s_t + copy-logits output section ----------------
__global__ void k8_s(const float* __restrict__ ws_w, const float* __restrict__ ws_b,
                     float* __restrict__ d_out) {
    __shared__ float red[8];
    __shared__ float sh[2];
    int b = blockIdx.x, t = threadIdx.x;
    float a = 0.f;
    for (int j = t; j < H; j += 256) a += g_context[b * H + j] * ws_w[j];
    for (int j = t; j < H; j += 256) a += g_featT[(H + j) * B + b] * ws_w[H + j];
#pragma unroll
    for (int o = 16; o > 0; o >>= 1) a += __shfl_xor_sync(~0u, a, o);
    if ((t & 31) == 0) red[t >> 5] = a;
    __syncthreads();
    if (t == 0) {
        float zz = ws_b[0];
        for (int w = 0; w < 8; w++) zz += red[w];
        float s  = (zz >= 0.f) ? -log1pf(expf(-zz)) : zz - log1pf(expf(zz));
        float zm = -zz;
        float l1 = (zm >= 0.f) ? -log1pf(expf(-zm)) : zm - log1pf(expf(zm));
        l1 = fmaxf(l1, -41.446531673892822f);
        g_sB[b] = s;
        g_l1m[b] = l1;
        sh[0] = l1;
        sh[1] = g_lse[b];
    }
    __syncthreads();
    if (t < 128)
        d_out[(size_t)b * LOGN + VOUT + t] = sh[0] + g_scores[b * L + t] - sh[1];
}

// ---------------- K11a/b: log-sum-exp over VOUT per batch ----------------
__global__ void k11a_lse() {
    __shared__ float pm[8][32];
    __shared__ float ps[8][32];
    int w = threadIdx.x >> 5, lane = threadIdx.x & 31;
    int base = blockIdx.x * 1024 + w * 128;
    float m = -INFINITY, s = 0.f;
    for (int i = 0; i < 128; i++) {
        int v = base + i;
        if (v < VOUT) {
            float x = g_wgout[(size_t)v * B + lane];
            if (x > m) { s = s * expf(m - x) + 1.f; m = x; }
            else       { s += expf(x - m); }
        }
    }
    pm[w][lane] = m; ps[w][lane] = s;
    __syncthreads();
    if (w == 0) {
        float M = pm[0][lane], S = ps[0][lane];
#pragma unroll
        for (int i = 1; i < 8; i++) {
            float m2 = pm[i][lane], s2 = ps[i][lane];
            float nm = fmaxf(M, m2);
            S = S * expf(M - nm) + s2 * expf(m2 - nm);
            M = nm;
        }
        g_pmax[blockIdx.x * 32 + lane] = M;
        g_psum[blockIdx.x * 32 + lane] = S;
    }
}

__global__ void k11b_lse() {
    int b = threadIdx.x;
    float M = g_pmax[b], S = g_psum[b];
    for (int i = 1; i < NCHUNK; i++) {
        float m2 = g_pmax[i * 32 + b], s2 = g_psum[i * 32 + b];
        float nm = fmaxf(M, m2);
        S = S * expf(M - nm) + s2 * expf(m2 - nm);
        M = nm;
    }
    g_wlse[b] = M + logf(S);
}

// ---------------- K12: transpose + final vocab logits write ----------------
__global__ void k12_out(float* __restrict__ d_out) {
    __shared__ float sm[32][33];
    int tx = threadIdx.x & 31, ty = threadIdx.x >> 5;  // 32 x 8
    int v0 = blockIdx.x * 32;
#pragma unroll
    for (int r = 0; r < 4; r++) {
        int row = r * 8 + ty;
        int v = v0 + row;
        if (v > VOUT - 1) v = VOUT - 1;
        sm[row][tx] = g_wgout[(size_t)v * B + tx];
    }
    __syncthreads();
#pragma unroll
    for (int r = 0; r < 4; r++) {
        int b = r * 8 + ty;
        int v = v0 + tx;
        if (v < VOUT)
            d_out[(size_t)b * LOGN + v] = g_sB[b] + sm[tx][b] - g_wlse[b];
    }
}

// ---------------- launch ----------------
extern "C" void kernel_launch(void* const* d_in, const int* in_sizes, int n_in,
                              void* d_out, int out_size) {
    const int*   n_input  = (const int*)d_in[0];
    const int*   t_input  = (const int*)d_in[1];
    const float* h0       = (const float*)d_in[2];
    const float* c0       = (const float*)d_in[3];
    const float* enc_out  = (const float*)d_in[4];
    const unsigned char* mask = (const unsigned char*)d_in[5];
    const float* h_parent = (const float*)d_in[6];
    const float* embN     = (const float*)d_in[7];
    const float* embT     = (const float*)d_in[8];
    const float* W_ih     = (const float*)d_in[9];
    const float* W_hh     = (const float*)d_in[10];
    const float* b_ih     = (const float*)d_in[11];
    const float* b_hh     = (const float*)d_in[12];
    const float* Wh_w     = (const float*)d_in[13];
    const float* Wh_b     = (const float*)d_in[14];
    const float* Wm_w     = (const float*)d_in[15];
    const float* Wm_b     = (const float*)d_in[16];
    const float* v_w      = (const float*)d_in[17];
    const float* v_b      = (const float*)d_in[18];
    const float* wg_w     = (const float*)d_in[19];
    const float* wg_b     = (const float*)d_in[20];
    const float* ws_w     = (const float*)d_in[21];
    const float* ws_b     = (const float*)d_in[22];
    float* out = (float*)d_out;

    float* gatesP; cudaGetSymbolAddress((void**)&gatesP, g_gates);
    float* qTP;    cudaGetSymbolAddress((void**)&qTP, g_qT);
    float* wgoutP; cudaGetSymbolAddress((void**)&wgoutP, g_wgout);
    float* xhTP;   cudaGetSymbolAddress((void**)&xhTP, g_xhT);
    float* featTP; cudaGetSymbolAddress((void**)&featTP, g_featT);

    k1_prep<<<B, 256>>>(n_input, t_input, h0, h_parent, embN, embT, v_b);
    // LSTM gates: [4096 x 1792] @ xhT
    gemm_k<64, false><<<G4 / 64, 128>>>(W_ih, EIN, EIN / 32, W_hh, H, H / 32,
                                        xhTP, b_ih, b_hh, gatesP, G4);
    k3_lstm<<<(B * H) / 256, 256>>>(c0, out);
    // q = Wh_w @ h_new + Wh_b  (h_new section of featT)
    gemm_k<64, false><<<H / 64, 128>>>(Wh_w, H, H / 32, (const float*)nullptr, 0, 0,
                                       featTP + H * B, Wh_b, (const float*)nullptr, qTP, H);
    k5_score<<<dim3(H / 64, B), 256>>>(enc_out, Wm_w, Wm_b, v_w);
    k7_ctx<<<B, 256>>>(enc_out, mask);
    k8_s<<<B, 256>>>(ws_w, ws_b, out);
    // vocab GEMM: [50003 x 3072] @ featT
    gemm_k<128, true><<<(VOUT + 127) / 128, 128>>>(wg_w, F3, F3 / 32, (const float*)nullptr, 0, 0,
                                                   featTP, wg_b, (const float*)nullptr, wgoutP, VOUT);
    k11a_lse<<<NCHUNK, 256>>>();
    k11b_lse<<<1, 32>>>();
    k12_out<<<(VOUT + 31) / 32, 256>>>(out);
}

// round 3
// speedup vs baseline: 1.0921x; 1.0921x over previous
#include <cuda_runtime.h>
#include <math.h>

typedef unsigned long long ull;

#define DI __device__ __forceinline__

DI ull pk2(float x, float y){ ull r; asm("mov.b64 %0,{%1,%2};" : "=l"(r) : "f"(x), "f"(y)); return r; }
DI void upk2(ull v, float& x, float& y){ asm("mov.b64 {%0,%1},%2;" : "=f"(x), "=f"(y) : "l"(v)); }
DI ull ffma2(ull a, ull b, ull c){ ull d; asm("fma.rn.f32x2 %0,%1,%2,%3;" : "=l"(d) : "l"(a), "l"(b), "l"(c)); return d; }

static constexpr int B    = 32;
static constexpr int L    = 128;
static constexpr int H    = 1024;
static constexpr int EN   = 256;
static constexpr int ET   = 512;
static constexpr int EIN  = 768;     // EN + ET
static constexpr int G4   = 4096;    // 4*H
static constexpr int VOUT = 50003;
static constexpr int LOGN = VOUT + L;       // 50131
static constexpr int F3   = 3072;           // 3*H
static constexpr int NLOG = B * LOGN;       // logits elements
static constexpr int NCHUNK = 49;           // ceil(50003/1024)

// ---------------- scratch (static device memory; no allocations) ----------------
__device__ __align__(16) float g_xhT[(EIN + H) * B];   // [k][b]: emb-concat then h0
__device__ __align__(16) float g_featT[F3 * B];        // [k][b]: context | h_new | h_parent
__device__ __align__(16) float g_gates[G4 * B];        // [j][b]
__device__ __align__(16) float g_qT[H * B];            // [j][b]
__device__ __align__(16) float g_scores[B * L];
__device__ float g_lse[B];
__device__ __align__(16) float g_context[B * H];
__device__ float g_sB[B];
__device__ float g_l1m[B];
__device__ __align__(16) float g_wgout[(VOUT + 32) * B]; // [v][b]
__device__ float g_pmax[NCHUNK * 32];
__device__ float g_psum[NCHUNK * 32];
__device__ float g_wlse[B];

// ---------------- K1: embeddings + transposed staging + score init ----------------
__global__ void k1_prep(const int* __restrict__ n_in, const int* __restrict__ t_in,
                        const float* __restrict__ h0, const float* __restrict__ h_parent,
                        const float* __restrict__ embN, const float* __restrict__ embT,
                        const float* __restrict__ v_b) {
    int b = blockIdx.x;
    int t = threadIdx.x;
    int n  = n_in[b];
    int tt = t_in[b];
    for (int k = t; k < EIN; k += blockDim.x) {
        float v = (k < EN) ? embN[n * EN + k] : embT[(size_t)tt * ET + (k - EN)];
        g_xhT[k * B + b] = v;
    }
    for (int k = t; k < H; k += blockDim.x) {
        g_xhT[(EIN + k) * B + b]     = h0[b * H + k];
        g_featT[(2 * H + k) * B + b] = h_parent[b * H + k];
    }
    if (t < L) g_scores[b * L + t] = v_b[0];
}

// ---------------- pipelined blocked GEMM: out[row][b] = sum_k A[row][k]*Bmat[k][b] ----------------
// 128 threads, BK=16, ping-pong smem, global->reg prefetch.
// Two concatenated A segments (LSTM: W_ih then W_hh against stacked Bmat).
template<int BM, bool CLAMP>
DI void g_load(const float* __restrict__ A1, int ldA1, int kb1,
               const float* __restrict__ A2, int ldA2,
               const float* __restrict__ Bmat, int rows, int r0, int tid, int t,
               float4* areg, float4& breg) {
    const float* A; int ld; int kt;
    if (t < kb1) { A = A1; ld = ldA1; kt = t; }
    else         { A = A2; ld = ldA2; kt = t - kb1; }
    int k0 = kt * 16;
#pragma unroll
    for (int i = 0; i < BM / 32; i++) {
        int idx = i * 128 + tid;
        int row = idx >> 2, c4 = idx & 3;
        int rr = r0 + row;
        if (CLAMP && rr > rows - 1) rr = rows - 1;
        areg[i] = *(const float4*)&A[(size_t)rr * ld + k0 + 4 * c4];
    }
    breg = ((const float4*)(Bmat + t * 16 * 32))[tid];
}

template<int BM>
DI void g_store(float* AsD, float* Bs, int tid, const float4* areg, const float4& breg) {
#pragma unroll
    for (int i = 0; i < BM / 32; i++) {
        int idx = i * 128 + tid;
        int row = idx >> 2, c4 = idx & 3;
        float* p = &AsD[(4 * c4) * (2 * BM) + 2 * row];
        p[0] = areg[i].x;          p[1] = areg[i].x;
        p[2 * BM] = areg[i].y;     p[2 * BM + 1] = areg[i].y;
        p[4 * BM] = areg[i].z;     p[4 * BM + 1] = areg[i].z;
        p[6 * BM] = areg[i].w;     p[6 * BM + 1] = areg[i].w;
    }
    ((float4*)Bs)[tid] = breg;
}

template<int BM>
DI void g_comp(const float* AsD, const float* Bs, ull (*acc)[2], int tm0, int tb0) {
    constexpr int R = BM / 16;
#pragma unroll
    for (int k = 0; k < 16; k++) {
        ulonglong2 b2 = *(const ulonglong2*)&Bs[k * 32 + tb0];
#pragma unroll
        for (int i = 0; i < R; i++) {
            ull a2 = *(const ull*)&AsD[k * 2 * BM + 2 * (tm0 + i)];
            acc[i][0] = ffma2(a2, b2.x, acc[i][0]);
            acc[i][1] = ffma2(a2, b2.y, acc[i][1]);
        }
    }
}

template<int BM, bool CLAMP>
__global__ void __launch_bounds__(128) gemm_k(const float* __restrict__ A1, int ldA1, int kb1,
                                              const float* __restrict__ A2, int ldA2, int kb2,
                                              const float* __restrict__ Bmat,
                                              const float* __restrict__ bias1,
                                              const float* __restrict__ bias2,
                                              float* __restrict__ outT, int rows) {
    constexpr int R = BM / 16;
    __shared__ __align__(16) float AsD[2][16 * 2 * BM];
    __shared__ __align__(16) float Bs[2][16 * 32];
    int tid = threadIdx.x;
    int r0 = blockIdx.x * BM;
    int tm0 = (tid >> 3) * R;
    int tb0 = (tid & 7) * 4;
    int nkt = kb1 + kb2;
    ull acc[R][2];
    ull z = pk2(0.f, 0.f);
#pragma unroll
    for (int i = 0; i < R; i++) { acc[i][0] = z; acc[i][1] = z; }

    float4 areg[BM / 32];
    float4 breg;
    g_load<BM, CLAMP>(A1, ldA1, kb1, A2, ldA2, Bmat, rows, r0, tid, 0, areg, breg);
    g_store<BM>(AsD[0], Bs[0], tid, areg, breg);
    __syncthreads();
    for (int t = 1; t < nkt; t++) {
        g_load<BM, CLAMP>(A1, ldA1, kb1, A2, ldA2, Bmat, rows, r0, tid, t, areg, breg);
        g_comp<BM>(AsD[(t - 1) & 1], Bs[(t - 1) & 1], acc, tm0, tb0);
        g_store<BM>(AsD[t & 1], Bs[t & 1], tid, areg, breg);
        __syncthreads();
    }
    g_comp<BM>(AsD[(nkt - 1) & 1], Bs[(nkt - 1) & 1], acc, tm0, tb0);

#pragma unroll
    for (int i = 0; i < R; i++) {
        int row = r0 + tm0 + i;
        if (!CLAMP || row < rows) {
            float bias = bias1[row];
            if (bias2) bias += bias2[row];
            float4 o;
            upk2(acc[i][0], o.x, o.y);
            upk2(acc[i][1], o.z, o.w);
            o.x += bias; o.y += bias; o.z += bias; o.w += bias;
            *(float4*)&outT[(size_t)row * 32 + tb0] = o;
        }
    }
}

// ---------------- K3: LSTM pointwise ----------------
__global__ void k3_lstm(const float* __restrict__ c0, float* __restrict__ d_out) {
    int idx = blockIdx.x * blockDim.x + threadIdx.x;   // 32768 total
    int b = idx & 31, j = idx >> 5;
    float gi = g_gates[j * B + b];
    float gf = g_gates[(H + j) * B + b];
    float gg = g_gates[(2 * H + j) * B + b];
    float go = g_gates[(3 * H + j) * B + b];
    float cp = c0[b * H + j];
    float si = 1.f / (1.f + expf(-gi));
    float sf = 1.f / (1.f + expf(-gf));
    float so = 1.f / (1.f + expf(-go));
    float cn = sf * cp + si * tanhf(gg);
    float hn = so * tanhf(cn);
    g_featT[(H + j) * B + b] = hn;                       // "out" feature section
    d_out[NLOG + b * H + j] = hn;                        // h_new output
    d_out[NLOG + B * H + b * H + j] = cn;                // c_new output
}

// ---------------- K5: attention GEMM (enc@Wm^T), pipelined, fused v*tanh epilogue ----------------
__global__ void __launch_bounds__(256) k5_score(const float* __restrict__ enc,
                                                const float* __restrict__ Wm_w,
                                                const float* __restrict__ Wm_b,
                                                const float* __restrict__ v_w) {
    __shared__ __align__(16) float AsD[2][16 * 256];  // duplicated A: [k][2*row]
    __shared__ __align__(16) float Bs[2][16 * 64];    // [k][j]
    __shared__ float red[128];
    int tid = threadIdx.x;
    int n0 = blockIdx.x * 64;
    int by = blockIdx.y;                 // batch (BM == L)
    int tm0 = (tid >> 4) * 8;
    int tn0 = (tid & 15) * 4;
    ull z = pk2(0.f, 0.f);
    ull acc[8][2];
#pragma unroll
    for (int i = 0; i < 8; i++) { acc[i][0] = z; acc[i][1] = z; }
    const float* A = enc + (size_t)by * L * H;

    int arow = tid >> 2, ac4 = tid & 3;      // A loader: 2 iters of (row, c4)
    int brow = tid >> 2, bc4 = tid & 3;      // B loader

    float4 areg[2], breg;
    auto loadt = [&](int kt) {
        int k0 = kt * 16;
#pragma unroll
        for (int i = 0; i < 2; i++) {
            int row = arow + i * 64;
            areg[i] = *(const float4*)&A[row * H + k0 + 4 * ac4];
        }
        breg = *(const float4*)&Wm_w[(size_t)(n0 + brow) * H + k0 + 4 * bc4];
    };
    auto storet = [&](int bsel) {
        float* AD = AsD[bsel];
        float* BB = Bs[bsel];
#pragma unroll
        for (int i = 0; i < 2; i++) {
            int row = arow + i * 64;
            float* p = &AD[(4 * ac4) * 256 + 2 * row];
            p[0] = areg[i].x;   p[1] = areg[i].x;
            p[256] = areg[i].y; p[257] = areg[i].y;
            p[512] = areg[i].z; p[513] = areg[i].z;
            p[768] = areg[i].w; p[769] = areg[i].w;
        }
        BB[(4 * bc4) * 64 + brow]     = breg.x;
        BB[(4 * bc4 + 1) * 64 + brow] = breg.y;
        BB[(4 * bc4 + 2) * 64 + brow] = breg.z;
        BB[(4 * bc4 + 3) * 64 + brow] = breg.w;
    };
    auto compt = [&](int bsel) {
        const float* AD = AsD[bsel];
        const float* BB = Bs[bsel];
#pragma unroll
        for (int k = 0; k < 16; k++) {
            ulonglong2 b2 = *(const ulonglong2*)&BB[k * 64 + tn0];
#pragma unroll
            for (int i = 0; i < 8; i++) {
                ull a2 = *(const ull*)&AD[k * 256 + 2 * (tm0 + i)];
                acc[i][0] = ffma2(a2, b2.x, acc[i][0]);
                acc[i][1] = ffma2(a2, b2.y, acc[i][1]);
            }
        }
    };

    loadt(0);
    storet(0);
    __syncthreads();
    for (int t = 1; t < H / 16; t++) {
        loadt(t);
        compt((t - 1) & 1);
        storet(t & 1);
        __syncthreads();
    }
    compt((H / 16 - 1) & 1);

    if (tid < 128) red[tid] = 0.f;
    __syncthreads();
    float4 vw = *(const float4*)&v_w[n0 + tn0];
    float4 mb = *(const float4*)&Wm_b[n0 + tn0];
    float qv0 = g_qT[(n0 + tn0 + 0) * B + by];
    float qv1 = g_qT[(n0 + tn0 + 1) * B + by];
    float qv2 = g_qT[(n0 + tn0 + 2) * B + by];
    float qv3 = g_qT[(n0 + tn0 + 3) * B + by];
#pragma unroll
    for (int i = 0; i < 8; i++) {
        float x0, x1, x2, x3;
        upk2(acc[i][0], x0, x1);
        upk2(acc[i][1], x2, x3);
        float p = vw.x * tanhf(x0 + mb.x + qv0) + vw.y * tanhf(x1 + mb.y + qv1)
                + vw.z * tanhf(x2 + mb.z + qv2) + vw.w * tanhf(x3 + mb.w + qv3);
        atomicAdd(&red[tm0 + i], p);
    }
    __syncthreads();
    if (tid < 128) atomicAdd(&g_scores[by * L + tid], red[tid]);
}

// ---------------- K7: softmax over L + context + featT(context) ----------------
__global__ void k7_ctx(const float* __restrict__ enc, const unsigned char* __restrict__ mask) {
    __shared__ float sc[128];
    __shared__ float redm[16];
    int b = blockIdx.x, t = threadIdx.x;
    if (t < 128) {
        float s = g_scores[b * L + t];
        if (mask[b * L + t]) s = -1e20f;
        sc[t] = s;
        g_scores[b * L + t] = s;   // masked scores for copy-logp path
    }
    __syncthreads();
    float m = (t < 128) ? sc[t] : -INFINITY;
#pragma unroll
    for (int o = 16; o > 0; o >>= 1) m = fmaxf(m, __shfl_xor_sync(~0u, m, o));
    if ((t & 31) == 0) redm[t >> 5] = m;
    __syncthreads();
    if (t == 0) {
        float mm = redm[0];
        for (int w = 1; w < 8; w++) mm = fmaxf(mm, redm[w]);
        redm[0] = mm;
    }
    __syncthreads();
    float mx = redm[0];
    float e = (t < 128) ? expf(sc[t] - mx) : 0.f;
    float s = e;
#pragma unroll
    for (int o = 16; o > 0; o >>= 1) s += __shfl_xor_sync(~0u, s, o);
    if ((t & 31) == 0) redm[8 + (t >> 5)] = s;
    __syncthreads();
    if (t == 0) {
        float ss = 0.f;
        for (int w = 0; w < 8; w++) ss += redm[8 + w];
        redm[8] = ss;
    }
    __syncthreads();
    float sum = redm[8];
    if (t < 128) sc[t] = e / sum;           // attention weights
    if (t == 0) g_lse[b] = mx + logf(sum);
    __syncthreads();
    const float* E = enc + (size_t)b * L * H;
#pragma unroll
    for (int jj = 0; jj < 4; jj++) {
        int j = t + jj * 256;
        float a = 0.f;
#pragma unroll 4
        for (int l = 0; l < 128; l++) a += sc[l] * E[l * H + j];
        g_context[b * H + j] = a;
        g_featT[j * B + b] = a;
    }
}

// ---------------- K8: pointer switch s_t + copy-logits output section ----------------
__global__ void k8_s(const float* __restrict__ ws_w, const float* __restrict__ ws_b,
                     float* __restrict__ d_out) {
    __shared__ float red[8];
    __shared__ float sh[2];
    int b = blockIdx.x, t = threadIdx.x;
    float a = 0.f;
    for (int j = t; j < H; j += 256) a += g_context[b * H + j] * ws_w[j];
    for (int j = t; j < H; j += 256) a += g_featT[(H + j) * B + b] * ws_w[H + j];
#pragma unroll
    for (int o = 16; o > 0; o >>= 1) a += __shfl_xor_sync(~0u, a, o);
    if ((t & 31) == 0) red[t >> 5] = a;
    __syncthreads();
    if (t == 0) {
        float zz = ws_b[0];
        for (int w = 0; w < 8; w++) zz += red[w];
        float s  = (zz >= 0.f) ? -log1pf(expf(-zz)) : zz - log1pf(expf(zz));
        float zm = -zz;
        float l1 = (zm >= 0.f) ? -log1pf(expf(-zm)) : zm - log1pf(expf(zm));
        l1 = fmaxf(l1, -41.446531673892822f);
        g_sB[b] = s;
        g_l1m[b] = l1;
        sh[0] = l1;
        sh[1] = g_lse[b];
    }
    __syncthreads();
    if (t < 128)
        d_out[(size_t)b * LOGN + VOUT + t] = sh[0] + g_scores[b * L + t] - sh[1];
}

// ---------------- K11a/b: log-sum-exp over VOUT per batch ----------------
__global__ void k11a_lse() {
    __shared__ float pm[8][32];
    __shared__ float ps[8][32];
    int w = threadIdx.x >> 5, lane = threadIdx.x & 31;
    int base = blockIdx.x * 1024 + w * 128;
    float m = -INFINITY, s = 0.f;
    for (int i = 0; i < 128; i++) {
        int v = base + i;
        if (v < VOUT) {
            float x = g_wgout[(size_t)v * B + lane];
            if (x > m) { s = s * expf(m - x) + 1.f; m = x; }
            else       { s += expf(x - m); }
        }
    }
    pm[w][lane] = m; ps[w][lane] = s;
    __syncthreads();
    if (w == 0) {
        float M = pm[0][lane], S = ps[0][lane];
#pragma unroll
        for (int i = 1; i < 8; i++) {
            float m2 = pm[i][lane], s2 = ps[i][lane];
            float nm = fmaxf(M, m2);
            S = S * expf(M - nm) + s2 * expf(m2 - nm);
            M = nm;
        }
        g_pmax[blockIdx.x * 32 + lane] = M;
        g_psum[blockIdx.x * 32 + lane] = S;
    }
}

__global__ void k11b_lse() {
    int b = threadIdx.x;
    float M = g_pmax[b], S = g_psum[b];
    for (int i = 1; i < NCHUNK; i++) {
        float m2 = g_pmax[i * 32 + b], s2 = g_psum[i * 32 + b];
        float nm = fmaxf(M, m2);
        S = S * expf(M - nm) + s2 * expf(m2 - nm);
        M = nm;
    }
    g_wlse[b] = M + logf(S);
}

// ---------------- K12: transpose + final vocab logits write ----------------
__global__ void k12_out(float* __restrict__ d_out) {
    __shared__ float sm[32][33];
    int tx = threadIdx.x & 31, ty = threadIdx.x >> 5;  // 32 x 8
    int v0 = blockIdx.x * 32;
#pragma unroll
    for (int r = 0; r < 4; r++) {
        int row = r * 8 + ty;
        int v = v0 + row;
        if (v > VOUT - 1) v = VOUT - 1;
        sm[row][tx] = g_wgout[(size_t)v * B + tx];
    }
    __syncthreads();
#pragma unroll
    for (int r = 0; r < 4; r++) {
        int b = r * 8 + ty;
        int v = v0 + tx;
        if (v < VOUT)
            d_out[(size_t)b * LOGN + v] = g_sB[b] + sm[tx][b] - g_wlse[b];
    }
}

// ---------------- launch ----------------
extern "C" void kernel_launch(void* const* d_in, const int* in_sizes, int n_in,
                              void* d_out, int out_size) {
    const int*   n_input  = (const int*)d_in[0];
    const int*   t_input  = (const int*)d_in[1];
    const float* h0       = (const float*)d_in[2];
    const float* c0       = (const float*)d_in[3];
    const float* enc_out  = (const float*)d_in[4];
    const unsigned char* mask = (const unsigned char*)d_in[5];
    const float* h_parent = (const float*)d_in[6];
    const float* embN     = (const float*)d_in[7];
    const float* embT     = (const float*)d_in[8];
    const float* W_ih     = (const float*)d_in[9];
    const float* W_hh     = (const float*)d_in[10];
    const float* b_ih     = (const float*)d_in[11];
    const float* b_hh     = (const float*)d_in[12];
    const float* Wh_w     = (const float*)d_in[13];
    const float* Wh_b     = (const float*)d_in[14];
    const float* Wm_w     = (const float*)d_in[15];
    const float* Wm_b     = (const float*)d_in[16];
    const float* v_w      = (const float*)d_in[17];
    const float* v_b      = (const float*)d_in[18];
    const float* wg_w     = (const float*)d_in[19];
    const float* wg_b     = (const float*)d_in[20];
    const float* ws_w     = (const float*)d_in[21];
    const float* ws_b     = (const float*)d_in[22];
    float* out = (float*)d_out;

    float* gatesP; cudaGetSymbolAddress((void**)&gatesP, g_gates);
    float* qTP;    cudaGetSymbolAddress((void**)&qTP, g_qT);
    float* wgoutP; cudaGetSymbolAddress((void**)&wgoutP, g_wgout);
    float* xhTP;   cudaGetSymbolAddress((void**)&xhTP, g_xhT);
    float* featTP; cudaGetSymbolAddress((void**)&featTP, g_featT);

    k1_prep<<<B, 256>>>(n_input, t_input, h0, h_parent, embN, embT, v_b);
    // LSTM gates: [4096 x 1792] @ xhT
    gemm_k<64, false><<<G4 / 64, 128>>>(W_ih, EIN, EIN / 16, W_hh, H, H / 16,
                                        xhTP, b_ih, b_hh, gatesP, G4);
    k3_lstm<<<(B * H) / 256, 256>>>(c0, out);
    // q = Wh_w @ h_new + Wh_b  (h_new section of featT)
    gemm_k<64, false><<<H / 64, 128>>>(Wh_w, H, H / 16, (const float*)nullptr, 0, 0,
                                       featTP + H * B, Wh_b, (const float*)nullptr, qTP, H);
    k5_score<<<dim3(H / 64, B), 256>>>(enc_out, Wm_w, Wm_b, v_w);
    k7_ctx<<<B, 256>>>(enc_out, mask);
    k8_s<<<B, 256>>>(ws_w, ws_b, out);
    // vocab GEMM: [50003 x 3072] @ featT
    gemm_k<128, true><<<(VOUT + 127) / 128, 128>>>(wg_w, F3, F3 / 16, (const float*)nullptr, 0, 0,
                                                   featTP, wg_b, (const float*)nullptr, wgoutP, VOUT);
    k11a_lse<<<NCHUNK, 256>>>();
    k11b_lse<<<1, 32>>>();
    k12_out<<<(VOUT + 31) / 32, 256>>>(out);
}

// round 4
// speedup vs baseline: 1.1673x; 1.0688x over previous
#include <cuda_runtime.h>
#include <math.h>

typedef unsigned long long ull;

#define DI __device__ __forceinline__

DI ull pk2(float x, float y){ ull r; asm("mov.b64 %0,{%1,%2};" : "=l"(r) : "f"(x), "f"(y)); return r; }
DI void upk2(ull v, float& x, float& y){ asm("mov.b64 {%0,%1},%2;" : "=f"(x), "=f"(y) : "l"(v)); }
DI ull ffma2(ull a, ull b, ull c){ ull d; asm("fma.rn.f32x2 %0,%1,%2,%3;" : "=l"(d) : "l"(a), "l"(b), "l"(c)); return d; }

static constexpr int B    = 32;
static constexpr int L    = 128;
static constexpr int H    = 1024;
static constexpr int EN   = 256;
static constexpr int ET   = 512;
static constexpr int EIN  = 768;     // EN + ET
static constexpr int G4   = 4096;    // 4*H
static constexpr int VOUT = 50003;
static constexpr int LOGN = VOUT + L;       // 50131
static constexpr int F3   = 3072;           // 3*H
static constexpr int NLOG = B * LOGN;       // logits elements
static constexpr int NCHUNK = 49;           // ceil(50003/1024)

// ---------------- scratch (static device memory; no allocations) ----------------
__device__ __align__(16) float g_xhT[(EIN + H) * B];   // [k][b]: emb-concat then h0
__device__ __align__(16) float g_featT[F3 * B];        // [k][b]: context | h_new | h_parent
__device__ __align__(16) float g_gates[G4 * B];        // [j][b]
__device__ __align__(16) float g_qT[H * B];            // [j][b]
__device__ __align__(16) float g_scores[B * L];
__device__ float g_lse[B];
__device__ __align__(16) float g_context[B * H];
__device__ float g_sB[B];
__device__ float g_l1m[B];
__device__ __align__(16) float g_wgout[(VOUT + 32) * B]; // [v][b]
__device__ float g_pmax[NCHUNK * 32];
__device__ float g_psum[NCHUNK * 32];
__device__ float g_wlse[B];

// ---------------- K1: embeddings + transposed staging + score init ----------------
__global__ void k1_prep(const int* __restrict__ n_in, const int* __restrict__ t_in,
                        const float* __restrict__ h0, const float* __restrict__ h_parent,
                        const float* __restrict__ embN, const float* __restrict__ embT,
                        const float* __restrict__ v_b) {
    int b = blockIdx.x;
    int t = threadIdx.x;
    int n  = n_in[b];
    int tt = t_in[b];
    for (int k = t; k < EIN; k += blockDim.x) {
        float v = (k < EN) ? embN[n * EN + k] : embT[(size_t)tt * ET + (k - EN)];
        g_xhT[k * B + b] = v;
    }
    for (int k = t; k < H; k += blockDim.x) {
        g_xhT[(EIN + k) * B + b]     = h0[b * H + k];
        g_featT[(2 * H + k) * B + b] = h_parent[b * H + k];
    }
    if (t < L) g_scores[b * L + t] = v_b[0];
}

// ---------------- deep-pipelined blocked GEMM ----------------
// out[row][b] = sum_k A[row][k] * Bmat[k][b],   Bmat is [k][32] contiguous.
// 128 threads, BK=16, 3 smem stages, prefetch 2 tiles ahead in registers.
// A smem layout: [k][row] padded (BM+2) -> row-pair LDS.64 for ffma2.
// Two concatenated A segments (LSTM: W_ih then W_hh against stacked Bmat).
template<int BM, bool CLAMP>
__global__ void __launch_bounds__(128) gemm_k(const float* __restrict__ A1, int ldA1, int kb1,
                                              const float* __restrict__ A2, int ldA2, int kb2,
                                              const float* __restrict__ Bmat,
                                              const float* __restrict__ bias1,
                                              const float* __restrict__ bias2,
                                              float* __restrict__ outT, int rows) {
    constexpr int R    = BM / 16;     // rows per thread
    constexpr int RP   = R / 2;       // row pairs per thread
    constexpr int LDAS = BM + 2;      // padded A smem row stride (floats)
    constexpr int NA   = BM / 32;     // float4 A loads per thread per tile
    __shared__ __align__(16) float As[3][16 * LDAS];
    __shared__ __align__(16) float Bs[3][16 * 32];
    int tid = threadIdx.x;
    int r0 = blockIdx.x * BM;
    int tm0 = (tid >> 3) * R;
    int tb0 = (tid & 7) * 4;
    int nkt = kb1 + kb2;

    ull acc[RP][4];
    ull z = pk2(0.f, 0.f);
#pragma unroll
    for (int p = 0; p < RP; p++)
#pragma unroll
        for (int c = 0; c < 4; c++) acc[p][c] = z;

    float4 rA[2][NA];
    float4 rB[2];

    auto ld = [&](int t, int buf) {
        const float* A; int ld_; int kt;
        if (t < kb1) { A = A1; ld_ = ldA1; kt = t; }
        else         { A = A2; ld_ = ldA2; kt = t - kb1; }
        int k0 = kt * 16;
#pragma unroll
        for (int i = 0; i < NA; i++) {
            int idx = i * 128 + tid;
            int row = idx >> 2, c4 = idx & 3;
            int rr = r0 + row;
            if (CLAMP && rr > rows - 1) rr = rows - 1;
            rA[buf][i] = *(const float4*)&A[(size_t)rr * ld_ + k0 + 4 * c4];
        }
        rB[buf] = ((const float4*)(Bmat + t * 16 * 32))[tid];
    };
    auto st = [&](int stage, int buf) {
        float* AD = As[stage];
#pragma unroll
        for (int i = 0; i < NA; i++) {
            int idx = i * 128 + tid;
            int row = idx >> 2, c4 = idx & 3;
            AD[(4 * c4 + 0) * LDAS + row] = rA[buf][i].x;
            AD[(4 * c4 + 1) * LDAS + row] = rA[buf][i].y;
            AD[(4 * c4 + 2) * LDAS + row] = rA[buf][i].z;
            AD[(4 * c4 + 3) * LDAS + row] = rA[buf][i].w;
        }
        ((float4*)Bs[stage])[tid] = rB[buf];
    };
    auto comp = [&](int stage) {
        const float* AD = As[stage];
        const float* BB = Bs[stage];
#pragma unroll
        for (int k = 0; k < 16; k++) {
            float4 bv = *(const float4*)&BB[k * 32 + tb0];
            ull b2[4];
            b2[0] = pk2(bv.x, bv.x);
            b2[1] = pk2(bv.y, bv.y);
            b2[2] = pk2(bv.z, bv.z);
            b2[3] = pk2(bv.w, bv.w);
#pragma unroll
            for (int p = 0; p < RP; p++) {
                ull a2 = *(const ull*)&AD[k * LDAS + tm0 + 2 * p];
#pragma unroll
                for (int c = 0; c < 4; c++)
                    acc[p][c] = ffma2(a2, b2[c], acc[p][c]);
            }
        }
    };

    // preamble: tiles 0 and 1 in flight, tile 0 staged
    ld(0, 0);
    ld(1, 1);
    st(0, 0);
    __syncthreads();
    for (int t = 0; t < nkt; t++) {
        if (t + 1 < nkt) st((t + 1) % 3, (t + 1) & 1);
        if (t + 2 < nkt) ld(t + 2, t & 1);
        comp(t % 3);
        __syncthreads();
    }

#pragma unroll
    for (int p = 0; p < RP; p++) {
        int ra = r0 + tm0 + 2 * p;
        int rb_ = ra + 1;
        float4 lo, hi;
        upk2(acc[p][0], lo.x, hi.x);
        upk2(acc[p][1], lo.y, hi.y);
        upk2(acc[p][2], lo.z, hi.z);
        upk2(acc[p][3], lo.w, hi.w);
        if (!CLAMP || ra < rows) {
            float ba = bias1[ra]; if (bias2) ba += bias2[ra];
            lo.x += ba; lo.y += ba; lo.z += ba; lo.w += ba;
            *(float4*)&outT[(size_t)ra * 32 + tb0] = lo;
        }
        if (!CLAMP || rb_ < rows) {
            float bb = bias1[rb_]; if (bias2) bb += bias2[rb_];
            hi.x += bb; hi.y += bb; hi.z += bb; hi.w += bb;
            *(float4*)&outT[(size_t)rb_ * 32 + tb0] = hi;
        }
    }
}

// ---------------- K3: LSTM pointwise ----------------
__global__ void k3_lstm(const float* __restrict__ c0, float* __restrict__ d_out) {
    int idx = blockIdx.x * blockDim.x + threadIdx.x;   // 32768 total
    int b = idx & 31, j = idx >> 5;
    float gi = g_gates[j * B + b];
    float gf = g_gates[(H + j) * B + b];
    float gg = g_gates[(2 * H + j) * B + b];
    float go = g_gates[(3 * H + j) * B + b];
    float cp = c0[b * H + j];
    float si = 1.f / (1.f + expf(-gi));
    float sf = 1.f / (1.f + expf(-gf));
    float so = 1.f / (1.f + expf(-go));
    float cn = sf * cp + si * tanhf(gg);
    float hn = so * tanhf(cn);
    g_featT[(H + j) * B + b] = hn;                       // "out" feature section
    d_out[NLOG + b * H + j] = hn;                        // h_new output
    d_out[NLOG + B * H + b * H + j] = cn;                // c_new output
}

// ---------------- K5: attention GEMM (enc@Wm^T), pipelined, fused v*tanh epilogue ----------------
__global__ void __launch_bounds__(256) k5_score(const float* __restrict__ enc,
                                                const float* __restrict__ Wm_w,
                                                const float* __restrict__ Wm_b,
                                                const float* __restrict__ v_w) {
    __shared__ __align__(16) float AsD[2][16 * 256];  // duplicated A: [k][2*row]
    __shared__ __align__(16) float Bs[2][16 * 64];    // [k][j]
    __shared__ float red[128];
    int tid = threadIdx.x;
    int n0 = blockIdx.x * 64;
    int by = blockIdx.y;                 // batch (BM == L)
    int tm0 = (tid >> 4) * 8;
    int tn0 = (tid & 15) * 4;
    ull z = pk2(0.f, 0.f);
    ull acc[8][2];
#pragma unroll
    for (int i = 0; i < 8; i++) { acc[i][0] = z; acc[i][1] = z; }
    const float* A = enc + (size_t)by * L * H;

    int arow = tid >> 2, ac4 = tid & 3;      // A loader: 2 iters of (row, c4)
    int brow = tid >> 2, bc4 = tid & 3;      // B loader

    float4 areg[2], breg;
    auto loadt = [&](int kt) {
        int k0 = kt * 16;
#pragma unroll
        for (int i = 0; i < 2; i++) {
            int row = arow + i * 64;
            areg[i] = *(const float4*)&A[row * H + k0 + 4 * ac4];
        }
        breg = *(const float4*)&Wm_w[(size_t)(n0 + brow) * H + k0 + 4 * bc4];
    };
    auto storet = [&](int bsel) {
        float* AD = AsD[bsel];
        float* BB = Bs[bsel];
#pragma unroll
        for (int i = 0; i < 2; i++) {
            int row = arow + i * 64;
            float* p = &AD[(4 * ac4) * 256 + 2 * row];
            p[0] = areg[i].x;   p[1] = areg[i].x;
            p[256] = areg[i].y; p[257] = areg[i].y;
            p[512] = areg[i].z; p[513] = areg[i].z;
            p[768] = areg[i].w; p[769] = areg[i].w;
        }
        BB[(4 * bc4) * 64 + brow]     = breg.x;
        BB[(4 * bc4 + 1) * 64 + brow] = breg.y;
        BB[(4 * bc4 + 2) * 64 + brow] = breg.z;
        BB[(4 * bc4 + 3) * 64 + brow] = breg.w;
    };
    auto compt = [&](int bsel) {
        const float* AD = AsD[bsel];
        const float* BB = Bs[bsel];
#pragma unroll
        for (int k = 0; k < 16; k++) {
            ulonglong2 b2 = *(const ulonglong2*)&BB[k * 64 + tn0];
#pragma unroll
            for (int i = 0; i < 8; i++) {
                ull a2 = *(const ull*)&AD[k * 256 + 2 * (tm0 + i)];
                acc[i][0] = ffma2(a2, b2.x, acc[i][0]);
                acc[i][1] = ffma2(a2, b2.y, acc[i][1]);
            }
        }
    };

    loadt(0);
    storet(0);
    __syncthreads();
    for (int t = 1; t < H / 16; t++) {
        loadt(t);
        compt((t - 1) & 1);
        storet(t & 1);
        __syncthreads();
    }
    compt((H / 16 - 1) & 1);

    if (tid < 128) red[tid] = 0.f;
    __syncthreads();
    float4 vw = *(const float4*)&v_w[n0 + tn0];
    float4 mb = *(const float4*)&Wm_b[n0 + tn0];
    float qv0 = g_qT[(n0 + tn0 + 0) * B + by];
    float qv1 = g_qT[(n0 + tn0 + 1) * B + by];
    float qv2 = g_qT[(n0 + tn0 + 2) * B + by];
    float qv3 = g_qT[(n0 + tn0 + 3) * B + by];
#pragma unroll
    for (int i = 0; i < 8; i++) {
        float x0, x1, x2, x3;
        upk2(acc[i][0], x0, x1);
        upk2(acc[i][1], x2, x3);
        float p = vw.x * tanhf(x0 + mb.x + qv0) + vw.y * tanhf(x1 + mb.y + qv1)
                + vw.z * tanhf(x2 + mb.z + qv2) + vw.w * tanhf(x3 + mb.w + qv3);
        atomicAdd(&red[tm0 + i], p);
    }
    __syncthreads();
    if (tid < 128) atomicAdd(&g_scores[by * L + tid], red[tid]);
}

// ---------------- K7: softmax over L + context + featT(context) ----------------
__global__ void k7_ctx(const float* __restrict__ enc, const unsigned char* __restrict__ mask) {
    __shared__ float sc[128];
    __shared__ float redm[16];
    int b = blockIdx.x, t = threadIdx.x;
    if (t < 128) {
        float s = g_scores[b * L + t];
        if (mask[b * L + t]) s = -1e20f;
        sc[t] = s;
        g_scores[b * L + t] = s;   // masked scores for copy-logp path
    }
    __syncthreads();
    float m = (t < 128) ? sc[t] : -INFINITY;
#pragma unroll
    for (int o = 16; o > 0; o >>= 1) m = fmaxf(m, __shfl_xor_sync(~0u, m, o));
    if ((t & 31) == 0) redm[t >> 5] = m;
    __syncthreads();
    if (t == 0) {
        float mm = redm[0];
        for (int w = 1; w < 8; w++) mm = fmaxf(mm, redm[w]);
        redm[0] = mm;
    }
    __syncthreads();
    float mx = redm[0];
    float e = (t < 128) ? expf(sc[t] - mx) : 0.f;
    float s = e;
#pragma unroll
    for (int o = 16; o > 0; o >>= 1) s += __shfl_xor_sync(~0u, s, o);
    if ((t & 31) == 0) redm[8 + (t >> 5)] = s;
    __syncthreads();
    if (t == 0) {
        float ss = 0.f;
        for (int w = 0; w < 8; w++) ss += redm[8 + w];
        redm[8] = ss;
    }
    __syncthreads();
    float sum = redm[8];
    if (t < 128) sc[t] = e / sum;           // attention weights
    if (t == 0) g_lse[b] = mx + logf(sum);
    __syncthreads();
    const float* E = enc + (size_t)b * L * H;
#pragma unroll
    for (int jj = 0; jj < 4; jj++) {
        int j = t + jj * 256;
        float a = 0.f;
#pragma unroll 4
        for (int l = 0; l < 128; l++) a += sc[l] * E[l * H + j];
        g_context[b * H + j] = a;
        g_featT[j * B + b] = a;
    }
}

// ---------------- K8: pointer switch s_t + copy-logits output section ----------------
__global__ void k8_s(const float* __restrict__ ws_w, const float* __restrict__ ws_b,
                     float* __restrict__ d_out) {
    __shared__ float red[8];
    __shared__ float sh[2];
    int b = blockIdx.x, t = threadIdx.x;
    float a = 0.f;
    for (int j = t; j < H; j += 256) a += g_context[b * H + j] * ws_w[j];
    for (int j = t; j < H; j += 256) a += g_featT[(H + j) * B + b] * ws_w[H + j];
#pragma unroll
    for (int o = 16; o > 0; o >>= 1) a += __shfl_xor_sync(~0u, a, o);
    if ((t & 31) == 0) red[t >> 5] = a;
    __syncthreads();
    if (t == 0) {
        float zz = ws_b[0];
        for (int w = 0; w < 8; w++) zz += red[w];
        float s  = (zz >= 0.f) ? -log1pf(expf(-zz)) : zz - log1pf(expf(zz));
        float zm = -zz;
        float l1 = (zm >= 0.f) ? -log1pf(expf(-zm)) : zm - log1pf(expf(zm));
        l1 = fmaxf(l1, -41.446531673892822f);
        g_sB[b] = s;
        g_l1m[b] = l1;
        sh[0] = l1;
        sh[1] = g_lse[b];
    }
    __syncthreads();
    if (t < 128)
        d_out[(size_t)b * LOGN + VOUT + t] = sh[0] + g_scores[b * L + t] - sh[1];
}

// ---------------- K11a/b: log-sum-exp over VOUT per batch ----------------
__global__ void k11a_lse() {
    __shared__ float pm[8][32];
    __shared__ float ps[8][32];
    int w = threadIdx.x >> 5, lane = threadIdx.x & 31;
    int base = blockIdx.x * 1024 + w * 128;
    float m = -INFINITY, s = 0.f;
    for (int i = 0; i < 128; i++) {
        int v = base + i;
        if (v < VOUT) {
            float x = g_wgout[(size_t)v * B + lane];
            if (x > m) { s = s * expf(m - x) + 1.f; m = x; }
            else       { s += expf(x - m); }
        }
    }
    pm[w][lane] = m; ps[w][lane] = s;
    __syncthreads();
    if (w == 0) {
        float M = pm[0][lane], S = ps[0][lane];
#pragma unroll
        for (int i = 1; i < 8; i++) {
            float m2 = pm[i][lane], s2 = ps[i][lane];
            float nm = fmaxf(M, m2);
            S = S * expf(M - nm) + s2 * expf(m2 - nm);
            M = nm;
        }
        g_pmax[blockIdx.x * 32 + lane] = M;
        g_psum[blockIdx.x * 32 + lane] = S;
    }
}

__global__ void k11b_lse() {
    int b = threadIdx.x;
    float M = g_pmax[b], S = g_psum[b];
    for (int i = 1; i < NCHUNK; i++) {
        float m2 = g_pmax[i * 32 + b], s2 = g_psum[i * 32 + b];
        float nm = fmaxf(M, m2);
        S = S * expf(M - nm) + s2 * expf(m2 - nm);
        M = nm;
    }
    g_wlse[b] = M + logf(S);
}

// ---------------- K12: transpose + final vocab logits write ----------------
__global__ void k12_out(float* __restrict__ d_out) {
    __shared__ float sm[32][33];
    int tx = threadIdx.x & 31, ty = threadIdx.x >> 5;  // 32 x 8
    int v0 = blockIdx.x * 32;
#pragma unroll
    for (int r = 0; r < 4; r++) {
        int row = r * 8 + ty;
        int v = v0 + row;
        if (v > VOUT - 1) v = VOUT - 1;
        sm[row][tx] = g_wgout[(size_t)v * B + tx];
    }
    __syncthreads();
#pragma unroll
    for (int r = 0; r < 4; r++) {
        int b = r * 8 + ty;
        int v = v0 + tx;
        if (v < VOUT)
            d_out[(size_t)b * LOGN + v] = g_sB[b] + sm[tx][b] - g_wlse[b];
    }
}

// ---------------- launch ----------------
extern "C" void kernel_launch(void* const* d_in, const int* in_sizes, int n_in,
                              void* d_out, int out_size) {
    const int*   n_input  = (const int*)d_in[0];
    const int*   t_input  = (const int*)d_in[1];
    const float* h0       = (const float*)d_in[2];
    const float* c0       = (const float*)d_in[3];
    const float* enc_out  = (const float*)d_in[4];
    const unsigned char* mask = (const unsigned char*)d_in[5];
    const float* h_parent = (const float*)d_in[6];
    const float* embN     = (const float*)d_in[7];
    const float* embT     = (const float*)d_in[8];
    const float* W_ih     = (const float*)d_in[9];
    const float* W_hh     = (const float*)d_in[10];
    const float* b_ih     = (const float*)d_in[11];
    const float* b_hh     = (const float*)d_in[12];
    const float* Wh_w     = (const float*)d_in[13];
    const float* Wh_b     = (const float*)d_in[14];
    const float* Wm_w     = (const float*)d_in[15];
    const float* Wm_b     = (const float*)d_in[16];
    const float* v_w      = (const float*)d_in[17];
    const float* v_b      = (const float*)d_in[18];
    const float* wg_w     = (const float*)d_in[19];
    const float* wg_b     = (const float*)d_in[20];
    const float* ws_w     = (const float*)d_in[21];
    const float* ws_b     = (const float*)d_in[22];
    float* out = (float*)d_out;

    float* gatesP; cudaGetSymbolAddress((void**)&gatesP, g_gates);
    float* qTP;    cudaGetSymbolAddress((void**)&qTP, g_qT);
    float* wgoutP; cudaGetSymbolAddress((void**)&wgoutP, g_wgout);
    float* xhTP;   cudaGetSymbolAddress((void**)&xhTP, g_xhT);
    float* featTP; cudaGetSymbolAddress((void**)&featTP, g_featT);

    k1_prep<<<B, 256>>>(n_input, t_input, h0, h_parent, embN, embT, v_b);
    // LSTM gates: [4096 x 1792] @ xhT
    gemm_k<64, false><<<G4 / 64, 128>>>(W_ih, EIN, EIN / 16, W_hh, H, H / 16,
                                        xhTP, b_ih, b_hh, gatesP, G4);
    k3_lstm<<<(B * H) / 256, 256>>>(c0, out);
    // q = Wh_w @ h_new + Wh_b  (h_new section of featT)
    gemm_k<32, false><<<H / 32, 128>>>(Wh_w, H, H / 16, (const float*)nullptr, 0, 0,
                                       featTP + H * B, Wh_b, (const float*)nullptr, qTP, H);
    k5_score<<<dim3(H / 64, B), 256>>>(enc_out, Wm_w, Wm_b, v_w);
    k7_ctx<<<B, 256>>>(enc_out, mask);
    k8_s<<<B, 256>>>(ws_w, ws_b, out);
    // vocab GEMM: [50003 x 3072] @ featT
    gemm_k<128, true><<<(VOUT + 127) / 128, 128>>>(wg_w, F3, F3 / 16, (const float*)nullptr, 0, 0,
                                                   featTP, wg_b, (const float*)nullptr, wgoutP, VOUT);
    k11a_lse<<<NCHUNK, 256>>>();
    k11b_lse<<<1, 32>>>();
    k12_out<<<(VOUT + 31) / 32, 256>>>(out);
}

// round 5
// speedup vs baseline: 1.3226x; 1.1331x over previous
#include <cuda_runtime.h>
#include <math.h>

typedef unsigned long long ull;

#define DI __device__ __forceinline__

DI ull pk2(float x, float y){ ull r; asm("mov.b64 %0,{%1,%2};" : "=l"(r) : "f"(x), "f"(y)); return r; }
DI void upk2(ull v, float& x, float& y){ asm("mov.b64 {%0,%1},%2;" : "=f"(x), "=f"(y) : "l"(v)); }
DI ull ffma2(ull a, ull b, ull c){ ull d; asm("fma.rn.f32x2 %0,%1,%2,%3;" : "=l"(d) : "l"(a), "l"(b), "l"(c)); return d; }

static constexpr int B    = 32;
static constexpr int L    = 128;
static constexpr int H    = 1024;
static constexpr int EN   = 256;
static constexpr int ET   = 512;
static constexpr int EIN  = 768;     // EN + ET
static constexpr int G4   = 4096;    // 4*H
static constexpr int VOUT = 50003;
static constexpr int LOGN = VOUT + L;       // 50131
static constexpr int F3   = 3072;           // 3*H
static constexpr int NLOG = B * LOGN;       // logits elements
static constexpr int NCHUNK = 49;           // ceil(50003/1024)

// ---------------- scratch ----------------
__device__ __align__(16) float g_xhT[(EIN + H) * B];   // [k][b]
__device__ __align__(16) float g_featT[F3 * B];        // [k][b]: context | h_new | h_parent
__device__ __align__(16) float g_gates[G4 * B];        // [j][b]
__device__ __align__(16) float g_qT[H * B];            // [j][b]
__device__ __align__(16) float g_scores[B * L];
__device__ float g_lse[B];
__device__ __align__(16) float g_context[B * H];
__device__ float g_sB[B];
__device__ float g_l1m[B];
__device__ __align__(16) float g_wgout[(VOUT + 32) * B]; // [v][b]
__device__ float g_pmax[NCHUNK * 32];
__device__ float g_psum[NCHUNK * 32];
__device__ float g_wlse[B];

// ---------------- K1: embeddings + staging + bias inits ----------------
__global__ void k1_prep(const int* __restrict__ n_in, const int* __restrict__ t_in,
                        const float* __restrict__ h0, const float* __restrict__ h_parent,
                        const float* __restrict__ embN, const float* __restrict__ embT,
                        const float* __restrict__ v_b,
                        const float* __restrict__ b_ih, const float* __restrict__ b_hh,
                        const float* __restrict__ Wh_b) {
    int b = blockIdx.x;
    int t = threadIdx.x;
    int n  = n_in[b];
    int tt = t_in[b];
    for (int k = t; k < EIN; k += blockDim.x) {
        float v = (k < EN) ? embN[n * EN + k] : embT[(size_t)tt * ET + (k - EN)];
        g_xhT[k * B + b] = v;
    }
    for (int k = t; k < H; k += blockDim.x) {
        g_xhT[(EIN + k) * B + b]     = h0[b * H + k];
        g_featT[(2 * H + k) * B + b] = h_parent[b * H + k];
        g_qT[k * B + b]              = Wh_b[k];            // bias init for split-K q
    }
    for (int j = t; j < G4; j += blockDim.x)
        g_gates[j * B + b] = b_ih[j] + b_hh[j];            // bias init for split-K gates
    if (t < L) g_scores[b * L + t] = v_b[0];
}

// ---------------- GEMM core: out[row][b] += A[row][:] . Bmat[:][b] ----------------
// 128 threads. Thread tile: 8? -> RT rows x 4 cols. 16 row-groups x 8 col-groups.
// A smem [k][row] pad2 (conflict-free), B smem pre-splatted pairs with swizzle.
// 2 smem stages + 2-tiles-ahead register prefetch. Optional split-K via blockIdx.y (ATOMIC).
template<int RT, bool CLAMP, bool ATOMIC>
__global__ void __launch_bounds__(128) gemm2(const float* __restrict__ A1, int ldA1, int kb1,
                                             const float* __restrict__ A2, int ldA2,
                                             const float* __restrict__ Bmat,
                                             const float* __restrict__ bias,
                                             float* __restrict__ out, int rows,
                                             int tilesPerChunk) {
    constexpr int BM   = 16 * RT;
    constexpr int LDAS = BM + 2;      // 130 or 66: 4*LDAS%32==8 -> conflict-free STS
    constexpr int LDBS = 66;          // splatted B row (max pos 64)
    constexpr int NA4  = BM / 32;     // float4 A loads per thread per tile
    constexpr int RP   = RT / 2;
    __shared__ __align__(16) float As[2][16 * LDAS];
    __shared__ __align__(16) float Bs[2][16 * LDBS];
    int tid = threadIdx.x;
    int r0  = blockIdx.x * BM;
    int t0  = blockIdx.y * tilesPerChunk;
    int nkt = tilesPerChunk;
    int rg = tid >> 3, cg = tid & 7;
    int rbase = rg * RT;
    int b0 = cg * 4;
    int cpos0 = 2 * b0 + 2 * (b0 >> 4);   // swizzled splat base; cols contiguous +2c
    int kkB = tid >> 3;                    // B loader k-row

    ull acc[RP][4];
    ull z = pk2(0.f, 0.f);
#pragma unroll
    for (int p = 0; p < RP; p++)
#pragma unroll
        for (int c = 0; c < 4; c++) acc[p][c] = z;

    float4 rA[2][NA4];
    float4 rB[2];

    auto ld = [&](int t, int buf) {
        const float* A; int ld_; int kt;
        if (t < kb1) { A = A1; ld_ = ldA1; kt = t; }
        else         { A = A2; ld_ = ldA2; kt = t - kb1; }
        int k0 = kt * 16;
#pragma unroll
        for (int i = 0; i < NA4; i++) {
            int idx = i * 128 + tid;
            int row = idx >> 2, c4 = idx & 3;
            int rr = r0 + row;
            if (CLAMP && rr > rows - 1) rr = rows - 1;
            rA[buf][i] = *(const float4*)&A[(size_t)rr * ld_ + k0 + 4 * c4];
        }
        rB[buf] = *(const float4*)&Bmat[(size_t)(t * 16 + kkB) * 32 + b0];
    };
    auto st = [&](int s) {
        float* AD = As[s];
#pragma unroll
        for (int i = 0; i < NA4; i++) {
            int idx = i * 128 + tid;
            int row = idx >> 2, c4 = idx & 3;
            AD[(4 * c4 + 0) * LDAS + row] = rA[s][i].x;
            AD[(4 * c4 + 1) * LDAS + row] = rA[s][i].y;
            AD[(4 * c4 + 2) * LDAS + row] = rA[s][i].z;
            AD[(4 * c4 + 3) * LDAS + row] = rA[s][i].w;
        }
        float* BD = &Bs[s][kkB * LDBS + cpos0];
        *(ull*)&BD[0] = pk2(rB[s].x, rB[s].x);
        *(ull*)&BD[2] = pk2(rB[s].y, rB[s].y);
        *(ull*)&BD[4] = pk2(rB[s].z, rB[s].z);
        *(ull*)&BD[6] = pk2(rB[s].w, rB[s].w);
    };
    auto comp = [&](int s) {
        const float* AD = As[s];
        const float* BD = Bs[s];
#pragma unroll
        for (int k = 0; k < 16; k++) {
            ull b2[4];
#pragma unroll
            for (int c = 0; c < 4; c++)
                b2[c] = *(const ull*)&BD[k * LDBS + cpos0 + 2 * c];
#pragma unroll
            for (int p = 0; p < RP; p++) {
                ull a2 = *(const ull*)&AD[k * LDAS + rbase + 2 * p];
#pragma unroll
                for (int c = 0; c < 4; c++)
                    acc[p][c] = ffma2(a2, b2[c], acc[p][c]);
            }
        }
    };

    ld(t0, 0);
    ld(t0 + 1, 1);
    st(0);
    __syncthreads();
    for (int tt = 0; tt < nkt; tt++) {
        if (tt + 1 < nkt) st((tt + 1) & 1);
        if (tt + 2 < nkt) ld(t0 + tt + 2, tt & 1);
        comp(tt & 1);
        __syncthreads();
    }

#pragma unroll
    for (int p = 0; p < RP; p++) {
        int ra = r0 + rbase + 2 * p;
        float4 lo, hi;
        upk2(acc[p][0], lo.x, hi.x);
        upk2(acc[p][1], lo.y, hi.y);
        upk2(acc[p][2], lo.z, hi.z);
        upk2(acc[p][3], lo.w, hi.w);
        if (ATOMIC) {
            atomicAdd(&out[(size_t)ra * 32 + b0 + 0], lo.x);
            atomicAdd(&out[(size_t)ra * 32 + b0 + 1], lo.y);
            atomicAdd(&out[(size_t)ra * 32 + b0 + 2], lo.z);
            atomicAdd(&out[(size_t)ra * 32 + b0 + 3], lo.w);
            atomicAdd(&out[(size_t)(ra + 1) * 32 + b0 + 0], hi.x);
            atomicAdd(&out[(size_t)(ra + 1) * 32 + b0 + 1], hi.y);
            atomicAdd(&out[(size_t)(ra + 1) * 32 + b0 + 2], hi.z);
            atomicAdd(&out[(size_t)(ra + 1) * 32 + b0 + 3], hi.w);
        } else {
            if (!CLAMP || ra < rows) {
                float bb = bias[ra];
                lo.x += bb; lo.y += bb; lo.z += bb; lo.w += bb;
                *(float4*)&out[(size_t)ra * 32 + b0] = lo;
            }
            if (!CLAMP || ra + 1 < rows) {
                float bb = bias[ra + 1];
                hi.x += bb; hi.y += bb; hi.z += bb; hi.w += bb;
                *(float4*)&out[(size_t)(ra + 1) * 32 + b0] = hi;
            }
        }
    }
}

// ---------------- K3: LSTM pointwise ----------------
__global__ void k3_lstm(const float* __restrict__ c0, float* __restrict__ d_out) {
    int idx = blockIdx.x * blockDim.x + threadIdx.x;   // 32768 total
    int b = idx & 31, j = idx >> 5;
    float gi = g_gates[j * B + b];
    float gf = g_gates[(H + j) * B + b];
    float gg = g_gates[(2 * H + j) * B + b];
    float go = g_gates[(3 * H + j) * B + b];
    float cp = c0[b * H + j];
    float si = 1.f / (1.f + expf(-gi));
    float sf = 1.f / (1.f + expf(-gf));
    float so = 1.f / (1.f + expf(-go));
    float cn = sf * cp + si * tanhf(gg);
    float hn = so * tanhf(cn);
    g_featT[(H + j) * B + b] = hn;
    d_out[NLOG + b * H + j] = hn;
    d_out[NLOG + B * H + b * H + j] = cn;
}

// ---------------- K5: attention GEMM + fused v*tanh epilogue ----------------
// 256 threads. rows = 128 L, cols = 64 n. Thread tile 8x4. Same core structure.
__global__ void __launch_bounds__(256) k5_score(const float* __restrict__ enc,
                                                const float* __restrict__ Wm_w,
                                                const float* __restrict__ Wm_b,
                                                const float* __restrict__ v_w) {
    constexpr int LDAS = 130;
    constexpr int LDBS = 134;   // splatted 64 cols: max pos 132
    __shared__ __align__(16) float As[2][16 * LDAS];
    __shared__ __align__(16) float Bs[2][16 * LDBS];
    __shared__ float red[128];
    int tid = threadIdx.x;
    int n0 = blockIdx.x * 64;
    int by = blockIdx.y;
    int rg = tid >> 4, cgx = tid & 15;
    int rbase = rg * 8;
    int nb0 = cgx * 4;
    int cpos0 = 2 * nb0 + 2 * (nb0 >> 4);
    const float* A = enc + (size_t)by * L * H;

    ull acc[4][4];
    ull z = pk2(0.f, 0.f);
#pragma unroll
    for (int p = 0; p < 4; p++)
#pragma unroll
        for (int c = 0; c < 4; c++) acc[p][c] = z;

    float4 rA[2][2];
    float4 rB[2];
    int nB = tid >> 2, bc4 = tid & 3;   // B loader: one n, 4 ks
    int bpos = 2 * nB + 2 * (nB >> 4);

    auto ld = [&](int t, int buf) {
        int k0 = t * 16;
#pragma unroll
        for (int i = 0; i < 2; i++) {
            int idx = i * 256 + tid;
            int row = idx >> 2, c4 = idx & 3;
            rA[buf][i] = *(const float4*)&A[row * H + k0 + 4 * c4];
        }
        rB[buf] = *(const float4*)&Wm_w[(size_t)(n0 + nB) * H + k0 + 4 * bc4];
    };
    auto st = [&](int s) {
        float* AD = As[s];
#pragma unroll
        for (int i = 0; i < 2; i++) {
            int idx = i * 256 + tid;
            int row = idx >> 2, c4 = idx & 3;
            AD[(4 * c4 + 0) * LDAS + row] = rA[s][i].x;
            AD[(4 * c4 + 1) * LDAS + row] = rA[s][i].y;
            AD[(4 * c4 + 2) * LDAS + row] = rA[s][i].z;
            AD[(4 * c4 + 3) * LDAS + row] = rA[s][i].w;
        }
        float* BD = Bs[s];
        *(ull*)&BD[(4 * bc4 + 0) * LDBS + bpos] = pk2(rB[s].x, rB[s].x);
        *(ull*)&BD[(4 * bc4 + 1) * LDBS + bpos] = pk2(rB[s].y, rB[s].y);
        *(ull*)&BD[(4 * bc4 + 2) * LDBS + bpos] = pk2(rB[s].z, rB[s].z);
        *(ull*)&BD[(4 * bc4 + 3) * LDBS + bpos] = pk2(rB[s].w, rB[s].w);
    };
    auto comp = [&](int s) {
        const float* AD = As[s];
        const float* BD = Bs[s];
#pragma unroll
        for (int k = 0; k < 16; k++) {
            ull b2[4];
#pragma unroll
            for (int c = 0; c < 4; c++)
                b2[c] = *(const ull*)&BD[k * LDBS + cpos0 + 2 * c];
#pragma unroll
            for (int p = 0; p < 4; p++) {
                ull a2 = *(const ull*)&AD[k * LDAS + rbase + 2 * p];
#pragma unroll
                for (int c = 0; c < 4; c++)
                    acc[p][c] = ffma2(a2, b2[c], acc[p][c]);
            }
        }
    };

    ld(0, 0);
    ld(1, 1);
    st(0);
    __syncthreads();
    constexpr int NKT = H / 16;
    for (int tt = 0; tt < NKT; tt++) {
        if (tt + 1 < NKT) st((tt + 1) & 1);
        if (tt + 2 < NKT) ld(tt + 2, tt & 1);
        comp(tt & 1);
        __syncthreads();
    }

    if (tid < 128) red[tid] = 0.f;
    __syncthreads();
    float4 vw = *(const float4*)&v_w[n0 + nb0];
    float4 mb = *(const float4*)&Wm_b[n0 + nb0];
    float qv0 = g_qT[(n0 + nb0 + 0) * B + by];
    float qv1 = g_qT[(n0 + nb0 + 1) * B + by];
    float qv2 = g_qT[(n0 + nb0 + 2) * B + by];
    float qv3 = g_qT[(n0 + nb0 + 3) * B + by];
#pragma unroll
    for (int p = 0; p < 4; p++) {
        float4 lo, hi;
        upk2(acc[p][0], lo.x, hi.x);
        upk2(acc[p][1], lo.y, hi.y);
        upk2(acc[p][2], lo.z, hi.z);
        upk2(acc[p][3], lo.w, hi.w);
        float plo = vw.x * tanhf(lo.x + mb.x + qv0) + vw.y * tanhf(lo.y + mb.y + qv1)
                  + vw.z * tanhf(lo.z + mb.z + qv2) + vw.w * tanhf(lo.w + mb.w + qv3);
        float phi = vw.x * tanhf(hi.x + mb.x + qv0) + vw.y * tanhf(hi.y + mb.y + qv1)
                  + vw.z * tanhf(hi.z + mb.z + qv2) + vw.w * tanhf(hi.w + mb.w + qv3);
        atomicAdd(&red[rbase + 2 * p], plo);
        atomicAdd(&red[rbase + 2 * p + 1], phi);
    }
    __syncthreads();
    if (tid < 128) atomicAdd(&g_scores[by * L + tid], red[tid]);
}

// ---------------- K7: softmax over L + context ----------------
__global__ void k7_ctx(const float* __restrict__ enc, const unsigned char* __restrict__ mask) {
    __shared__ float sc[128];
    __shared__ float redm[16];
    int b = blockIdx.x, t = threadIdx.x;
    if (t < 128) {
        float s = g_scores[b * L + t];
        if (mask[b * L + t]) s = -1e20f;
        sc[t] = s;
        g_scores[b * L + t] = s;
    }
    __syncthreads();
    float m = (t < 128) ? sc[t] : -INFINITY;
#pragma unroll
    for (int o = 16; o > 0; o >>= 1) m = fmaxf(m, __shfl_xor_sync(~0u, m, o));
    if ((t & 31) == 0) redm[t >> 5] = m;
    __syncthreads();
    if (t == 0) {
        float mm = redm[0];
        for (int w = 1; w < 8; w++) mm = fmaxf(mm, redm[w]);
        redm[0] = mm;
    }
    __syncthreads();
    float mx = redm[0];
    float e = (t < 128) ? expf(sc[t] - mx) : 0.f;
    float s = e;
#pragma unroll
    for (int o = 16; o > 0; o >>= 1) s += __shfl_xor_sync(~0u, s, o);
    if ((t & 31) == 0) redm[8 + (t >> 5)] = s;
    __syncthreads();
    if (t == 0) {
        float ss = 0.f;
        for (int w = 0; w < 8; w++) ss += redm[8 + w];
        redm[8] = ss;
    }
    __syncthreads();
    float sum = redm[8];
    if (t < 128) sc[t] = e / sum;
    if (t == 0) g_lse[b] = mx + logf(sum);
    __syncthreads();
    const float* E = enc + (size_t)b * L * H;
#pragma unroll
    for (int jj = 0; jj < 4; jj++) {
        int j = t + jj * 256;
        float a = 0.f;
#pragma unroll 4
        for (int l = 0; l < 128; l++) a += sc[l] * E[l * H + j];
        g_context[b * H + j] = a;
        g_featT[j * B + b] = a;
    }
}

// ---------------- K8: pointer switch + copy-logits ----------------
__global__ void k8_s(const float* __restrict__ ws_w, const float* __restrict__ ws_b,
                     float* __restrict__ d_out) {
    __shared__ float red[8];
    __shared__ float sh[2];
    int b = blockIdx.x, t = threadIdx.x;
    float a = 0.f;
    for (int j = t; j < H; j += 256) a += g_context[b * H + j] * ws_w[j];
    for (int j = t; j < H; j += 256) a += g_featT[(H + j) * B + b] * ws_w[H + j];
#pragma unroll
    for (int o = 16; o > 0; o >>= 1) a += __shfl_xor_sync(~0u, a, o);
    if ((t & 31) == 0) red[t >> 5] = a;
    __syncthreads();
    if (t == 0) {
        float zz = ws_b[0];
        for (int w = 0; w < 8; w++) zz += red[w];
        float s  = (zz >= 0.f) ? -log1pf(expf(-zz)) : zz - log1pf(expf(zz));
        float zm = -zz;
        float l1 = (zm >= 0.f) ? -log1pf(expf(-zm)) : zm - log1pf(expf(zm));
        l1 = fmaxf(l1, -41.446531673892822f);
        g_sB[b] = s;
        g_l1m[b] = l1;
        sh[0] = l1;
        sh[1] = g_lse[b];
    }
    __syncthreads();
    if (t < 128)
        d_out[(size_t)b * LOGN + VOUT + t] = sh[0] + g_scores[b * L + t] - sh[1];
}

// ---------------- K11a/b: log-sum-exp over VOUT ----------------
__global__ void k11a_lse() {
    __shared__ float pm[8][32];
    __shared__ float ps[8][32];
    int w = threadIdx.x >> 5, lane = threadIdx.x & 31;
    int base = blockIdx.x * 1024 + w * 128;
    float m = -INFINITY, s = 0.f;
    for (int i = 0; i < 128; i++) {
        int v = base + i;
        if (v < VOUT) {
            float x = g_wgout[(size_t)v * B + lane];
            if (x > m) { s = s * expf(m - x) + 1.f; m = x; }
            else       { s += expf(x - m); }
        }
    }
    pm[w][lane] = m; ps[w][lane] = s;
    __syncthreads();
    if (w == 0) {
        float M = pm[0][lane], S = ps[0][lane];
#pragma unroll
        for (int i = 1; i < 8; i++) {
            float m2 = pm[i][lane], s2 = ps[i][lane];
            float nm = fmaxf(M, m2);
            S = S * expf(M - nm) + s2 * expf(m2 - nm);
            M = nm;
        }
        g_pmax[blockIdx.x * 32 + lane] = M;
        g_psum[blockIdx.x * 32 + lane] = S;
    }
}

__global__ void k11b_lse() {
    int b = threadIdx.x;
    float M = g_pmax[b], S = g_psum[b];
    for (int i = 1; i < NCHUNK; i++) {
        float m2 = g_pmax[i * 32 + b], s2 = g_psum[i * 32 + b];
        float nm = fmaxf(M, m2);
        S = S * expf(M - nm) + s2 * expf(m2 - nm);
        M = nm;
    }
    g_wlse[b] = M + logf(S);
}

// ---------------- K12: transpose + final vocab logits ----------------
__global__ void k12_out(float* __restrict__ d_out) {
    __shared__ float sm[32][33];
    int tx = threadIdx.x & 31, ty = threadIdx.x >> 5;
    int v0 = blockIdx.x * 32;
#pragma unroll
    for (int r = 0; r < 4; r++) {
        int row = r * 8 + ty;
        int v = v0 + row;
        if (v > VOUT - 1) v = VOUT - 1;
        sm[row][tx] = g_wgout[(size_t)v * B + tx];
    }
    __syncthreads();
#pragma unroll
    for (int r = 0; r < 4; r++) {
        int b = r * 8 + ty;
        int v = v0 + tx;
        if (v < VOUT)
            d_out[(size_t)b * LOGN + v] = g_sB[b] + sm[tx][b] - g_wlse[b];
    }
}

// ---------------- launch ----------------
extern "C" void kernel_launch(void* const* d_in, const int* in_sizes, int n_in,
                              void* d_out, int out_size) {
    const int*   n_input  = (const int*)d_in[0];
    const int*   t_input  = (const int*)d_in[1];
    const float* h0       = (const float*)d_in[2];
    const float* c0       = (const float*)d_in[3];
    const float* enc_out  = (const float*)d_in[4];
    const unsigned char* mask = (const unsigned char*)d_in[5];
    const float* h_parent = (const float*)d_in[6];
    const float* embN     = (const float*)d_in[7];
    const float* embT     = (const float*)d_in[8];
    const float* W_ih     = (const float*)d_in[9];
    const float* W_hh     = (const float*)d_in[10];
    const float* b_ih     = (const float*)d_in[11];
    const float* b_hh     = (const float*)d_in[12];
    const float* Wh_w     = (const float*)d_in[13];
    const float* Wh_b     = (const float*)d_in[14];
    const float* Wm_w     = (const float*)d_in[15];
    const float* Wm_b     = (const float*)d_in[16];
    const float* v_w      = (const float*)d_in[17];
    const float* v_b      = (const float*)d_in[18];
    const float* wg_w     = (const float*)d_in[19];
    const float* wg_b     = (const float*)d_in[20];
    const float* ws_w     = (const float*)d_in[21];
    const float* ws_b     = (const float*)d_in[22];
    float* out = (float*)d_out;

    float* gatesP; cudaGetSymbolAddress((void**)&gatesP, g_gates);
    float* qTP;    cudaGetSymbolAddress((void**)&qTP, g_qT);
    float* wgoutP; cudaGetSymbolAddress((void**)&wgoutP, g_wgout);
    float* xhTP;   cudaGetSymbolAddress((void**)&xhTP, g_xhT);
    float* featTP; cudaGetSymbolAddress((void**)&featTP, g_featT);

    k1_prep<<<B, 256>>>(n_input, t_input, h0, h_parent, embN, embT, v_b, b_ih, b_hh, Wh_b);
    // LSTM gates: [4096 x 1792], BM=64, split-K x2 (56 tiles each), atomic accumulate
    gemm2<4, false, true><<<dim3(G4 / 64, 2), 128>>>(W_ih, EIN, EIN / 16, W_hh, H,
                                                     xhTP, (const float*)nullptr, gatesP, G4, 56);
    k3_lstm<<<(B * H) / 256, 256>>>(c0, out);
    // q: [1024 x 1024], BM=64, split-K x4 (16 tiles each), atomic accumulate
    gemm2<4, false, true><<<dim3(H / 64, 4), 128>>>(Wh_w, H, H / 16, (const float*)nullptr, 0,
                                                    featTP + H * B, (const float*)nullptr, qTP, H, 16);
    k5_score<<<dim3(H / 64, B), 256>>>(enc_out, Wm_w, Wm_b, v_w);
    k7_ctx<<<B, 256>>>(enc_out, mask);
    k8_s<<<B, 256>>>(ws_w, ws_b, out);
    // vocab GEMM: [50003 x 3072], BM=128
    gemm2<8, true, false><<<dim3((VOUT + 127) / 128, 1), 128>>>(wg_w, F3, F3 / 16,
                                                                (const float*)nullptr, 0,
                                                                featTP, wg_b, wgoutP, VOUT, F3 / 16);
    k11a_lse<<<NCHUNK, 256>>>();
    k11b_lse<<<1, 32>>>();
    k12_out<<<(VOUT + 31) / 32, 256>>>(out);
}

// round 7
// speedup vs baseline: 1.8395x; 1.3908x over previous
#include <cuda_runtime.h>
#include <cuda_bf16.h>
#include <math.h>

typedef unsigned long long ull;
typedef unsigned int u32;

#define DI __device__ __forceinline__

DI ull pk2(float x, float y){ ull r; asm("mov.b64 %0,{%1,%2};" : "=l"(r) : "f"(x), "f"(y)); return r; }
DI void upk2(ull v, float& x, float& y){ asm("mov.b64 {%0,%1},%2;" : "=f"(x), "=f"(y) : "l"(v)); }
DI ull ffma2(ull a, ull b, ull c){ ull d; asm("fma.rn.f32x2 %0,%1,%2,%3;" : "=l"(d) : "l"(a), "l"(b), "l"(c)); return d; }
DI u32 pkbf(float a, float b){ u32 r; asm("cvt.rn.bf16x2.f32 %0, %1, %2;" : "=r"(r) : "f"(b), "f"(a)); return r; }  // mem order [a,b]
DI float bfres(float v){ __nv_bfloat16 h = __float2bfloat16(v); return v - __bfloat162float(h); }

// warp mma: D[16x8] += A[16x16,row] * B[16x8,col], bf16 in, fp32 accum
DI void mma16816(float* d, const u32* a, u32 b0, u32 b1){
    asm volatile("mma.sync.aligned.m16n8k16.row.col.f32.bf16.bf16.f32 "
        "{%0,%1,%2,%3},{%4,%5,%6,%7},{%8,%9},{%0,%1,%2,%3};"
        : "+f"(d[0]), "+f"(d[1]), "+f"(d[2]), "+f"(d[3])
        : "r"(a[0]), "r"(a[1]), "r"(a[2]), "r"(a[3]), "r"(b0), "r"(b1));
}

static constexpr int B    = 32;
static constexpr int L    = 128;
static constexpr int H    = 1024;
static constexpr int EN   = 256;
static constexpr int ET   = 512;
static constexpr int EIN  = 768;
static constexpr int G4   = 4096;
static constexpr int VOUT = 50003;
static constexpr int LOGN = VOUT + L;
static constexpr int F3   = 3072;
static constexpr int NLOG = B * LOGN;
static constexpr int NCHUNK = 49;

// ---------------- scratch ----------------
__device__ __align__(16) float g_xhT[(EIN + H) * B];
__device__ __align__(16) float g_featT[F3 * B];
__device__ __align__(16) float g_gates[G4 * B];
__device__ __align__(16) float g_qT[H * B];
__device__ __align__(16) float g_scores[B * L];
__device__ float g_lse[B];
__device__ __align__(16) float g_context[B * H];
__device__ float g_sB[B];
__device__ float g_l1m[B];
__device__ __align__(16) float g_wgout[(VOUT + 64) * B];
__device__ float g_pmax[NCHUNK * 32];
__device__ float g_psum[NCHUNK * 32];
__device__ float g_wlse[B];
__device__ __align__(16) __nv_bfloat16 g_fhi[B * F3];
__device__ __align__(16) __nv_bfloat16 g_flo[B * F3];

// ---------------- K1: embeddings + staging + bias inits ----------------
__global__ void k1_prep(const int* __restrict__ n_in, const int* __restrict__ t_in,
                        const float* __restrict__ h0, const float* __restrict__ h_parent,
                        const float* __restrict__ embN, const float* __restrict__ embT,
                        const float* __restrict__ v_b,
                        const float* __restrict__ b_ih, const float* __restrict__ b_hh,
                        const float* __restrict__ Wh_b) {
    int b = blockIdx.x;
    int t = threadIdx.x;
    int n  = n_in[b];
    int tt = t_in[b];
    for (int k = t; k < EIN; k += blockDim.x) {
        float v = (k < EN) ? embN[n * EN + k] : embT[(size_t)tt * ET + (k - EN)];
        g_xhT[k * B + b] = v;
    }
    for (int k = t; k < H; k += blockDim.x) {
        g_xhT[(EIN + k) * B + b]     = h0[b * H + k];
        g_featT[(2 * H + k) * B + b] = h_parent[b * H + k];
        g_qT[k * B + b]              = Wh_b[k];
    }
    for (int j = t; j < G4; j += blockDim.x)
        g_gates[j * B + b] = b_ih[j] + b_hh[j];
    if (t < L) g_scores[b * L + t] = v_b[0];
}

// ---------------- FFMA2 GEMM core (gates/q) ----------------
template<int RT, bool CLAMP, bool ATOMIC>
__global__ void __launch_bounds__(128) gemm2(const float* __restrict__ A1, int ldA1, int kb1,
                                             const float* __restrict__ A2, int ldA2,
                                             const float* __restrict__ Bmat,
                                             const float* __restrict__ bias,
                                             float* __restrict__ out, int rows,
                                             int tilesPerChunk) {
    constexpr int BM   = 16 * RT;
    constexpr int LDAS = BM + 2;
    constexpr int LDBS = 66;
    constexpr int NA4  = BM / 32;
    constexpr int RP   = RT / 2;
    __shared__ __align__(16) float As[2][16 * LDAS];
    __shared__ __align__(16) float Bs[2][16 * LDBS];
    int tid = threadIdx.x;
    int r0  = blockIdx.x * BM;
    int t0  = blockIdx.y * tilesPerChunk;
    int nkt = tilesPerChunk;
    int rg = tid >> 3, cg = tid & 7;
    int rbase = rg * RT;
    int b0 = cg * 4;
    int cpos0 = 2 * b0 + 2 * (b0 >> 4);
    int kkB = tid >> 3;

    ull acc[RP][4];
    ull z = pk2(0.f, 0.f);
#pragma unroll
    for (int p = 0; p < RP; p++)
#pragma unroll
        for (int c = 0; c < 4; c++) acc[p][c] = z;

    float4 rA[2][NA4];
    float4 rB[2];

    auto ld = [&](int t, int buf) {
        const float* A; int ld_; int kt;
        if (t < kb1) { A = A1; ld_ = ldA1; kt = t; }
        else         { A = A2; ld_ = ldA2; kt = t - kb1; }
        int k0 = kt * 16;
#pragma unroll
        for (int i = 0; i < NA4; i++) {
            int idx = i * 128 + tid;
            int row = idx >> 2, c4 = idx & 3;
            int rr = r0 + row;
            if (CLAMP && rr > rows - 1) rr = rows - 1;
            rA[buf][i] = *(const float4*)&A[(size_t)rr * ld_ + k0 + 4 * c4];
        }
        rB[buf] = *(const float4*)&Bmat[(size_t)(t * 16 + kkB) * 32 + b0];
    };
    auto st = [&](int s) {
        float* AD = As[s];
#pragma unroll
        for (int i = 0; i < NA4; i++) {
            int idx = i * 128 + tid;
            int row = idx >> 2, c4 = idx & 3;
            AD[(4 * c4 + 0) * LDAS + row] = rA[s][i].x;
            AD[(4 * c4 + 1) * LDAS + row] = rA[s][i].y;
            AD[(4 * c4 + 2) * LDAS + row] = rA[s][i].z;
            AD[(4 * c4 + 3) * LDAS + row] = rA[s][i].w;
        }
        float* BD = &Bs[s][kkB * LDBS + cpos0];
        *(ull*)&BD[0] = pk2(rB[s].x, rB[s].x);
        *(ull*)&BD[2] = pk2(rB[s].y, rB[s].y);
        *(ull*)&BD[4] = pk2(rB[s].z, rB[s].z);
        *(ull*)&BD[6] = pk2(rB[s].w, rB[s].w);
    };
    auto comp = [&](int s) {
        const float* AD = As[s];
        const float* BD = Bs[s];
#pragma unroll
        for (int k = 0; k < 16; k++) {
            ull b2[4];
#pragma unroll
            for (int c = 0; c < 4; c++)
                b2[c] = *(const ull*)&BD[k * LDBS + cpos0 + 2 * c];
#pragma unroll
            for (int p = 0; p < RP; p++) {
                ull a2 = *(const ull*)&AD[k * LDAS + rbase + 2 * p];
#pragma unroll
                for (int c = 0; c < 4; c++)
                    acc[p][c] = ffma2(a2, b2[c], acc[p][c]);
            }
        }
    };

    ld(t0, 0);
    ld(t0 + 1, 1);
    st(0);
    __syncthreads();
    for (int tt = 0; tt < nkt; tt++) {
        if (tt + 1 < nkt) st((tt + 1) & 1);
        if (tt + 2 < nkt) ld(t0 + tt + 2, tt & 1);
        comp(tt & 1);
        __syncthreads();
    }

#pragma unroll
    for (int p = 0; p < RP; p++) {
        int ra = r0 + rbase + 2 * p;
        float4 lo, hi;
        upk2(acc[p][0], lo.x, hi.x);
        upk2(acc[p][1], lo.y, hi.y);
        upk2(acc[p][2], lo.z, hi.z);
        upk2(acc[p][3], lo.w, hi.w);
        if (ATOMIC) {
            atomicAdd(&out[(size_t)ra * 32 + b0 + 0], lo.x);
            atomicAdd(&out[(size_t)ra * 32 + b0 + 1], lo.y);
            atomicAdd(&out[(size_t)ra * 32 + b0 + 2], lo.z);
            atomicAdd(&out[(size_t)ra * 32 + b0 + 3], lo.w);
            atomicAdd(&out[(size_t)(ra + 1) * 32 + b0 + 0], hi.x);
            atomicAdd(&out[(size_t)(ra + 1) * 32 + b0 + 1], hi.y);
            atomicAdd(&out[(size_t)(ra + 1) * 32 + b0 + 2], hi.z);
            atomicAdd(&out[(size_t)(ra + 1) * 32 + b0 + 3], hi.w);
        } else {
            if (!CLAMP || ra < rows) {
                float bb = bias[ra];
                lo.x += bb; lo.y += bb; lo.z += bb; lo.w += bb;
                *(float4*)&out[(size_t)ra * 32 + b0] = lo;
            }
            if (!CLAMP || ra + 1 < rows) {
                float bb = bias[ra + 1];
                hi.x += bb; hi.y += bb; hi.z += bb; hi.w += bb;
                *(float4*)&out[(size_t)(ra + 1) * 32 + b0] = hi;
            }
        }
    }
}

// ---------------- K3: LSTM pointwise ----------------
__global__ void k3_lstm(const float* __restrict__ c0, float* __restrict__ d_out) {
    int idx = blockIdx.x * blockDim.x + threadIdx.x;
    int b = idx & 31, j = idx >> 5;
    float gi = g_gates[j * B + b];
    float gf = g_gates[(H + j) * B + b];
    float gg = g_gates[(2 * H + j) * B + b];
    float go = g_gates[(3 * H + j) * B + b];
    float cp = c0[b * H + j];
    float si = 1.f / (1.f + expf(-gi));
    float sf = 1.f / (1.f + expf(-gf));
    float so = 1.f / (1.f + expf(-go));
    float cn = sf * cp + si * tanhf(gg);
    float hn = so * tanhf(cn);
    g_featT[(H + j) * B + b] = hn;
    d_out[NLOG + b * H + j] = hn;
    d_out[NLOG + B * H + b * H + j] = cn;
}

// ---------------- K5: attention GEMM + fused v*tanh epilogue (FFMA2) ----------------
__global__ void __launch_bounds__(256) k5_score(const float* __restrict__ enc,
                                                const float* __restrict__ Wm_w,
                                                const float* __restrict__ Wm_b,
                                                const float* __restrict__ v_w) {
    constexpr int LDAS = 130;
    constexpr int LDBS = 134;
    __shared__ __align__(16) float As[2][16 * LDAS];
    __shared__ __align__(16) float Bs[2][16 * LDBS];
    __shared__ float red[128];
    int tid = threadIdx.x;
    int n0 = blockIdx.x * 64;
    int by = blockIdx.y;
    int rg = tid >> 4, cgx = tid & 15;
    int rbase = rg * 8;
    int nb0 = cgx * 4;
    int cpos0 = 2 * nb0 + 2 * (nb0 >> 4);
    const float* A = enc + (size_t)by * L * H;

    ull acc[4][4];
    ull z = pk2(0.f, 0.f);
#pragma unroll
    for (int p = 0; p < 4; p++)
#pragma unroll
        for (int c = 0; c < 4; c++) acc[p][c] = z;

    float4 rA[2][2];
    float4 rB[2];
    int nB = tid >> 2, bc4 = tid & 3;
    int bpos = 2 * nB + 2 * (nB >> 4);

    auto ld = [&](int t, int buf) {
        int k0 = t * 16;
#pragma unroll
        for (int i = 0; i < 2; i++) {
            int idx = i * 256 + tid;
            int row = idx >> 2, c4 = idx & 3;
            rA[buf][i] = *(const float4*)&A[row * H + k0 + 4 * c4];
        }
        rB[buf] = *(const float4*)&Wm_w[(size_t)(n0 + nB) * H + k0 + 4 * bc4];
    };
    auto st = [&](int s) {
        float* AD = As[s];
#pragma unroll
        for (int i = 0; i < 2; i++) {
            int idx = i * 256 + tid;
            int row = idx >> 2, c4 = idx & 3;
            AD[(4 * c4 + 0) * LDAS + row] = rA[s][i].x;
            AD[(4 * c4 + 1) * LDAS + row] = rA[s][i].y;
            AD[(4 * c4 + 2) * LDAS + row] = rA[s][i].z;
            AD[(4 * c4 + 3) * LDAS + row] = rA[s][i].w;
        }
        float* BD = Bs[s];
        *(ull*)&BD[(4 * bc4 + 0) * LDBS + bpos] = pk2(rB[s].x, rB[s].x);
        *(ull*)&BD[(4 * bc4 + 1) * LDBS + bpos] = pk2(rB[s].y, rB[s].y);
        *(ull*)&BD[(4 * bc4 + 2) * LDBS + bpos] = pk2(rB[s].z, rB[s].z);
        *(ull*)&BD[(4 * bc4 + 3) * LDBS + bpos] = pk2(rB[s].w, rB[s].w);
    };
    auto comp = [&](int s) {
        const float* AD = As[s];
        const float* BD = Bs[s];
#pragma unroll
        for (int k = 0; k < 16; k++) {
            ull b2[4];
#pragma unroll
            for (int c = 0; c < 4; c++)
                b2[c] = *(const ull*)&BD[k * LDBS + cpos0 + 2 * c];
#pragma unroll
            for (int p = 0; p < 4; p++) {
                ull a2 = *(const ull*)&AD[k * LDAS + rbase + 2 * p];
#pragma unroll
                for (int c = 0; c < 4; c++)
                    acc[p][c] = ffma2(a2, b2[c], acc[p][c]);
            }
        }
    };

    ld(0, 0);
    ld(1, 1);
    st(0);
    __syncthreads();
    constexpr int NKT = H / 16;
    for (int tt = 0; tt < NKT; tt++) {
        if (tt + 1 < NKT) st((tt + 1) & 1);
        if (tt + 2 < NKT) ld(tt + 2, tt & 1);
        comp(tt & 1);
        __syncthreads();
    }

    if (tid < 128) red[tid] = 0.f;
    __syncthreads();
    float4 vw = *(const float4*)&v_w[n0 + nb0];
    float4 mb = *(const float4*)&Wm_b[n0 + nb0];
    float qv0 = g_qT[(n0 + nb0 + 0) * B + by];
    float qv1 = g_qT[(n0 + nb0 + 1) * B + by];
    float qv2 = g_qT[(n0 + nb0 + 2) * B + by];
    float qv3 = g_qT[(n0 + nb0 + 3) * B + by];
#pragma unroll
    for (int p = 0; p < 4; p++) {
        float4 lo, hi;
        upk2(acc[p][0], lo.x, hi.x);
        upk2(acc[p][1], lo.y, hi.y);
        upk2(acc[p][2], lo.z, hi.z);
        upk2(acc[p][3], lo.w, hi.w);
        float plo = vw.x * tanhf(lo.x + mb.x + qv0) + vw.y * tanhf(lo.y + mb.y + qv1)
                  + vw.z * tanhf(lo.z + mb.z + qv2) + vw.w * tanhf(lo.w + mb.w + qv3);
        float phi = vw.x * tanhf(hi.x + mb.x + qv0) + vw.y * tanhf(hi.y + mb.y + qv1)
                  + vw.z * tanhf(hi.z + mb.z + qv2) + vw.w * tanhf(hi.w + mb.w + qv3);
        atomicAdd(&red[rbase + 2 * p], plo);
        atomicAdd(&red[rbase + 2 * p + 1], phi);
    }
    __syncthreads();
    if (tid < 128) atomicAdd(&g_scores[by * L + tid], red[tid]);
}

// ---------------- K7: softmax over L + context ----------------
__global__ void k7_ctx(const float* __restrict__ enc, const unsigned char* __restrict__ mask) {
    __shared__ float sc[128];
    __shared__ float redm[16];
    int b = blockIdx.x, t = threadIdx.x;
    if (t < 128) {
        float s = g_scores[b * L + t];
        if (mask[b * L + t]) s = -1e20f;
        sc[t] = s;
        g_scores[b * L + t] = s;
    }
    __syncthreads();
    float m = (t < 128) ? sc[t] : -INFINITY;
#pragma unroll
    for (int o = 16; o > 0; o >>= 1) m = fmaxf(m, __shfl_xor_sync(~0u, m, o));
    if ((t & 31) == 0) redm[t >> 5] = m;
    __syncthreads();
    if (t == 0) {
        float mm = redm[0];
        for (int w = 1; w < 8; w++) mm = fmaxf(mm, redm[w]);
        redm[0] = mm;
    }
    __syncthreads();
    float mx = redm[0];
    float e = (t < 128) ? expf(sc[t] - mx) : 0.f;
    float s = e;
#pragma unroll
    for (int o = 16; o > 0; o >>= 1) s += __shfl_xor_sync(~0u, s, o);
    if ((t & 31) == 0) redm[8 + (t >> 5)] = s;
    __syncthreads();
    if (t == 0) {
        float ss = 0.f;
        for (int w = 0; w < 8; w++) ss += redm[8 + w];
        redm[8] = ss;
    }
    __syncthreads();
    float sum = redm[8];
    if (t < 128) sc[t] = e / sum;
    if (t == 0) g_lse[b] = mx + logf(sum);
    __syncthreads();
    const float* E = enc + (size_t)b * L * H;
#pragma unroll
    for (int jj = 0; jj < 4; jj++) {
        int j = t + jj * 256;
        float a = 0.f;
#pragma unroll 4
        for (int l = 0; l < 128; l++) a += sc[l] * E[l * H + j];
        g_context[b * H + j] = a;
        g_featT[j * B + b] = a;
    }
}

// ---------------- K8: pointer switch + copy-logits ----------------
__global__ void k8_s(const float* __restrict__ ws_w, const float* __restrict__ ws_b,
                     float* __restrict__ d_out) {
    __shared__ float red[8];
    __shared__ float sh[2];
    int b = blockIdx.x, t = threadIdx.x;
    float a = 0.f;
    for (int j = t; j < H; j += 256) a += g_context[b * H + j] * ws_w[j];
    for (int j = t; j < H; j += 256) a += g_featT[(H + j) * B + b] * ws_w[H + j];
#pragma unroll
    for (int o = 16; o > 0; o >>= 1) a += __shfl_xor_sync(~0u, a, o);
    if ((t & 31) == 0) red[t >> 5] = a;
    __syncthreads();
    if (t == 0) {
        float zz = ws_b[0];
        for (int w = 0; w < 8; w++) zz += red[w];
        float s  = (zz >= 0.f) ? -log1pf(expf(-zz)) : zz - log1pf(expf(zz));
        float zm = -zz;
        float l1 = (zm >= 0.f) ? -log1pf(expf(-zm)) : zm - log1pf(expf(zm));
        l1 = fmaxf(l1, -41.446531673892822f);
        g_sB[b] = s;
        g_l1m[b] = l1;
        sh[0] = l1;
        sh[1] = g_lse[b];
    }
    __syncthreads();
    if (t < 128)
        d_out[(size_t)b * LOGN + VOUT + t] = sh[0] + g_scores[b * L + t] - sh[1];
}

// ---------------- K9: split features into bf16 hi/lo, [b][k] layout ----------------
__global__ void k9_split(__nv_bfloat16* __restrict__ fhi, __nv_bfloat16* __restrict__ flo) {
    int b = blockIdx.y;
    int k = blockIdx.x * 256 + threadIdx.x;
    float v = g_featT[k * B + b];
    __nv_bfloat16 h = __float2bfloat16(v);
    fhi[b * F3 + k] = h;
    flo[b * F3 + k] = __float2bfloat16(v - __bfloat162float(h));
}

// ---------------- K10: vocab GEMM via mma.sync bf16 3-pass split ----------------
// CTA: 128 vocab rows x 32 batches. 8 warps, warp w -> rows [16w,16w+16).
// K streamed in 48 chunks of 64. A converted fp32->bf16 hi/lo in-kernel.
static constexpr int KC   = 64;
static constexpr int NCHP = F3 / KC;   // 48
static constexpr int LDK  = 72;        // padded k-stride (halves) -> conflict-free

__global__ void __launch_bounds__(256) k10_mma(const float* __restrict__ wg_w,
                                               const float* __restrict__ wg_b,
                                               const __nv_bfloat16* __restrict__ fhi,
                                               const __nv_bfloat16* __restrict__ flo) {
    __shared__ __align__(16) __nv_bfloat16 sAhi[128 * LDK];
    __shared__ __align__(16) __nv_bfloat16 sAlo[128 * LDK];
    __shared__ __align__(16) __nv_bfloat16 sBhi[32 * LDK];
    __shared__ __align__(16) __nv_bfloat16 sBlo[32 * LDK];
    int tid = threadIdx.x, w = tid >> 5, lane = tid & 31;
    int r0 = blockIdx.x * 128;
    int g = lane >> 2, q = lane & 3;

    float d[4][4];
#pragma unroll
    for (int nb = 0; nb < 4; nb++)
#pragma unroll
        for (int c = 0; c < 4; c++) d[nb][c] = 0.f;

    for (int ch = 0; ch < NCHP; ch++) {
        int k0 = ch * KC;
        // LDG A: 128 rows x 64 fp32
        float4 av[8];
#pragma unroll
        for (int i = 0; i < 8; i++) {
            int idx = i * 256 + tid;
            int row = idx >> 4, c4 = idx & 15;
            int rr = r0 + row;
            if (rr > VOUT - 1) rr = VOUT - 1;
            av[i] = *(const float4*)&wg_w[(size_t)rr * F3 + k0 + 4 * c4];
        }
        // LDG B: 32 n x 64 k bf16 hi/lo
        uint2 bh[2], bl[2];
#pragma unroll
        for (int i = 0; i < 2; i++) {
            int j = i * 256 + tid;
            int n = j >> 4, cc = j & 15;
            bh[i] = *(const uint2*)&fhi[n * F3 + k0 + cc * 4];
            bl[i] = *(const uint2*)&flo[n * F3 + k0 + cc * 4];
        }
        __syncthreads();   // previous chunk's compute done before overwrite
        // convert + STS A
#pragma unroll
        for (int i = 0; i < 8; i++) {
            int idx = i * 256 + tid;
            int row = idx >> 4, c4 = idx & 15;
            uint2 h, l;
            h.x = pkbf(av[i].x, av[i].y);
            h.y = pkbf(av[i].z, av[i].w);
            l.x = pkbf(bfres(av[i].x), bfres(av[i].y));
            l.y = pkbf(bfres(av[i].z), bfres(av[i].w));
            *(uint2*)&sAhi[row * LDK + c4 * 4] = h;
            *(uint2*)&sAlo[row * LDK + c4 * 4] = l;
        }
        // STS B
#pragma unroll
        for (int i = 0; i < 2; i++) {
            int j = i * 256 + tid;
            int n = j >> 4, cc = j & 15;
            *(uint2*)&sBhi[n * LDK + cc * 4] = bh[i];
            *(uint2*)&sBlo[n * LDK + cc * 4] = bl[i];
        }
        __syncthreads();
        // compute: 4 k16 steps
#pragma unroll
        for (int ks = 0; ks < 4; ks++) {
            int kk = ks * 16 + q * 2;
            int ar = w * 16 + g;
            u32 ah[4], al[4];
            ah[0] = *(const u32*)&sAhi[ar * LDK + kk];
            ah[1] = *(const u32*)&sAhi[(ar + 8) * LDK + kk];
            ah[2] = *(const u32*)&sAhi[ar * LDK + kk + 8];
            ah[3] = *(const u32*)&sAhi[(ar + 8) * LDK + kk + 8];
            al[0] = *(const u32*)&sAlo[ar * LDK + kk];
            al[1] = *(const u32*)&sAlo[(ar + 8) * LDK + kk];
            al[2] = *(const u32*)&sAlo[ar * LDK + kk + 8];
            al[3] = *(const u32*)&sAlo[(ar + 8) * LDK + kk + 8];
#pragma unroll
            for (int nb = 0; nb < 4; nb++) {
                int bn = nb * 8 + g;
                u32 bh0 = *(const u32*)&sBhi[bn * LDK + kk];
                u32 bh1 = *(const u32*)&sBhi[bn * LDK + kk + 8];
                u32 bl0 = *(const u32*)&sBlo[bn * LDK + kk];
                u32 bl1 = *(const u32*)&sBlo[bn * LDK + kk + 8];
                mma16816(d[nb], ah, bh0, bh1);
                mma16816(d[nb], al, bh0, bh1);
                mma16816(d[nb], ah, bl0, bl1);
            }
        }
    }
    // epilogue
    int vlo = r0 + w * 16 + g;
    int vhi = vlo + 8;
    float blo = (vlo < VOUT) ? wg_b[vlo] : 0.f;
    float bhi_ = (vhi < VOUT) ? wg_b[vhi] : 0.f;
#pragma unroll
    for (int nb = 0; nb < 4; nb++) {
        int col = nb * 8 + q * 2;
        if (vlo < VOUT) {
            float2 o = { d[nb][0] + blo, d[nb][1] + blo };
            *(float2*)&g_wgout[(size_t)vlo * 32 + col] = o;
        }
        if (vhi < VOUT) {
            float2 o = { d[nb][2] + bhi_, d[nb][3] + bhi_ };
            *(float2*)&g_wgout[(size_t)vhi * 32 + col] = o;
        }
    }
}

// ---------------- K11a/b: log-sum-exp over VOUT ----------------
__global__ void k11a_lse() {
    __shared__ float pm[8][32];
    __shared__ float ps[8][32];
    int w = threadIdx.x >> 5, lane = threadIdx.x & 31;
    int base = blockIdx.x * 1024 + w * 128;
    float m = -INFINITY, s = 0.f;
    for (int i = 0; i < 128; i++) {
        int v = base + i;
        if (v < VOUT) {
            float x = g_wgout[(size_t)v * B + lane];
            if (x > m) { s = s * expf(m - x) + 1.f; m = x; }
            else       { s += expf(x - m); }
        }
    }
    pm[w][lane] = m; ps[w][lane] = s;
    __syncthreads();
    if (w == 0) {
        float M = pm[0][lane], S = ps[0][lane];
#pragma unroll
        for (int i = 1; i < 8; i++) {
            float m2 = pm[i][lane], s2 = ps[i][lane];
            float nm = fmaxf(M, m2);
            S = S * expf(M - nm) + s2 * expf(m2 - nm);
            M = nm;
        }
        g_pmax[blockIdx.x * 32 + lane] = M;
        g_psum[blockIdx.x * 32 + lane] = S;
    }
}

__global__ void k11b_lse() {
    int b = threadIdx.x;
    float M = g_pmax[b], S = g_psum[b];
    for (int i = 1; i < NCHUNK; i++) {
        float m2 = g_pmax[i * 32 + b], s2 = g_psum[i * 32 + b];
        float nm = fmaxf(M, m2);
        S = S * expf(M - nm) + s2 * expf(m2 - nm);
        M = nm;
    }
    g_wlse[b] = M + logf(S);
}

// ---------------- K12: transpose + final vocab logits ----------------
__global__ void k12_out(float* __restrict__ d_out) {
    __shared__ float sm[32][33];
    int tx = threadIdx.x & 31, ty = threadIdx.x >> 5;
    int v0 = blockIdx.x * 32;
#pragma unroll
    for (int r = 0; r < 4; r++) {
        int row = r * 8 + ty;
        int v = v0 + row;
        if (v > VOUT - 1) v = VOUT - 1;
        sm[row][tx] = g_wgout[(size_t)v * B + tx];
    }
    __syncthreads();
#pragma unroll
    for (int r = 0; r < 4; r++) {
        int b = r * 8 + ty;
        int v = v0 + tx;
        if (v < VOUT)
            d_out[(size_t)b * LOGN + v] = g_sB[b] + sm[tx][b] - g_wlse[b];
    }
}

// ---------------- launch ----------------
extern "C" void kernel_launch(void* const* d_in, const int* in_sizes, int n_in,
                              void* d_out, int out_size) {
    const int*   n_input  = (const int*)d_in[0];
    const int*   t_input  = (const int*)d_in[1];
    const float* h0       = (const float*)d_in[2];
    const float* c0       = (const float*)d_in[3];
    const float* enc_out  = (const float*)d_in[4];
    const unsigned char* mask = (const unsigned char*)d_in[5];
    const float* h_parent = (const float*)d_in[6];
    const float* embN     = (const float*)d_in[7];
    const float* embT     = (const float*)d_in[8];
    const float* W_ih     = (const float*)d_in[9];
    const float* W_hh     = (const float*)d_in[10];
    const float* b_ih     = (const float*)d_in[11];
    const float* b_hh     = (const float*)d_in[12];
    const float* Wh_w     = (const float*)d_in[13];
    const float* Wh_b     = (const float*)d_in[14];
    const float* Wm_w     = (const float*)d_in[15];
    const float* Wm_b     = (const float*)d_in[16];
    const float* v_w      = (const float*)d_in[17];
    const float* v_b      = (const float*)d_in[18];
    const float* wg_w     = (const float*)d_in[19];
    const float* wg_b     = (const float*)d_in[20];
    const float* ws_w     = (const float*)d_in[21];
    const float* ws_b     = (const float*)d_in[22];
    float* out = (float*)d_out;

    float* gatesP; cudaGetSymbolAddress((void**)&gatesP, g_gates);
    float* qTP;    cudaGetSymbolAddress((void**)&qTP, g_qT);
    float* xhTP;   cudaGetSymbolAddress((void**)&xhTP, g_xhT);
    float* featTP; cudaGetSymbolAddress((void**)&featTP, g_featT);
    __nv_bfloat16* fhiP; cudaGetSymbolAddress((void**)&fhiP, g_fhi);
    __nv_bfloat16* floP; cudaGetSymbolAddress((void**)&floP, g_flo);

    k1_prep<<<B, 256>>>(n_input, t_input, h0, h_parent, embN, embT, v_b, b_ih, b_hh, Wh_b);
    gemm2<4, false, true><<<dim3(G4 / 64, 2), 128>>>(W_ih, EIN, EIN / 16, W_hh, H,
                                                     xhTP, (const float*)nullptr, gatesP, G4, 56);
    k3_lstm<<<(B * H) / 256, 256>>>(c0, out);
    gemm2<4, false, true><<<dim3(H / 64, 4), 128>>>(Wh_w, H, H / 16, (const float*)nullptr, 0,
                                                    featTP + H * B, (const float*)nullptr, qTP, H, 16);
    k5_score<<<dim3(H / 64, B), 256>>>(enc_out, Wm_w, Wm_b, v_w);
    k7_ctx<<<B, 256>>>(enc_out, mask);
    k8_s<<<B, 256>>>(ws_w, ws_b, out);
    k9_split<<<dim3(F3 / 256, B), 256>>>(fhiP, floP);
    k10_mma<<<(VOUT + 127) / 128, 256>>>(wg_w, wg_b, fhiP, floP);
    k11a_lse<<<NCHUNK, 256>>>();
    k11b_lse<<<1, 32>>>();
    k12_out<<<(VOUT + 31) / 32, 256>>>(out);
}

// round 8
// speedup vs baseline: 2.3378x; 1.2709x over previous
#include <cuda_runtime.h>
#include <cuda_bf16.h>
#include <math.h>

typedef unsigned long long ull;
typedef unsigned int u32;

#define DI __device__ __forceinline__

DI ull pk2(float x, float y){ ull r; asm("mov.b64 %0,{%1,%2};" : "=l"(r) : "f"(x), "f"(y)); return r; }
DI void upk2(ull v, float& x, float& y){ asm("mov.b64 {%0,%1},%2;" : "=f"(x), "=f"(y) : "l"(v)); }
DI ull ffma2(ull a, ull b, ull c){ ull d; asm("fma.rn.f32x2 %0,%1,%2,%3;" : "=l"(d) : "l"(a), "l"(b), "l"(c)); return d; }
DI u32 pkbf(float a, float b){ u32 r; asm("cvt.rn.bf16x2.f32 %0, %1, %2;" : "=r"(r) : "f"(b), "f"(a)); return r; }  // mem order [a,b]
DI float bfres(float v){ __nv_bfloat16 h = __float2bfloat16(v); return v - __bfloat162float(h); }

// warp mma: D[16x8] += A[16x16,row] * B[16x8,col], bf16 in, fp32 accum
DI void mma16816(float* d, const u32* a, u32 b0, u32 b1){
    asm volatile("mma.sync.aligned.m16n8k16.row.col.f32.bf16.bf16.f32 "
        "{%0,%1,%2,%3},{%4,%5,%6,%7},{%8,%9},{%0,%1,%2,%3};"
        : "+f"(d[0]), "+f"(d[1]), "+f"(d[2]), "+f"(d[3])
        : "r"(a[0]), "r"(a[1]), "r"(a[2]), "r"(a[3]), "r"(b0), "r"(b1));
}

static constexpr int B    = 32;
static constexpr int L    = 128;
static constexpr int H    = 1024;
static constexpr int EN   = 256;
static constexpr int ET   = 512;
static constexpr int EIN  = 768;
static constexpr int G4   = 4096;
static constexpr int VOUT = 50003;
static constexpr int LOGN = VOUT + L;
static constexpr int F3   = 3072;
static constexpr int NLOG = B * LOGN;
static constexpr int NCHUNK = 49;

// ---------------- scratch ----------------
__device__ __align__(16) float g_xhT[(EIN + H) * B];
__device__ __align__(16) float g_featT[F3 * B];
__device__ __align__(16) float g_gates[G4 * B];
__device__ __align__(16) float g_qT[H * B];
__device__ __align__(16) float g_scores[B * L];
__device__ float g_lse[B];
__device__ __align__(16) float g_context[B * H];
__device__ float g_sB[B];
__device__ float g_l1m[B];
__device__ __align__(16) float g_wgout[(VOUT + 64) * B];
__device__ float g_pmax[NCHUNK * 32];
__device__ float g_psum[NCHUNK * 32];
__device__ float g_wlse[B];
__device__ __align__(16) __nv_bfloat16 g_fhi[B * F3];
__device__ __align__(16) __nv_bfloat16 g_flo[B * F3];
__device__ __align__(16) __nv_bfloat16 g_ehi[B * L * H];
__device__ __align__(16) __nv_bfloat16 g_elo[B * L * H];
__device__ __align__(16) __nv_bfloat16 g_wmhi[H * H];
__device__ __align__(16) __nv_bfloat16 g_wmlo[H * H];

// ---------------- K0: generic fp32 -> bf16 hi/lo split ----------------
__global__ void k0_split(const float* __restrict__ src, __nv_bfloat16* __restrict__ hi,
                         __nv_bfloat16* __restrict__ lo) {
    int i = blockIdx.x * 256 + threadIdx.x;
    float v = src[i];
    __nv_bfloat16 h = __float2bfloat16(v);
    hi[i] = h;
    lo[i] = __float2bfloat16(v - __bfloat162float(h));
}

// ---------------- K1: embeddings + staging + bias inits ----------------
__global__ void k1_prep(const int* __restrict__ n_in, const int* __restrict__ t_in,
                        const float* __restrict__ h0, const float* __restrict__ h_parent,
                        const float* __restrict__ embN, const float* __restrict__ embT,
                        const float* __restrict__ v_b,
                        const float* __restrict__ b_ih, const float* __restrict__ b_hh,
                        const float* __restrict__ Wh_b) {
    int b = blockIdx.x;
    int t = threadIdx.x;
    int n  = n_in[b];
    int tt = t_in[b];
    for (int k = t; k < EIN; k += blockDim.x) {
        float v = (k < EN) ? embN[n * EN + k] : embT[(size_t)tt * ET + (k - EN)];
        g_xhT[k * B + b] = v;
    }
    for (int k = t; k < H; k += blockDim.x) {
        g_xhT[(EIN + k) * B + b]     = h0[b * H + k];
        g_featT[(2 * H + k) * B + b] = h_parent[b * H + k];
        g_qT[k * B + b]              = Wh_b[k];
    }
    for (int j = t; j < G4; j += blockDim.x)
        g_gates[j * B + b] = b_ih[j] + b_hh[j];
    if (t < L) g_scores[b * L + t] = v_b[0];
}

// ---------------- FFMA2 GEMM core (gates/q) ----------------
template<int RT, bool CLAMP, bool ATOMIC>
__global__ void __launch_bounds__(128) gemm2(const float* __restrict__ A1, int ldA1, int kb1,
                                             const float* __restrict__ A2, int ldA2,
                                             const float* __restrict__ Bmat,
                                             const float* __restrict__ bias,
                                             float* __restrict__ out, int rows,
                                             int tilesPerChunk) {
    constexpr int BM   = 16 * RT;
    constexpr int LDAS = BM + 2;
    constexpr int LDBS = 66;
    constexpr int NA4  = BM / 32;
    constexpr int RP   = RT / 2;
    __shared__ __align__(16) float As[2][16 * LDAS];
    __shared__ __align__(16) float Bs[2][16 * LDBS];
    int tid = threadIdx.x;
    int r0  = blockIdx.x * BM;
    int t0  = blockIdx.y * tilesPerChunk;
    int nkt = tilesPerChunk;
    int rg = tid >> 3, cg = tid & 7;
    int rbase = rg * RT;
    int b0 = cg * 4;
    int cpos0 = 2 * b0 + 2 * (b0 >> 4);
    int kkB = tid >> 3;

    ull acc[RP][4];
    ull z = pk2(0.f, 0.f);
#pragma unroll
    for (int p = 0; p < RP; p++)
#pragma unroll
        for (int c = 0; c < 4; c++) acc[p][c] = z;

    float4 rA[2][NA4];
    float4 rB[2];

    auto ld = [&](int t, int buf) {
        const float* A; int ld_; int kt;
        if (t < kb1) { A = A1; ld_ = ldA1; kt = t; }
        else         { A = A2; ld_ = ldA2; kt = t - kb1; }
        int k0 = kt * 16;
#pragma unroll
        for (int i = 0; i < NA4; i++) {
            int idx = i * 128 + tid;
            int row = idx >> 2, c4 = idx & 3;
            int rr = r0 + row;
            if (CLAMP && rr > rows - 1) rr = rows - 1;
            rA[buf][i] = *(const float4*)&A[(size_t)rr * ld_ + k0 + 4 * c4];
        }
        rB[buf] = *(const float4*)&Bmat[(size_t)(t * 16 + kkB) * 32 + b0];
    };
    auto st = [&](int s) {
        float* AD = As[s];
#pragma unroll
        for (int i = 0; i < NA4; i++) {
            int idx = i * 128 + tid;
            int row = idx >> 2, c4 = idx & 3;
            AD[(4 * c4 + 0) * LDAS + row] = rA[s][i].x;
            AD[(4 * c4 + 1) * LDAS + row] = rA[s][i].y;
            AD[(4 * c4 + 2) * LDAS + row] = rA[s][i].z;
            AD[(4 * c4 + 3) * LDAS + row] = rA[s][i].w;
        }
        float* BD = &Bs[s][kkB * LDBS + cpos0];
        *(ull*)&BD[0] = pk2(rB[s].x, rB[s].x);
        *(ull*)&BD[2] = pk2(rB[s].y, rB[s].y);
        *(ull*)&BD[4] = pk2(rB[s].z, rB[s].z);
        *(ull*)&BD[6] = pk2(rB[s].w, rB[s].w);
    };
    auto comp = [&](int s) {
        const float* AD = As[s];
        const float* BD = Bs[s];
#pragma unroll
        for (int k = 0; k < 16; k++) {
            ull b2[4];
#pragma unroll
            for (int c = 0; c < 4; c++)
                b2[c] = *(const ull*)&BD[k * LDBS + cpos0 + 2 * c];
#pragma unroll
            for (int p = 0; p < RP; p++) {
                ull a2 = *(const ull*)&AD[k * LDAS + rbase + 2 * p];
#pragma unroll
                for (int c = 0; c < 4; c++)
                    acc[p][c] = ffma2(a2, b2[c], acc[p][c]);
            }
        }
    };

    ld(t0, 0);
    ld(t0 + 1, 1);
    st(0);
    __syncthreads();
    for (int tt = 0; tt < nkt; tt++) {
        if (tt + 1 < nkt) st((tt + 1) & 1);
        if (tt + 2 < nkt) ld(t0 + tt + 2, tt & 1);
        comp(tt & 1);
        __syncthreads();
    }

#pragma unroll
    for (int p = 0; p < RP; p++) {
        int ra = r0 + rbase + 2 * p;
        float4 lo, hi;
        upk2(acc[p][0], lo.x, hi.x);
        upk2(acc[p][1], lo.y, hi.y);
        upk2(acc[p][2], lo.z, hi.z);
        upk2(acc[p][3], lo.w, hi.w);
        if (ATOMIC) {
            atomicAdd(&out[(size_t)ra * 32 + b0 + 0], lo.x);
            atomicAdd(&out[(size_t)ra * 32 + b0 + 1], lo.y);
            atomicAdd(&out[(size_t)ra * 32 + b0 + 2], lo.z);
            atomicAdd(&out[(size_t)ra * 32 + b0 + 3], lo.w);
            atomicAdd(&out[(size_t)(ra + 1) * 32 + b0 + 0], hi.x);
            atomicAdd(&out[(size_t)(ra + 1) * 32 + b0 + 1], hi.y);
            atomicAdd(&out[(size_t)(ra + 1) * 32 + b0 + 2], hi.z);
            atomicAdd(&out[(size_t)(ra + 1) * 32 + b0 + 3], hi.w);
        } else {
            if (!CLAMP || ra < rows) {
                float bb = bias[ra];
                lo.x += bb; lo.y += bb; lo.z += bb; lo.w += bb;
                *(float4*)&out[(size_t)ra * 32 + b0] = lo;
            }
            if (!CLAMP || ra + 1 < rows) {
                float bb = bias[ra + 1];
                hi.x += bb; hi.y += bb; hi.z += bb; hi.w += bb;
                *(float4*)&out[(size_t)(ra + 1) * 32 + b0] = hi;
            }
        }
    }
}

// ---------------- K3: LSTM pointwise ----------------
__global__ void k3_lstm(const float* __restrict__ c0, float* __restrict__ d_out) {
    int idx = blockIdx.x * blockDim.x + threadIdx.x;
    int b = idx & 31, j = idx >> 5;
    float gi = g_gates[j * B + b];
    float gf = g_gates[(H + j) * B + b];
    float gg = g_gates[(2 * H + j) * B + b];
    float go = g_gates[(3 * H + j) * B + b];
    float cp = c0[b * H + j];
    float si = 1.f / (1.f + expf(-gi));
    float sf = 1.f / (1.f + expf(-gf));
    float so = 1.f / (1.f + expf(-go));
    float cn = sf * cp + si * tanhf(gg);
    float hn = so * tanhf(cn);
    g_featT[(H + j) * B + b] = hn;
    d_out[NLOG + b * H + j] = hn;
    d_out[NLOG + B * H + b * H + j] = cn;
}

// ---------------- K5: attention GEMM via mma.sync bf16 3-pass + fused v*tanh ----------------
// CTA = (n-block of 64, batch). A = enc[b] (128 x H), B = Wm rows n0..n0+63.
// K in 32 chunks of 32. smem LDK=40 halves (conflict-free fragment LDS).
static constexpr int K5KC  = 32;
static constexpr int K5LDK = 40;

__global__ void __launch_bounds__(256) k5_mma(const __nv_bfloat16* __restrict__ ehi,
                                              const __nv_bfloat16* __restrict__ elo,
                                              const __nv_bfloat16* __restrict__ wmhi,
                                              const __nv_bfloat16* __restrict__ wmlo,
                                              const float* __restrict__ Wm_b,
                                              const float* __restrict__ v_w) {
    __shared__ __align__(16) __nv_bfloat16 sAhi[128 * K5LDK];
    __shared__ __align__(16) __nv_bfloat16 sAlo[128 * K5LDK];
    __shared__ __align__(16) __nv_bfloat16 sBhi[64 * K5LDK];
    __shared__ __align__(16) __nv_bfloat16 sBlo[64 * K5LDK];
    __shared__ float red[128];
    int tid = threadIdx.x, w = tid >> 5, lane = tid & 31;
    int g = lane >> 2, q = lane & 3;
    int n0 = blockIdx.x * 64;
    int by = blockIdx.y;
    const __nv_bfloat16* Ah = ehi + (size_t)by * L * H;
    const __nv_bfloat16* Al = elo + (size_t)by * L * H;

    float d[8][4];
#pragma unroll
    for (int nb = 0; nb < 8; nb++)
#pragma unroll
        for (int c = 0; c < 4; c++) d[nb][c] = 0.f;

    for (int ch = 0; ch < H / K5KC; ch++) {
        int k0 = ch * K5KC;
        // LDG A: 128 rows x 32 halves; per thread 2 x uint4 (8 halves each), hi+lo
        uint4 avh[2], avl[2];
#pragma unroll
        for (int i = 0; i < 2; i++) {
            int idx = i * 256 + tid;
            int row = idx >> 2, c8 = (idx & 3) * 8;
            avh[i] = *(const uint4*)&Ah[row * H + k0 + c8];
            avl[i] = *(const uint4*)&Al[row * H + k0 + c8];
        }
        // LDG B: 64 rows x 32 halves; per thread 1 x uint4, hi+lo
        int brow = tid >> 2, bc8 = (tid & 3) * 8;
        uint4 bvh = *(const uint4*)&wmhi[(size_t)(n0 + brow) * H + k0 + bc8];
        uint4 bvl = *(const uint4*)&wmlo[(size_t)(n0 + brow) * H + k0 + bc8];
        __syncthreads();   // previous chunk compute done
#pragma unroll
        for (int i = 0; i < 2; i++) {
            int idx = i * 256 + tid;
            int row = idx >> 2, c8 = (idx & 3) * 8;
            *(uint4*)&sAhi[row * K5LDK + c8] = avh[i];
            *(uint4*)&sAlo[row * K5LDK + c8] = avl[i];
        }
        *(uint4*)&sBhi[brow * K5LDK + bc8] = bvh;
        *(uint4*)&sBlo[brow * K5LDK + bc8] = bvl;
        __syncthreads();
#pragma unroll
        for (int ks = 0; ks < 2; ks++) {
            int kk = ks * 16 + q * 2;
            int ar = w * 16 + g;
            u32 ah[4], al[4];
            ah[0] = *(const u32*)&sAhi[ar * K5LDK + kk];
            ah[1] = *(const u32*)&sAhi[(ar + 8) * K5LDK + kk];
            ah[2] = *(const u32*)&sAhi[ar * K5LDK + kk + 8];
            ah[3] = *(const u32*)&sAhi[(ar + 8) * K5LDK + kk + 8];
            al[0] = *(const u32*)&sAlo[ar * K5LDK + kk];
            al[1] = *(const u32*)&sAlo[(ar + 8) * K5LDK + kk];
            al[2] = *(const u32*)&sAlo[ar * K5LDK + kk + 8];
            al[3] = *(const u32*)&sAlo[(ar + 8) * K5LDK + kk + 8];
#pragma unroll
            for (int nb = 0; nb < 8; nb++) {
                int bn = nb * 8 + g;
                u32 bh0 = *(const u32*)&sBhi[bn * K5LDK + kk];
                u32 bh1 = *(const u32*)&sBhi[bn * K5LDK + kk + 8];
                u32 bl0 = *(const u32*)&sBlo[bn * K5LDK + kk];
                u32 bl1 = *(const u32*)&sBlo[bn * K5LDK + kk + 8];
                mma16816(d[nb], ah, bh0, bh1);
                mma16816(d[nb], al, bh0, bh1);
                mma16816(d[nb], ah, bl0, bl1);
            }
        }
    }

    // epilogue: p = v[n]*tanh(acc + q[b][n] + Wm_b[n]); reduce over n
    float plo = 0.f, phi = 0.f;
#pragma unroll
    for (int nb = 0; nb < 8; nb++) {
        int col0 = n0 + nb * 8 + q * 2;
        int col1 = col0 + 1;
        float vw0 = v_w[col0], vw1 = v_w[col1];
        float mb0 = Wm_b[col0], mb1 = Wm_b[col1];
        float q0 = g_qT[col0 * B + by];
        float q1 = g_qT[col1 * B + by];
        plo += vw0 * tanhf(d[nb][0] + mb0 + q0) + vw1 * tanhf(d[nb][1] + mb1 + q1);
        phi += vw0 * tanhf(d[nb][2] + mb0 + q0) + vw1 * tanhf(d[nb][3] + mb1 + q1);
    }
    plo += __shfl_xor_sync(~0u, plo, 1);
    plo += __shfl_xor_sync(~0u, plo, 2);
    phi += __shfl_xor_sync(~0u, phi, 1);
    phi += __shfl_xor_sync(~0u, phi, 2);
    if (q == 0) {
        red[w * 16 + g] = plo;
        red[w * 16 + g + 8] = phi;
    }
    __syncthreads();
    if (tid < 128) atomicAdd(&g_scores[by * L + tid], red[tid]);
}

// ---------------- K7: softmax over L + context ----------------
__global__ void k7_ctx(const float* __restrict__ enc, const unsigned char* __restrict__ mask) {
    __shared__ float sc[128];
    __shared__ float redm[16];
    int b = blockIdx.x, t = threadIdx.x;
    if (t < 128) {
        float s = g_scores[b * L + t];
        if (mask[b * L + t]) s = -1e20f;
        sc[t] = s;
        g_scores[b * L + t] = s;
    }
    __syncthreads();
    float m = (t < 128) ? sc[t] : -INFINITY;
#pragma unroll
    for (int o = 16; o > 0; o >>= 1) m = fmaxf(m, __shfl_xor_sync(~0u, m, o));
    if ((t & 31) == 0) redm[t >> 5] = m;
    __syncthreads();
    if (t == 0) {
        float mm = redm[0];
        for (int w = 1; w < 8; w++) mm = fmaxf(mm, redm[w]);
        redm[0] = mm;
    }
    __syncthreads();
    float mx = redm[0];
    float e = (t < 128) ? expf(sc[t] - mx) : 0.f;
    float s = e;
#pragma unroll
    for (int o = 16; o > 0; o >>= 1) s += __shfl_xor_sync(~0u, s, o);
    if ((t & 31) == 0) redm[8 + (t >> 5)] = s;
    __syncthreads();
    if (t == 0) {
        float ss = 0.f;
        for (int w = 0; w < 8; w++) ss += redm[8 + w];
        redm[8] = ss;
    }
    __syncthreads();
    float sum = redm[8];
    if (t < 128) sc[t] = e / sum;
    if (t == 0) g_lse[b] = mx + logf(sum);
    __syncthreads();
    const float* E = enc + (size_t)b * L * H;
#pragma unroll
    for (int jj = 0; jj < 4; jj++) {
        int j = t + jj * 256;
        float a = 0.f;
#pragma unroll 4
        for (int l = 0; l < 128; l++) a += sc[l] * E[l * H + j];
        g_context[b * H + j] = a;
        g_featT[j * B + b] = a;
    }
}

// ---------------- K8: pointer switch + copy-logits ----------------
__global__ void k8_s(const float* __restrict__ ws_w, const float* __restrict__ ws_b,
                     float* __restrict__ d_out) {
    __shared__ float red[8];
    __shared__ float sh[2];
    int b = blockIdx.x, t = threadIdx.x;
    float a = 0.f;
    for (int j = t; j < H; j += 256) a += g_context[b * H + j] * ws_w[j];
    for (int j = t; j < H; j += 256) a += g_featT[(H + j) * B + b] * ws_w[H + j];
#pragma unroll
    for (int o = 16; o > 0; o >>= 1) a += __shfl_xor_sync(~0u, a, o);
    if ((t & 31) == 0) red[t >> 5] = a;
    __syncthreads();
    if (t == 0) {
        float zz = ws_b[0];
        for (int w = 0; w < 8; w++) zz += red[w];
        float s  = (zz >= 0.f) ? -log1pf(expf(-zz)) : zz - log1pf(expf(zz));
        float zm = -zz;
        float l1 = (zm >= 0.f) ? -log1pf(expf(-zm)) : zm - log1pf(expf(zm));
        l1 = fmaxf(l1, -41.446531673892822f);
        g_sB[b] = s;
        g_l1m[b] = l1;
        sh[0] = l1;
        sh[1] = g_lse[b];
    }
    __syncthreads();
    if (t < 128)
        d_out[(size_t)b * LOGN + VOUT + t] = sh[0] + g_scores[b * L + t] - sh[1];
}

// ---------------- K9: split features into bf16 hi/lo, [b][k] layout ----------------
__global__ void k9_split(__nv_bfloat16* __restrict__ fhi, __nv_bfloat16* __restrict__ flo) {
    int b = blockIdx.y;
    int k = blockIdx.x * 256 + threadIdx.x;
    float v = g_featT[k * B + b];
    __nv_bfloat16 h = __float2bfloat16(v);
    fhi[b * F3 + k] = h;
    flo[b * F3 + k] = __float2bfloat16(v - __bfloat162float(h));
}

// ---------------- K10: vocab GEMM via mma.sync bf16 3-pass split ----------------
static constexpr int KC   = 64;
static constexpr int NCHP = F3 / KC;   // 48
static constexpr int LDK  = 72;

__global__ void __launch_bounds__(256) k10_mma(const float* __restrict__ wg_w,
                                               const float* __restrict__ wg_b,
                                               const __nv_bfloat16* __restrict__ fhi,
                                               const __nv_bfloat16* __restrict__ flo) {
    __shared__ __align__(16) __nv_bfloat16 sAhi[128 * LDK];
    __shared__ __align__(16) __nv_bfloat16 sAlo[128 * LDK];
    __shared__ __align__(16) __nv_bfloat16 sBhi[32 * LDK];
    __shared__ __align__(16) __nv_bfloat16 sBlo[32 * LDK];
    int tid = threadIdx.x, w = tid >> 5, lane = tid & 31;
    int r0 = blockIdx.x * 128;
    int g = lane >> 2, q = lane & 3;

    float d[4][4];
#pragma unroll
    for (int nb = 0; nb < 4; nb++)
#pragma unroll
        for (int c = 0; c < 4; c++) d[nb][c] = 0.f;

    for (int ch = 0; ch < NCHP; ch++) {
        int k0 = ch * KC;
        float4 av[8];
#pragma unroll
        for (int i = 0; i < 8; i++) {
            int idx = i * 256 + tid;
            int row = idx >> 4, c4 = idx & 15;
            int rr = r0 + row;
            if (rr > VOUT - 1) rr = VOUT - 1;
            av[i] = *(const float4*)&wg_w[(size_t)rr * F3 + k0 + 4 * c4];
        }
        uint2 bh[2], bl[2];
#pragma unroll
        for (int i = 0; i < 2; i++) {
            int j = i * 256 + tid;
            int n = j >> 4, cc = j & 15;
            bh[i] = *(const uint2*)&fhi[n * F3 + k0 + cc * 4];
            bl[i] = *(const uint2*)&flo[n * F3 + k0 + cc * 4];
        }
        __syncthreads();
#pragma unroll
        for (int i = 0; i < 8; i++) {
            int idx = i * 256 + tid;
            int row = idx >> 4, c4 = idx & 15;
            uint2 h, l;
            h.x = pkbf(av[i].x, av[i].y);
            h.y = pkbf(av[i].z, av[i].w);
            l.x = pkbf(bfres(av[i].x), bfres(av[i].y));
            l.y = pkbf(bfres(av[i].z), bfres(av[i].w));
            *(uint2*)&sAhi[row * LDK + c4 * 4] = h;
            *(uint2*)&sAlo[row * LDK + c4 * 4] = l;
        }
#pragma unroll
        for (int i = 0; i < 2; i++) {
            int j = i * 256 + tid;
            int n = j >> 4, cc = j & 15;
            *(uint2*)&sBhi[n * LDK + cc * 4] = bh[i];
            *(uint2*)&sBlo[n * LDK + cc * 4] = bl[i];
        }
        __syncthreads();
#pragma unroll
        for (int ks = 0; ks < 4; ks++) {
            int kk = ks * 16 + q * 2;
            int ar = w * 16 + g;
            u32 ah[4], al[4];
            ah[0] = *(const u32*)&sAhi[ar * LDK + kk];
            ah[1] = *(const u32*)&sAhi[(ar + 8) * LDK + kk];
            ah[2] = *(const u32*)&sAhi[ar * LDK + kk + 8];
            ah[3] = *(const u32*)&sAhi[(ar + 8) * LDK + kk + 8];
            al[0] = *(const u32*)&sAlo[ar * LDK + kk];
            al[1] = *(const u32*)&sAlo[(ar + 8) * LDK + kk];
            al[2] = *(const u32*)&sAlo[ar * LDK + kk + 8];
            al[3] = *(const u32*)&sAlo[(ar + 8) * LDK + kk + 8];
#pragma unroll
            for (int nb = 0; nb < 4; nb++) {
                int bn = nb * 8 + g;
                u32 bh0 = *(const u32*)&sBhi[bn * LDK + kk];
                u32 bh1 = *(const u32*)&sBhi[bn * LDK + kk + 8];
                u32 bl0 = *(const u32*)&sBlo[bn * LDK + kk];
                u32 bl1 = *(const u32*)&sBlo[bn * LDK + kk + 8];
                mma16816(d[nb], ah, bh0, bh1);
                mma16816(d[nb], al, bh0, bh1);
                mma16816(d[nb], ah, bl0, bl1);
            }
        }
    }
    int vlo = r0 + w * 16 + g;
    int vhi = vlo + 8;
    float blo = (vlo < VOUT) ? wg_b[vlo] : 0.f;
    float bhi_ = (vhi < VOUT) ? wg_b[vhi] : 0.f;
#pragma unroll
    for (int nb = 0; nb < 4; nb++) {
        int col = nb * 8 + q * 2;
        if (vlo < VOUT) {
            float2 o = { d[nb][0] + blo, d[nb][1] + blo };
            *(float2*)&g_wgout[(size_t)vlo * 32 + col] = o;
        }
        if (vhi < VOUT) {
            float2 o = { d[nb][2] + bhi_, d[nb][3] + bhi_ };
            *(float2*)&g_wgout[(size_t)vhi * 32 + col] = o;
        }
    }
}

// ---------------- K11a/b: log-sum-exp over VOUT ----------------
__global__ void k11a_lse() {
    __shared__ float pm[8][32];
    __shared__ float ps[8][32];
    int w = threadIdx.x >> 5, lane = threadIdx.x & 31;
    int base = blockIdx.x * 1024 + w * 128;
    float m = -INFINITY, s = 0.f;
    for (int i = 0; i < 128; i++) {
        int v = base + i;
        if (v < VOUT) {
            float x = g_wgout[(size_t)v * B + lane];
            if (x > m) { s = s * expf(m - x) + 1.f; m = x; }
            else       { s += expf(x - m); }
        }
    }
    pm[w][lane] = m; ps[w][lane] = s;
    __syncthreads();
    if (w == 0) {
        float M = pm[0][lane], S = ps[0][lane];
#pragma unroll
        for (int i = 1; i < 8; i++) {
            float m2 = pm[i][lane], s2 = ps[i][lane];
            float nm = fmaxf(M, m2);
            S = S * expf(M - nm) + s2 * expf(m2 - nm);
            M = nm;
        }
        g_pmax[blockIdx.x * 32 + lane] = M;
        g_psum[blockIdx.x * 32 + lane] = S;
    }
}

__global__ void k11b_lse() {
    int b = threadIdx.x;
    float M = g_pmax[b], S = g_psum[b];
    for (int i = 1; i < NCHUNK; i++) {
        float m2 = g_pmax[i * 32 + b], s2 = g_psum[i * 32 + b];
        float nm = fmaxf(M, m2);
        S = S * expf(M - nm) + s2 * expf(m2 - nm);
        M = nm;
    }
    g_wlse[b] = M + logf(S);
}

// ---------------- K12: transpose + final vocab logits ----------------
__global__ void k12_out(float* __restrict__ d_out) {
    __shared__ float sm[32][33];
    int tx = threadIdx.x & 31, ty = threadIdx.x >> 5;
    int v0 = blockIdx.x * 32;
#pragma unroll
    for (int r = 0; r < 4; r++) {
        int row = r * 8 + ty;
        int v = v0 + row;
        if (v > VOUT - 1) v = VOUT - 1;
        sm[row][tx] = g_wgout[(size_t)v * B + tx];
    }
    __syncthreads();
#pragma unroll
    for (int r = 0; r < 4; r++) {
        int b = r * 8 + ty;
        int v = v0 + tx;
        if (v < VOUT)
            d_out[(size_t)b * LOGN + v] = g_sB[b] + sm[tx][b] - g_wlse[b];
    }
}

// ---------------- launch ----------------
extern "C" void kernel_launch(void* const* d_in, const int* in_sizes, int n_in,
                              void* d_out, int out_size) {
    const int*   n_input  = (const int*)d_in[0];
    const int*   t_input  = (const int*)d_in[1];
    const float* h0       = (const float*)d_in[2];
    const float* c0       = (const float*)d_in[3];
    const float* enc_out  = (const float*)d_in[4];
    const unsigned char* mask = (const unsigned char*)d_in[5];
    const float* h_parent = (const float*)d_in[6];
    const float* embN     = (const float*)d_in[7];
    const float* embT     = (const float*)d_in[8];
    const float* W_ih     = (const float*)d_in[9];
    const float* W_hh     = (const float*)d_in[10];
    const float* b_ih     = (const float*)d_in[11];
    const float* b_hh     = (const float*)d_in[12];
    const float* Wh_w     = (const float*)d_in[13];
    const float* Wh_b     = (const float*)d_in[14];
    const float* Wm_w     = (const float*)d_in[15];
    const float* Wm_b     = (const float*)d_in[16];
    const float* v_w      = (const float*)d_in[17];
    const float* v_b      = (const float*)d_in[18];
    const float* wg_w     = (const float*)d_in[19];
    const float* wg_b     = (const float*)d_in[20];
    const float* ws_w     = (const float*)d_in[21];
    const float* ws_b     = (const float*)d_in[22];
    float* out = (float*)d_out;

    float* gatesP; cudaGetSymbolAddress((void**)&gatesP, g_gates);
    float* qTP;    cudaGetSymbolAddress((void**)&qTP, g_qT);
    float* xhTP;   cudaGetSymbolAddress((void**)&xhTP, g_xhT);
    float* featTP; cudaGetSymbolAddress((void**)&featTP, g_featT);
    __nv_bfloat16* fhiP;  cudaGetSymbolAddress((void**)&fhiP, g_fhi);
    __nv_bfloat16* floP;  cudaGetSymbolAddress((void**)&floP, g_flo);
    __nv_bfloat16* ehiP;  cudaGetSymbolAddress((void**)&ehiP, g_ehi);
    __nv_bfloat16* eloP;  cudaGetSymbolAddress((void**)&eloP, g_elo);
    __nv_bfloat16* wmhiP; cudaGetSymbolAddress((void**)&wmhiP, g_wmhi);
    __nv_bfloat16* wmloP; cudaGetSymbolAddress((void**)&wmloP, g_wmlo);

    // input-only deps: split enc and Wm first (overlaps with LSTM chain)
    k0_split<<<(B * L * H) / 256, 256>>>(enc_out, ehiP, eloP);
    k0_split<<<(H * H) / 256, 256>>>(Wm_w, wmhiP, wmloP);
    k1_prep<<<B, 256>>>(n_input, t_input, h0, h_parent, embN, embT, v_b, b_ih, b_hh, Wh_b);
    gemm2<4, false, true><<<dim3(G4 / 64, 2), 128>>>(W_ih, EIN, EIN / 16, W_hh, H,
                                                     xhTP, (const float*)nullptr, gatesP, G4, 56);
    k3_lstm<<<(B * H) / 256, 256>>>(c0, out);
    gemm2<4, false, true><<<dim3(H / 64, 4), 128>>>(Wh_w, H, H / 16, (const float*)nullptr, 0,
                                                    featTP + H * B, (const float*)nullptr, qTP, H, 16);
    k5_mma<<<dim3(H / 64, B), 256>>>(ehiP, eloP, wmhiP, wmloP, Wm_b, v_w);
    k7_ctx<<<B, 256>>>(enc_out, mask);
    k8_s<<<B, 256>>>(ws_w, ws_b, out);
    k9_split<<<dim3(F3 / 256, B), 256>>>(fhiP, floP);
    k10_mma<<<(VOUT + 127) / 128, 256>>>(wg_w, wg_b, fhiP, floP);
    k11a_lse<<<NCHUNK, 256>>>();
    k11b_lse<<<1, 32>>>();
    k12_out<<<(VOUT + 31) / 32, 256>>>(out);
}

// round 9
// speedup vs baseline: 2.7999x; 1.1977x over previous
#include <cuda_runtime.h>
#include <cuda_bf16.h>
#include <math.h>

typedef unsigned long long ull;
typedef unsigned int u32;

#define DI __device__ __forceinline__

DI u32 pkbf(float a, float b){ u32 r; asm("cvt.rn.bf16x2.f32 %0, %1, %2;" : "=r"(r) : "f"(b), "f"(a)); return r; }  // mem order [a,b]
DI float bfres(float v){ __nv_bfloat16 h = __float2bfloat16(v); return v - __bfloat162float(h); }

// warp mma: D[16x8] += A[16x16,row] * B[16x8,col], bf16 in, fp32 accum
DI void mma16816(float* d, const u32* a, u32 b0, u32 b1){
    asm volatile("mma.sync.aligned.m16n8k16.row.col.f32.bf16.bf16.f32 "
        "{%0,%1,%2,%3},{%4,%5,%6,%7},{%8,%9},{%0,%1,%2,%3};"
        : "+f"(d[0]), "+f"(d[1]), "+f"(d[2]), "+f"(d[3])
        : "r"(a[0]), "r"(a[1]), "r"(a[2]), "r"(a[3]), "r"(b0), "r"(b1));
}

static constexpr int B    = 32;
static constexpr int L    = 128;
static constexpr int H    = 1024;
static constexpr int EN   = 256;
static constexpr int ET   = 512;
static constexpr int EIN  = 768;
static constexpr int EIN2 = 1792;   // EIN + H
static constexpr int G4   = 4096;
static constexpr int VOUT = 50003;
static constexpr int LOGN = VOUT + L;
static constexpr int F3   = 3072;
static constexpr int NLOG = B * LOGN;
static constexpr int NCHUNK = 49;

// ---------------- scratch ----------------
__device__ __align__(16) float g_featT[F3 * B];
__device__ __align__(16) float g_gates[G4 * B];
__device__ __align__(16) float g_qT[H * B];
__device__ __align__(16) float g_scores[B * L];
__device__ float g_lse[B];
__device__ __align__(16) float g_context[B * H];
__device__ float g_sB[B];
__device__ __align__(16) float g_wgout[(VOUT + 64) * B];
__device__ float g_pmax[NCHUNK * 32];
__device__ float g_psum[NCHUNK * 32];
__device__ float g_wlse[B];
__device__ __align__(16) __nv_bfloat16 g_fhi[B * F3];
__device__ __align__(16) __nv_bfloat16 g_flo[B * F3];
__device__ __align__(16) __nv_bfloat16 g_ehi[B * L * H];
__device__ __align__(16) __nv_bfloat16 g_elo[B * L * H];
__device__ __align__(16) __nv_bfloat16 g_wmhi[H * H];
__device__ __align__(16) __nv_bfloat16 g_wmlo[H * H];
__device__ __align__(16) __nv_bfloat16 g_xbhi[B * EIN2];
__device__ __align__(16) __nv_bfloat16 g_xblo[B * EIN2];
__device__ __align__(16) __nv_bfloat16 g_hnhi[B * H];
__device__ __align__(16) __nv_bfloat16 g_hnlo[B * H];

// ---------------- K0: generic fp32 -> bf16 hi/lo split ----------------
__global__ void k0_split(const float* __restrict__ src, __nv_bfloat16* __restrict__ hi,
                         __nv_bfloat16* __restrict__ lo) {
    int i = blockIdx.x * 256 + threadIdx.x;
    float v = src[i];
    __nv_bfloat16 h = __float2bfloat16(v);
    hi[i] = h;
    lo[i] = __float2bfloat16(v - __bfloat162float(h));
}

// ---------------- K1: embeddings + staging + bias inits + x split ----------------
__global__ void k1_prep(const int* __restrict__ n_in, const int* __restrict__ t_in,
                        const float* __restrict__ h0, const float* __restrict__ h_parent,
                        const float* __restrict__ embN, const float* __restrict__ embT,
                        const float* __restrict__ v_b,
                        const float* __restrict__ b_ih, const float* __restrict__ b_hh,
                        const float* __restrict__ Wh_b) {
    int b = blockIdx.x;
    int t = threadIdx.x;
    int n  = n_in[b];
    int tt = t_in[b];
    for (int k = t; k < EIN; k += blockDim.x) {
        float v = (k < EN) ? embN[n * EN + k] : embT[(size_t)tt * ET + (k - EN)];
        __nv_bfloat16 h = __float2bfloat16(v);
        g_xbhi[b * EIN2 + k] = h;
        g_xblo[b * EIN2 + k] = __float2bfloat16(v - __bfloat162float(h));
    }
    for (int k = t; k < H; k += blockDim.x) {
        float v = h0[b * H + k];
        __nv_bfloat16 h = __float2bfloat16(v);
        g_xbhi[b * EIN2 + EIN + k] = h;
        g_xblo[b * EIN2 + EIN + k] = __float2bfloat16(v - __bfloat162float(h));
        g_featT[(2 * H + k) * B + b] = h_parent[b * H + k];
        g_qT[k * B + b]              = Wh_b[k];
    }
    for (int j = t; j < G4; j += blockDim.x)
        g_gates[j * B + b] = b_ih[j] + b_hh[j];
    if (t < L) g_scores[b * L + t] = v_b[0];
}

// ---------------- KG: generic weight GEMM via mma, split-K, atomic out ----------------
// out[row][b] += A[row][:] . x[b][:]  (A fp32 split in-kernel, x pre-split bf16)
// A = two concatenated segments (A1: kb1 chunks of 32, then A2). 128 rows/CTA.
static constexpr int GLDK = 40;
__global__ void __launch_bounds__(256) kg_mma(const float* __restrict__ A1, int ldA1, int kb1,
                                              const float* __restrict__ A2, int ldA2,
                                              const __nv_bfloat16* __restrict__ bhi,
                                              const __nv_bfloat16* __restrict__ blo, int ldB,
                                              float* __restrict__ out, int chunksPerSplit) {
    __shared__ __align__(16) __nv_bfloat16 sAhi[128 * GLDK];
    __shared__ __align__(16) __nv_bfloat16 sAlo[128 * GLDK];
    __shared__ __align__(16) __nv_bfloat16 sBhi[32 * GLDK];
    __shared__ __align__(16) __nv_bfloat16 sBlo[32 * GLDK];
    int tid = threadIdx.x, w = tid >> 5, lane = tid & 31;
    int g = lane >> 2, q = lane & 3;
    int r0 = blockIdx.x * 128;
    int c0 = blockIdx.y * chunksPerSplit;

    float d[4][4];
#pragma unroll
    for (int nb = 0; nb < 4; nb++)
#pragma unroll
        for (int c = 0; c < 4; c++) d[nb][c] = 0.f;

    float4 av[4];
    uint2 bh, bl;
    int arow = tid >> 3, ac4 = tid & 7;   // A: 8 float4 per row, 4 iters cover 128 rows
    int bn = tid >> 3, bcc = tid & 7;     // B: 8 uint2 per n-row

    auto ldg = [&](int ch) {
        const float* A; int ld_; int kk;
        if (ch < kb1) { A = A1; ld_ = ldA1; kk = ch * 32; }
        else          { A = A2; ld_ = ldA2; kk = (ch - kb1) * 32; }
#pragma unroll
        for (int i = 0; i < 4; i++)
            av[i] = *(const float4*)&A[(size_t)(r0 + arow + i * 32) * ld_ + kk + 4 * ac4];
        int kb = ch * 32;
        bh = *(const uint2*)&bhi[bn * ldB + kb + bcc * 4];
        bl = *(const uint2*)&blo[bn * ldB + kb + bcc * 4];
    };
    auto sts = [&]() {
#pragma unroll
        for (int i = 0; i < 4; i++) {
            uint2 h, l;
            h.x = pkbf(av[i].x, av[i].y);
            h.y = pkbf(av[i].z, av[i].w);
            l.x = pkbf(bfres(av[i].x), bfres(av[i].y));
            l.y = pkbf(bfres(av[i].z), bfres(av[i].w));
            *(uint2*)&sAhi[(arow + i * 32) * GLDK + ac4 * 4] = h;
            *(uint2*)&sAlo[(arow + i * 32) * GLDK + ac4 * 4] = l;
        }
        *(uint2*)&sBhi[bn * GLDK + bcc * 4] = bh;
        *(uint2*)&sBlo[bn * GLDK + bcc * 4] = bl;
    };
    auto comp = [&]() {
#pragma unroll
        for (int ks = 0; ks < 2; ks++) {
            int kk = ks * 16 + q * 2;
            int ar = w * 16 + g;
            u32 ah[4], al[4];
            ah[0] = *(const u32*)&sAhi[ar * GLDK + kk];
            ah[1] = *(const u32*)&sAhi[(ar + 8) * GLDK + kk];
            ah[2] = *(const u32*)&sAhi[ar * GLDK + kk + 8];
            ah[3] = *(const u32*)&sAhi[(ar + 8) * GLDK + kk + 8];
            al[0] = *(const u32*)&sAlo[ar * GLDK + kk];
            al[1] = *(const u32*)&sAlo[(ar + 8) * GLDK + kk];
            al[2] = *(const u32*)&sAlo[ar * GLDK + kk + 8];
            al[3] = *(const u32*)&sAlo[(ar + 8) * GLDK + kk + 8];
#pragma unroll
            for (int nb = 0; nb < 4; nb++) {
                int bnn = nb * 8 + g;
                u32 bh0 = *(const u32*)&sBhi[bnn * GLDK + kk];
                u32 bh1 = *(const u32*)&sBhi[bnn * GLDK + kk + 8];
                u32 bl0 = *(const u32*)&sBlo[bnn * GLDK + kk];
                u32 bl1 = *(const u32*)&sBlo[bnn * GLDK + kk + 8];
                mma16816(d[nb], ah, bh0, bh1);
                mma16816(d[nb], al, bh0, bh1);
                mma16816(d[nb], ah, bl0, bl1);
            }
        }
    };

    ldg(c0);
    for (int t = 0; t < chunksPerSplit; t++) {
        __syncthreads();
        sts();
        if (t + 1 < chunksPerSplit) ldg(c0 + t + 1);
        __syncthreads();
        comp();
    }

    int vlo = r0 + w * 16 + g;
    int vhi = vlo + 8;
#pragma unroll
    for (int nb = 0; nb < 4; nb++) {
        int col = nb * 8 + q * 2;
        atomicAdd(&out[(size_t)vlo * 32 + col], d[nb][0]);
        atomicAdd(&out[(size_t)vlo * 32 + col + 1], d[nb][1]);
        atomicAdd(&out[(size_t)vhi * 32 + col], d[nb][2]);
        atomicAdd(&out[(size_t)vhi * 32 + col + 1], d[nb][3]);
    }
}

// ---------------- K3: LSTM pointwise (+ h_new bf16 split) ----------------
__global__ void k3_lstm(const float* __restrict__ c0, float* __restrict__ d_out) {
    int idx = blockIdx.x * blockDim.x + threadIdx.x;
    int b = idx & 31, j = idx >> 5;
    float gi = g_gates[j * B + b];
    float gf = g_gates[(H + j) * B + b];
    float gg = g_gates[(2 * H + j) * B + b];
    float go = g_gates[(3 * H + j) * B + b];
    float cp = c0[b * H + j];
    float si = 1.f / (1.f + expf(-gi));
    float sf = 1.f / (1.f + expf(-gf));
    float so = 1.f / (1.f + expf(-go));
    float cn = sf * cp + si * tanhf(gg);
    float hn = so * tanhf(cn);
    g_featT[(H + j) * B + b] = hn;
    __nv_bfloat16 hh = __float2bfloat16(hn);
    g_hnhi[b * H + j] = hh;
    g_hnlo[b * H + j] = __float2bfloat16(hn - __bfloat162float(hh));
    d_out[NLOG + b * H + j] = hn;
    d_out[NLOG + B * H + b * H + j] = cn;
}

// ---------------- K5: attention GEMM via mma 3-pass + fused v*tanh ----------------
static constexpr int K5KC  = 32;
static constexpr int K5LDK = 40;

__global__ void __launch_bounds__(256) k5_mma(const __nv_bfloat16* __restrict__ ehi,
                                              const __nv_bfloat16* __restrict__ elo,
                                              const __nv_bfloat16* __restrict__ wmhi,
                                              const __nv_bfloat16* __restrict__ wmlo,
                                              const float* __restrict__ Wm_b,
                                              const float* __restrict__ v_w) {
    __shared__ __align__(16) __nv_bfloat16 sAhi[128 * K5LDK];
    __shared__ __align__(16) __nv_bfloat16 sAlo[128 * K5LDK];
    __shared__ __align__(16) __nv_bfloat16 sBhi[64 * K5LDK];
    __shared__ __align__(16) __nv_bfloat16 sBlo[64 * K5LDK];
    __shared__ float red[128];
    int tid = threadIdx.x, w = tid >> 5, lane = tid & 31;
    int g = lane >> 2, q = lane & 3;
    int n0 = blockIdx.x * 64;
    int by = blockIdx.y;
    const __nv_bfloat16* Ah = ehi + (size_t)by * L * H;
    const __nv_bfloat16* Al = elo + (size_t)by * L * H;

    float d[8][4];
#pragma unroll
    for (int nb = 0; nb < 8; nb++)
#pragma unroll
        for (int c = 0; c < 4; c++) d[nb][c] = 0.f;

    uint4 avh[2], avl[2], bvh, bvl;
    int arow = tid >> 2, ac8 = (tid & 3) * 8;
    int brow = tid >> 2, bc8 = (tid & 3) * 8;

    auto ldg = [&](int ch) {
        int k0 = ch * K5KC;
#pragma unroll
        for (int i = 0; i < 2; i++) {
            avh[i] = *(const uint4*)&Ah[(arow + i * 64) * H + k0 + ac8];
            avl[i] = *(const uint4*)&Al[(arow + i * 64) * H + k0 + ac8];
        }
        bvh = *(const uint4*)&wmhi[(size_t)(n0 + brow) * H + k0 + bc8];
        bvl = *(const uint4*)&wmlo[(size_t)(n0 + brow) * H + k0 + bc8];
    };
    auto sts = [&]() {
#pragma unroll
        for (int i = 0; i < 2; i++) {
            *(uint4*)&sAhi[(arow + i * 64) * K5LDK + ac8] = avh[i];
            *(uint4*)&sAlo[(arow + i * 64) * K5LDK + ac8] = avl[i];
        }
        *(uint4*)&sBhi[brow * K5LDK + bc8] = bvh;
        *(uint4*)&sBlo[brow * K5LDK + bc8] = bvl;
    };
    auto comp = [&]() {
#pragma unroll
        for (int ks = 0; ks < 2; ks++) {
            int kk = ks * 16 + q * 2;
            int ar = w * 16 + g;
            u32 ah[4], al[4];
            ah[0] = *(const u32*)&sAhi[ar * K5LDK + kk];
            ah[1] = *(const u32*)&sAhi[(ar + 8) * K5LDK + kk];
            ah[2] = *(const u32*)&sAhi[ar * K5LDK + kk + 8];
            ah[3] = *(const u32*)&sAhi[(ar + 8) * K5LDK + kk + 8];
            al[0] = *(const u32*)&sAlo[ar * K5LDK + kk];
            al[1] = *(const u32*)&sAlo[(ar + 8) * K5LDK + kk];
            al[2] = *(const u32*)&sAlo[ar * K5LDK + kk + 8];
            al[3] = *(const u32*)&sAlo[(ar + 8) * K5LDK + kk + 8];
#pragma unroll
            for (int nb = 0; nb < 8; nb++) {
                int bn = nb * 8 + g;
                u32 bh0 = *(const u32*)&sBhi[bn * K5LDK + kk];
                u32 bh1 = *(const u32*)&sBhi[bn * K5LDK + kk + 8];
                u32 bl0 = *(const u32*)&sBlo[bn * K5LDK + kk];
                u32 bl1 = *(const u32*)&sBlo[bn * K5LDK + kk + 8];
                mma16816(d[nb], ah, bh0, bh1);
                mma16816(d[nb], al, bh0, bh1);
                mma16816(d[nb], ah, bl0, bl1);
            }
        }
    };

    constexpr int NCH = H / K5KC;
    ldg(0);
    for (int ch = 0; ch < NCH; ch++) {
        __syncthreads();
        sts();
        if (ch + 1 < NCH) ldg(ch + 1);
        __syncthreads();
        comp();
    }

    float plo = 0.f, phi = 0.f;
#pragma unroll
    for (int nb = 0; nb < 8; nb++) {
        int col0 = n0 + nb * 8 + q * 2;
        int col1 = col0 + 1;
        float vw0 = v_w[col0], vw1 = v_w[col1];
        float mb0 = Wm_b[col0], mb1 = Wm_b[col1];
        float q0 = g_qT[col0 * B + by];
        float q1 = g_qT[col1 * B + by];
        plo += vw0 * tanhf(d[nb][0] + mb0 + q0) + vw1 * tanhf(d[nb][1] + mb1 + q1);
        phi += vw0 * tanhf(d[nb][2] + mb0 + q0) + vw1 * tanhf(d[nb][3] + mb1 + q1);
    }
    plo += __shfl_xor_sync(~0u, plo, 1);
    plo += __shfl_xor_sync(~0u, plo, 2);
    phi += __shfl_xor_sync(~0u, phi, 1);
    phi += __shfl_xor_sync(~0u, phi, 2);
    if (q == 0) {
        red[w * 16 + g] = plo;
        red[w * 16 + g + 8] = phi;
    }
    __syncthreads();
    if (tid < 128) atomicAdd(&g_scores[by * L + tid], red[tid]);
}

// ---------------- K7: softmax over L + context ----------------
__global__ void k7_ctx(const float* __restrict__ enc, const unsigned char* __restrict__ mask) {
    __shared__ float sc[128];
    __shared__ float redm[16];
    int b = blockIdx.x, t = threadIdx.x;
    if (t < 128) {
        float s = g_scores[b * L + t];
        if (mask[b * L + t]) s = -1e20f;
        sc[t] = s;
        g_scores[b * L + t] = s;
    }
    __syncthreads();
    float m = (t < 128) ? sc[t] : -INFINITY;
#pragma unroll
    for (int o = 16; o > 0; o >>= 1) m = fmaxf(m, __shfl_xor_sync(~0u, m, o));
    if ((t & 31) == 0) redm[t >> 5] = m;
    __syncthreads();
    if (t == 0) {
        float mm = redm[0];
        for (int w = 1; w < 8; w++) mm = fmaxf(mm, redm[w]);
        redm[0] = mm;
    }
    __syncthreads();
    float mx = redm[0];
    float e = (t < 128) ? expf(sc[t] - mx) : 0.f;
    float s = e;
#pragma unroll
    for (int o = 16; o > 0; o >>= 1) s += __shfl_xor_sync(~0u, s, o);
    if ((t & 31) == 0) redm[8 + (t >> 5)] = s;
    __syncthreads();
    if (t == 0) {
        float ss = 0.f;
        for (int w = 0; w < 8; w++) ss += redm[8 + w];
        redm[8] = ss;
    }
    __syncthreads();
    float sum = redm[8];
    if (t < 128) sc[t] = e / sum;
    if (t == 0) g_lse[b] = mx + logf(sum);
    __syncthreads();
    const float* E = enc + (size_t)b * L * H;
#pragma unroll
    for (int jj = 0; jj < 4; jj++) {
        int j = t + jj * 256;
        float a = 0.f;
#pragma unroll 4
        for (int l = 0; l < 128; l++) a += sc[l] * E[l * H + j];
        g_context[b * H + j] = a;
        g_featT[j * B + b] = a;
    }
}

// ---------------- K8: pointer switch + copy-logits ----------------
__global__ void k8_s(const float* __restrict__ ws_w, const float* __restrict__ ws_b,
                     float* __restrict__ d_out) {
    __shared__ float red[8];
    __shared__ float sh[2];
    int b = blockIdx.x, t = threadIdx.x;
    float a = 0.f;
    for (int j = t; j < H; j += 256) a += g_context[b * H + j] * ws_w[j];
    for (int j = t; j < H; j += 256) a += g_featT[(H + j) * B + b] * ws_w[H + j];
#pragma unroll
    for (int o = 16; o > 0; o >>= 1) a += __shfl_xor_sync(~0u, a, o);
    if ((t & 31) == 0) red[t >> 5] = a;
    __syncthreads();
    if (t == 0) {
        float zz = ws_b[0];
        for (int w = 0; w < 8; w++) zz += red[w];
        float s  = (zz >= 0.f) ? -log1pf(expf(-zz)) : zz - log1pf(expf(zz));
        float zm = -zz;
        float l1 = (zm >= 0.f) ? -log1pf(expf(-zm)) : zm - log1pf(expf(zm));
        l1 = fmaxf(l1, -41.446531673892822f);
        g_sB[b] = s;
        sh[0] = l1;
        sh[1] = g_lse[b];
    }
    __syncthreads();
    if (t < 128)
        d_out[(size_t)b * LOGN + VOUT + t] = sh[0] + g_scores[b * L + t] - sh[1];
}

// ---------------- K9: split features into bf16 hi/lo, [b][k] layout ----------------
__global__ void k9_split(__nv_bfloat16* __restrict__ fhi, __nv_bfloat16* __restrict__ flo) {
    int b = blockIdx.y;
    int k = blockIdx.x * 256 + threadIdx.x;
    float v = g_featT[k * B + b];
    __nv_bfloat16 h = __float2bfloat16(v);
    fhi[b * F3 + k] = h;
    flo[b * F3 + k] = __float2bfloat16(v - __bfloat162float(h));
}

// ---------------- K10: vocab GEMM via mma 3-pass, KC=32, register prefetch ----------------
static constexpr int KC   = 32;
static constexpr int NCHP = F3 / KC;   // 96
static constexpr int LDK  = 40;

__global__ void __launch_bounds__(256) k10_mma(const float* __restrict__ wg_w,
                                               const float* __restrict__ wg_b,
                                               const __nv_bfloat16* __restrict__ fhi,
                                               const __nv_bfloat16* __restrict__ flo) {
    __shared__ __align__(16) __nv_bfloat16 sAhi[128 * LDK];
    __shared__ __align__(16) __nv_bfloat16 sAlo[128 * LDK];
    __shared__ __align__(16) __nv_bfloat16 sBhi[32 * LDK];
    __shared__ __align__(16) __nv_bfloat16 sBlo[32 * LDK];
    int tid = threadIdx.x, w = tid >> 5, lane = tid & 31;
    int r0 = blockIdx.x * 128;
    int g = lane >> 2, q = lane & 3;

    float d[4][4];
#pragma unroll
    for (int nb = 0; nb < 4; nb++)
#pragma unroll
        for (int c = 0; c < 4; c++) d[nb][c] = 0.f;

    float4 av[4];
    uint2 bh, bl;
    int arow = tid >> 3, ac4 = tid & 7;
    int bn = tid >> 3, bcc = tid & 7;

    auto ldg = [&](int ch) {
        int k0 = ch * KC;
#pragma unroll
        for (int i = 0; i < 4; i++) {
            int rr = r0 + arow + i * 32;
            if (rr > VOUT - 1) rr = VOUT - 1;
            av[i] = *(const float4*)&wg_w[(size_t)rr * F3 + k0 + 4 * ac4];
        }
        bh = *(const uint2*)&fhi[bn * F3 + k0 + bcc * 4];
        bl = *(const uint2*)&flo[bn * F3 + k0 + bcc * 4];
    };
    auto sts = [&]() {
#pragma unroll
        for (int i = 0; i < 4; i++) {
            uint2 h, l;
            h.x = pkbf(av[i].x, av[i].y);
            h.y = pkbf(av[i].z, av[i].w);
            l.x = pkbf(bfres(av[i].x), bfres(av[i].y));
            l.y = pkbf(bfres(av[i].z), bfres(av[i].w));
            *(uint2*)&sAhi[(arow + i * 32) * LDK + ac4 * 4] = h;
            *(uint2*)&sAlo[(arow + i * 32) * LDK + ac4 * 4] = l;
        }
        *(uint2*)&sBhi[bn * LDK + bcc * 4] = bh;
        *(uint2*)&sBlo[bn * LDK + bcc * 4] = bl;
    };
    auto comp = [&]() {
#pragma unroll
        for (int ks = 0; ks < 2; ks++) {
            int kk = ks * 16 + q * 2;
            int ar = w * 16 + g;
            u32 ah[4], al[4];
            ah[0] = *(const u32*)&sAhi[ar * LDK + kk];
            ah[1] = *(const u32*)&sAhi[(ar + 8) * LDK + kk];
            ah[2] = *(const u32*)&sAhi[ar * LDK + kk + 8];
            ah[3] = *(const u32*)&sAhi[(ar + 8) * LDK + kk + 8];
            al[0] = *(const u32*)&sAlo[ar * LDK + kk];
            al[1] = *(const u32*)&sAlo[(ar + 8) * LDK + kk];
            al[2] = *(const u32*)&sAlo[ar * LDK + kk + 8];
            al[3] = *(const u32*)&sAlo[(ar + 8) * LDK + kk + 8];
#pragma unroll
            for (int nb = 0; nb < 4; nb++) {
                int bnn = nb * 8 + g;
                u32 bh0 = *(const u32*)&sBhi[bnn * LDK + kk];
                u32 bh1 = *(const u32*)&sBhi[bnn * LDK + kk + 8];
                u32 bl0 = *(const u32*)&sBlo[bnn * LDK + kk];
                u32 bl1 = *(const u32*)&sBlo[bnn * LDK + kk + 8];
                mma16816(d[nb], ah, bh0, bh1);
                mma16816(d[nb], al, bh0, bh1);
                mma16816(d[nb], ah, bl0, bl1);
            }
        }
    };

    ldg(0);
    for (int ch = 0; ch < NCHP; ch++) {
        __syncthreads();
        sts();
        if (ch + 1 < NCHP) ldg(ch + 1);
        __syncthreads();
        comp();
    }

    int vlo = r0 + w * 16 + g;
    int vhi = vlo + 8;
    float blo = (vlo < VOUT) ? wg_b[vlo] : 0.f;
    float bhi_ = (vhi < VOUT) ? wg_b[vhi] : 0.f;
#pragma unroll
    for (int nb = 0; nb < 4; nb++) {
        int col = nb * 8 + q * 2;
        if (vlo < VOUT) {
            float2 o = { d[nb][0] + blo, d[nb][1] + blo };
            *(float2*)&g_wgout[(size_t)vlo * 32 + col] = o;
        }
        if (vhi < VOUT) {
            float2 o = { d[nb][2] + bhi_, d[nb][3] + bhi_ };
            *(float2*)&g_wgout[(size_t)vhi * 32 + col] = o;
        }
    }
}

// ---------------- K11a/b: log-sum-exp over VOUT (two-pass, unrolled) ----------------
__global__ void k11a_lse() {
    __shared__ float pm[8][32];
    __shared__ float ps[8][32];
    int w = threadIdx.x >> 5, lane = threadIdx.x & 31;
    int base = blockIdx.x * 1024 + w * 128;
    float mm[4] = {-INFINITY, -INFINITY, -INFINITY, -INFINITY};
#pragma unroll 8
    for (int i = 0; i < 128; i += 4) {
#pragma unroll
        for (int j = 0; j < 4; j++) {
            int v = base + i + j;
            if (v < VOUT) mm[j] = fmaxf(mm[j], g_wgout[(size_t)v * B + lane]);
        }
    }
    float m = fmaxf(fmaxf(mm[0], mm[1]), fmaxf(mm[2], mm[3]));
    float ss[4] = {0.f, 0.f, 0.f, 0.f};
#pragma unroll 8
    for (int i = 0; i < 128; i += 4) {
#pragma unroll
        for (int j = 0; j < 4; j++) {
            int v = base + i + j;
            if (v < VOUT) ss[j] += expf(g_wgout[(size_t)v * B + lane] - m);
        }
    }
    float s = (ss[0] + ss[1]) + (ss[2] + ss[3]);
    pm[w][lane] = m; ps[w][lane] = s;
    __syncthreads();
    if (w == 0) {
        float M = pm[0][lane], S = ps[0][lane];
#pragma unroll
        for (int i = 1; i < 8; i++) {
            float m2 = pm[i][lane], s2 = ps[i][lane];
            float nm = fmaxf(M, m2);
            S = S * expf(M - nm) + s2 * expf(m2 - nm);
            M = nm;
        }
        g_pmax[blockIdx.x * 32 + lane] = M;
        g_psum[blockIdx.x * 32 + lane] = S;
    }
}

__global__ void k11b_lse() {
    int b = threadIdx.x;
    float M = g_pmax[b], S = g_psum[b];
    for (int i = 1; i < NCHUNK; i++) {
        float m2 = g_pmax[i * 32 + b], s2 = g_psum[i * 32 + b];
        float nm = fmaxf(M, m2);
        S = S * expf(M - nm) + s2 * expf(m2 - nm);
        M = nm;
    }
    g_wlse[b] = M + logf(S);
}

// ---------------- K12: transpose + final vocab logits ----------------
__global__ void k12_out(float* __restrict__ d_out) {
    __shared__ float sm[32][33];
    int tx = threadIdx.x & 31, ty = threadIdx.x >> 5;
    int v0 = blockIdx.x * 32;
#pragma unroll
    for (int r = 0; r < 4; r++) {
        int row = r * 8 + ty;
        int v = v0 + row;
        if (v > VOUT - 1) v = VOUT - 1;
        sm[row][tx] = g_wgout[(size_t)v * B + tx];
    }
    __syncthreads();
#pragma unroll
    for (int r = 0; r < 4; r++) {
        int b = r * 8 + ty;
        int v = v0 + tx;
        if (v < VOUT)
            d_out[(size_t)b * LOGN + v] = g_sB[b] + sm[tx][b] - g_wlse[b];
    }
}

// ---------------- launch ----------------
extern "C" void kernel_launch(void* const* d_in, const int* in_sizes, int n_in,
                              void* d_out, int out_size) {
    const int*   n_input  = (const int*)d_in[0];
    const int*   t_input  = (const int*)d_in[1];
    const float* h0       = (const float*)d_in[2];
    const float* c0       = (const float*)d_in[3];
    const float* enc_out  = (const float*)d_in[4];
    const unsigned char* mask = (const unsigned char*)d_in[5];
    const float* h_parent = (const float*)d_in[6];
    const float* embN     = (const float*)d_in[7];
    const float* embT     = (const float*)d_in[8];
    const float* W_ih     = (const float*)d_in[9];
    const float* W_hh     = (const float*)d_in[10];
    const float* b_ih     = (const float*)d_in[11];
    const float* b_hh     = (const float*)d_in[12];
    const float* Wh_w     = (const float*)d_in[13];
    const float* Wh_b     = (const float*)d_in[14];
    const float* Wm_w     = (const float*)d_in[15];
    const float* Wm_b     = (const float*)d_in[16];
    const float* v_w      = (const float*)d_in[17];
    const float* v_b      = (const float*)d_in[18];
    const float* wg_w     = (const float*)d_in[19];
    const float* wg_b     = (const float*)d_in[20];
    const float* ws_w     = (const float*)d_in[21];
    const float* ws_b     = (const float*)d_in[22];
    float* out = (float*)d_out;

    float* gatesP; cudaGetSymbolAddress((void**)&gatesP, g_gates);
    float* qTP;    cudaGetSymbolAddress((void**)&qTP, g_qT);
    __nv_bfloat16* fhiP;  cudaGetSymbolAddress((void**)&fhiP, g_fhi);
    __nv_bfloat16* floP;  cudaGetSymbolAddress((void**)&floP, g_flo);
    __nv_bfloat16* ehiP;  cudaGetSymbolAddress((void**)&ehiP, g_ehi);
    __nv_bfloat16* eloP;  cudaGetSymbolAddress((void**)&eloP, g_elo);
    __nv_bfloat16* wmhiP; cudaGetSymbolAddress((void**)&wmhiP, g_wmhi);
    __nv_bfloat16* wmloP; cudaGetSymbolAddress((void**)&wmloP, g_wmlo);
    __nv_bfloat16* xbhiP; cudaGetSymbolAddress((void**)&xbhiP, g_xbhi);
    __nv_bfloat16* xbloP; cudaGetSymbolAddress((void**)&xbloP, g_xblo);
    __nv_bfloat16* hnhiP; cudaGetSymbolAddress((void**)&hnhiP, g_hnhi);
    __nv_bfloat16* hnloP; cudaGetSymbolAddress((void**)&hnloP, g_hnlo);

    k0_split<<<(B * L * H) / 256, 256>>>(enc_out, ehiP, eloP);
    k0_split<<<(H * H) / 256, 256>>>(Wm_w, wmhiP, wmloP);
    k1_prep<<<B, 256>>>(n_input, t_input, h0, h_parent, embN, embT, v_b, b_ih, b_hh, Wh_b);
    // LSTM gates: 56 chunks total (24 from W_ih, 32 from W_hh), split-K x4
    kg_mma<<<dim3(G4 / 128, 4), 256>>>(W_ih, EIN, EIN / 32, W_hh, H,
                                       xbhiP, xbloP, EIN2, gatesP, 14);
    k3_lstm<<<(B * H) / 256, 256>>>(c0, out);
    // q: 32 chunks, split-K x8
    kg_mma<<<dim3(H / 128, 8), 256>>>(Wh_w, H, H / 32, (const float*)nullptr, 0,
                                      hnhiP, hnloP, H, qTP, 4);
    k5_mma<<<dim3(H / 64, B), 256>>>(ehiP, eloP, wmhiP, wmloP, Wm_b, v_w);
    k7_ctx<<<B, 256>>>(enc_out, mask);
    k8_s<<<B, 256>>>(ws_w, ws_b, out);
    k9_split<<<dim3(F3 / 256, B), 256>>>(fhiP, floP);
    k10_mma<<<(VOUT + 127) / 128, 256>>>(wg_w, wg_b, fhiP, floP);
    k11a_lse<<<NCHUNK, 256>>>();
    k11b_lse<<<1, 32>>>();
    k12_out<<<(VOUT + 31) / 32, 256>>>(out);
}

// round 10
// speedup vs baseline: 3.0864x; 1.1023x over previous
#include <cuda_runtime.h>
#include <cuda_bf16.h>
#include <math.h>

typedef unsigned long long ull;
typedef unsigned int u32;

#define DI __device__ __forceinline__

DI u32 pkbf(float a, float b){ u32 r; asm("cvt.rn.bf16x2.f32 %0, %1, %2;" : "=r"(r) : "f"(b), "f"(a)); return r; }  // mem order [a,b]
DI float bfres(float v){ __nv_bfloat16 h = __float2bfloat16(v); return v - __bfloat162float(h); }

// warp mma: D[16x8] += A[16x16,row] * B[16x8,col], bf16 in, fp32 accum
DI void mma16816(float* d, const u32* a, u32 b0, u32 b1){
    asm volatile("mma.sync.aligned.m16n8k16.row.col.f32.bf16.bf16.f32 "
        "{%0,%1,%2,%3},{%4,%5,%6,%7},{%8,%9},{%0,%1,%2,%3};"
        : "+f"(d[0]), "+f"(d[1]), "+f"(d[2]), "+f"(d[3])
        : "r"(a[0]), "r"(a[1]), "r"(a[2]), "r"(a[3]), "r"(b0), "r"(b1));
}

static constexpr int B    = 32;
static constexpr int L    = 128;
static constexpr int H    = 1024;
static constexpr int EN   = 256;
static constexpr int ET   = 512;
static constexpr int EIN  = 768;
static constexpr int EIN2 = 1792;   // EIN + H
static constexpr int G4   = 4096;
static constexpr int VOUT = 50003;
static constexpr int LOGN = VOUT + L;
static constexpr int F3   = 3072;
static constexpr int NLOG = B * LOGN;
static constexpr int NCHUNK = 49;

// ---------------- scratch ----------------
__device__ __align__(16) float g_featT[F3 * B];
__device__ __align__(16) float g_gates[G4 * B];
__device__ __align__(16) float g_qT[H * B];
__device__ __align__(16) float g_scores[B * L];
__device__ float g_lse[B];
__device__ __align__(16) float g_context[B * H];
__device__ float g_sB[B];
__device__ __align__(16) float g_wgout[(VOUT + 64) * B];
__device__ float g_pmax[NCHUNK * 32];
__device__ float g_psum[NCHUNK * 32];
__device__ float g_wlse[B];
__device__ __align__(16) __nv_bfloat16 g_fhi[B * F3];
__device__ __align__(16) __nv_bfloat16 g_flo[B * F3];
__device__ __align__(16) __nv_bfloat16 g_ehi[B * L * H];
__device__ __align__(16) __nv_bfloat16 g_elo[B * L * H];
__device__ __align__(16) __nv_bfloat16 g_wmhi[H * H];
__device__ __align__(16) __nv_bfloat16 g_wmlo[H * H];
__device__ __align__(16) __nv_bfloat16 g_xbhi[B * EIN2];
__device__ __align__(16) __nv_bfloat16 g_xblo[B * EIN2];
__device__ __align__(16) __nv_bfloat16 g_hnhi[B * H];
__device__ __align__(16) __nv_bfloat16 g_hnlo[B * H];

// ---------------- K0: generic fp32 -> bf16 hi/lo split ----------------
__global__ void k0_split(const float* __restrict__ src, __nv_bfloat16* __restrict__ hi,
                         __nv_bfloat16* __restrict__ lo) {
    int i = blockIdx.x * 256 + threadIdx.x;
    float v = src[i];
    __nv_bfloat16 h = __float2bfloat16(v);
    hi[i] = h;
    lo[i] = __float2bfloat16(v - __bfloat162float(h));
}

// ---------------- K1: embeddings + staging + bias inits + x split ----------------
__global__ void k1_prep(const int* __restrict__ n_in, const int* __restrict__ t_in,
                        const float* __restrict__ h0, const float* __restrict__ h_parent,
                        const float* __restrict__ embN, const float* __restrict__ embT,
                        const float* __restrict__ v_b,
                        const float* __restrict__ b_ih, const float* __restrict__ b_hh,
                        const float* __restrict__ Wh_b) {
    int b = blockIdx.x;
    int t = threadIdx.x;
    int n  = n_in[b];
    int tt = t_in[b];
    for (int k = t; k < EIN; k += blockDim.x) {
        float v = (k < EN) ? embN[n * EN + k] : embT[(size_t)tt * ET + (k - EN)];
        __nv_bfloat16 h = __float2bfloat16(v);
        g_xbhi[b * EIN2 + k] = h;
        g_xblo[b * EIN2 + k] = __float2bfloat16(v - __bfloat162float(h));
    }
    for (int k = t; k < H; k += blockDim.x) {
        float v = h0[b * H + k];
        __nv_bfloat16 h = __float2bfloat16(v);
        g_xbhi[b * EIN2 + EIN + k] = h;
        g_xblo[b * EIN2 + EIN + k] = __float2bfloat16(v - __bfloat162float(h));
        g_featT[(2 * H + k) * B + b] = h_parent[b * H + k];
        g_qT[k * B + b]              = Wh_b[k];
    }
    for (int j = t; j < G4; j += blockDim.x)
        g_gates[j * B + b] = b_ih[j] + b_hh[j];
    if (t < L) g_scores[b * L + t] = v_b[0];
}

// ---------------- KG: generic weight GEMM via mma, split-K, atomic out ----------------
static constexpr int GLDK = 40;
__global__ void __launch_bounds__(256) kg_mma(const float* __restrict__ A1, int ldA1, int kb1,
                                              const float* __restrict__ A2, int ldA2,
                                              const __nv_bfloat16* __restrict__ bhi,
                                              const __nv_bfloat16* __restrict__ blo, int ldB,
                                              float* __restrict__ out, int chunksPerSplit) {
    __shared__ __align__(16) __nv_bfloat16 sAhi[128 * GLDK];
    __shared__ __align__(16) __nv_bfloat16 sAlo[128 * GLDK];
    __shared__ __align__(16) __nv_bfloat16 sBhi[32 * GLDK];
    __shared__ __align__(16) __nv_bfloat16 sBlo[32 * GLDK];
    int tid = threadIdx.x, w = tid >> 5, lane = tid & 31;
    int g = lane >> 2, q = lane & 3;
    int r0 = blockIdx.x * 128;
    int c0 = blockIdx.y * chunksPerSplit;

    float d[4][4];
#pragma unroll
    for (int nb = 0; nb < 4; nb++)
#pragma unroll
        for (int c = 0; c < 4; c++) d[nb][c] = 0.f;

    float4 av[4];
    uint2 bh, bl;
    int arow = tid >> 3, ac4 = tid & 7;
    int bn = tid >> 3, bcc = tid & 7;

    auto ldg = [&](int ch) {
        const float* A; int ld_; int kk;
        if (ch < kb1) { A = A1; ld_ = ldA1; kk = ch * 32; }
        else          { A = A2; ld_ = ldA2; kk = (ch - kb1) * 32; }
#pragma unroll
        for (int i = 0; i < 4; i++)
            av[i] = *(const float4*)&A[(size_t)(r0 + arow + i * 32) * ld_ + kk + 4 * ac4];
        int kb = ch * 32;
        bh = *(const uint2*)&bhi[bn * ldB + kb + bcc * 4];
        bl = *(const uint2*)&blo[bn * ldB + kb + bcc * 4];
    };
    auto sts = [&]() {
#pragma unroll
        for (int i = 0; i < 4; i++) {
            uint2 h, l;
            h.x = pkbf(av[i].x, av[i].y);
            h.y = pkbf(av[i].z, av[i].w);
            l.x = pkbf(bfres(av[i].x), bfres(av[i].y));
            l.y = pkbf(bfres(av[i].z), bfres(av[i].w));
            *(uint2*)&sAhi[(arow + i * 32) * GLDK + ac4 * 4] = h;
            *(uint2*)&sAlo[(arow + i * 32) * GLDK + ac4 * 4] = l;
        }
        *(uint2*)&sBhi[bn * GLDK + bcc * 4] = bh;
        *(uint2*)&sBlo[bn * GLDK + bcc * 4] = bl;
    };
    auto comp = [&]() {
#pragma unroll
        for (int ks = 0; ks < 2; ks++) {
            int kk = ks * 16 + q * 2;
            int ar = w * 16 + g;
            u32 ah[4], al[4];
            ah[0] = *(const u32*)&sAhi[ar * GLDK + kk];
            ah[1] = *(const u32*)&sAhi[(ar + 8) * GLDK + kk];
            ah[2] = *(const u32*)&sAhi[ar * GLDK + kk + 8];
            ah[3] = *(const u32*)&sAhi[(ar + 8) * GLDK + kk + 8];
            al[0] = *(const u32*)&sAlo[ar * GLDK + kk];
            al[1] = *(const u32*)&sAlo[(ar + 8) * GLDK + kk];
            al[2] = *(const u32*)&sAlo[ar * GLDK + kk + 8];
            al[3] = *(const u32*)&sAlo[(ar + 8) * GLDK + kk + 8];
#pragma unroll
            for (int nb = 0; nb < 4; nb++) {
                int bnn = nb * 8 + g;
                u32 bh0 = *(const u32*)&sBhi[bnn * GLDK + kk];
                u32 bh1 = *(const u32*)&sBhi[bnn * GLDK + kk + 8];
                u32 bl0 = *(const u32*)&sBlo[bnn * GLDK + kk];
                u32 bl1 = *(const u32*)&sBlo[bnn * GLDK + kk + 8];
                mma16816(d[nb], ah, bh0, bh1);
                mma16816(d[nb], al, bh0, bh1);
                mma16816(d[nb], ah, bl0, bl1);
            }
        }
    };

    ldg(c0);
    for (int t = 0; t < chunksPerSplit; t++) {
        __syncthreads();
        sts();
        if (t + 1 < chunksPerSplit) ldg(c0 + t + 1);
        __syncthreads();
        comp();
    }

    int vlo = r0 + w * 16 + g;
    int vhi = vlo + 8;
#pragma unroll
    for (int nb = 0; nb < 4; nb++) {
        int col = nb * 8 + q * 2;
        atomicAdd(&out[(size_t)vlo * 32 + col], d[nb][0]);
        atomicAdd(&out[(size_t)vlo * 32 + col + 1], d[nb][1]);
        atomicAdd(&out[(size_t)vhi * 32 + col], d[nb][2]);
        atomicAdd(&out[(size_t)vhi * 32 + col + 1], d[nb][3]);
    }
}

// ---------------- K3: LSTM pointwise (+ h_new bf16 split) ----------------
__global__ void k3_lstm(const float* __restrict__ c0, float* __restrict__ d_out) {
    int idx = blockIdx.x * blockDim.x + threadIdx.x;
    int b = idx & 31, j = idx >> 5;
    float gi = g_gates[j * B + b];
    float gf = g_gates[(H + j) * B + b];
    float gg = g_gates[(2 * H + j) * B + b];
    float go = g_gates[(3 * H + j) * B + b];
    float cp = c0[b * H + j];
    float si = 1.f / (1.f + expf(-gi));
    float sf = 1.f / (1.f + expf(-gf));
    float so = 1.f / (1.f + expf(-go));
    float cn = sf * cp + si * tanhf(gg);
    float hn = so * tanhf(cn);
    g_featT[(H + j) * B + b] = hn;
    __nv_bfloat16 hh = __float2bfloat16(hn);
    g_hnhi[b * H + j] = hh;
    g_hnlo[b * H + j] = __float2bfloat16(hn - __bfloat162float(hh));
    d_out[NLOG + b * H + j] = hn;
    d_out[NLOG + B * H + b * H + j] = cn;
}

// ---------------- K5: attention GEMM via mma 3-pass + fused v*tanh ----------------
static constexpr int K5KC  = 32;
static constexpr int K5LDK = 40;

__global__ void __launch_bounds__(256) k5_mma(const __nv_bfloat16* __restrict__ ehi,
                                              const __nv_bfloat16* __restrict__ elo,
                                              const __nv_bfloat16* __restrict__ wmhi,
                                              const __nv_bfloat16* __restrict__ wmlo,
                                              const float* __restrict__ Wm_b,
                                              const float* __restrict__ v_w) {
    __shared__ __align__(16) __nv_bfloat16 sAhi[128 * K5LDK];
    __shared__ __align__(16) __nv_bfloat16 sAlo[128 * K5LDK];
    __shared__ __align__(16) __nv_bfloat16 sBhi[64 * K5LDK];
    __shared__ __align__(16) __nv_bfloat16 sBlo[64 * K5LDK];
    __shared__ float red[128];
    int tid = threadIdx.x, w = tid >> 5, lane = tid & 31;
    int g = lane >> 2, q = lane & 3;
    int n0 = blockIdx.x * 64;
    int by = blockIdx.y;
    const __nv_bfloat16* Ah = ehi + (size_t)by * L * H;
    const __nv_bfloat16* Al = elo + (size_t)by * L * H;

    float d[8][4];
#pragma unroll
    for (int nb = 0; nb < 8; nb++)
#pragma unroll
        for (int c = 0; c < 4; c++) d[nb][c] = 0.f;

    uint4 avh[2], avl[2], bvh, bvl;
    int arow = tid >> 2, ac8 = (tid & 3) * 8;
    int brow = tid >> 2, bc8 = (tid & 3) * 8;

    auto ldg = [&](int ch) {
        int k0 = ch * K5KC;
#pragma unroll
        for (int i = 0; i < 2; i++) {
            avh[i] = *(const uint4*)&Ah[(arow + i * 64) * H + k0 + ac8];
            avl[i] = *(const uint4*)&Al[(arow + i * 64) * H + k0 + ac8];
        }
        bvh = *(const uint4*)&wmhi[(size_t)(n0 + brow) * H + k0 + bc8];
        bvl = *(const uint4*)&wmlo[(size_t)(n0 + brow) * H + k0 + bc8];
    };
    auto sts = [&]() {
#pragma unroll
        for (int i = 0; i < 2; i++) {
            *(uint4*)&sAhi[(arow + i * 64) * K5LDK + ac8] = avh[i];
            *(uint4*)&sAlo[(arow + i * 64) * K5LDK + ac8] = avl[i];
        }
        *(uint4*)&sBhi[brow * K5LDK + bc8] = bvh;
        *(uint4*)&sBlo[brow * K5LDK + bc8] = bvl;
    };
    auto comp = [&]() {
#pragma unroll
        for (int ks = 0; ks < 2; ks++) {
            int kk = ks * 16 + q * 2;
            int ar = w * 16 + g;
            u32 ah[4], al[4];
            ah[0] = *(const u32*)&sAhi[ar * K5LDK + kk];
            ah[1] = *(const u32*)&sAhi[(ar + 8) * K5LDK + kk];
            ah[2] = *(const u32*)&sAhi[ar * K5LDK + kk + 8];
            ah[3] = *(const u32*)&sAhi[(ar + 8) * K5LDK + kk + 8];
            al[0] = *(const u32*)&sAlo[ar * K5LDK + kk];
            al[1] = *(const u32*)&sAlo[(ar + 8) * K5LDK + kk];
            al[2] = *(const u32*)&sAlo[ar * K5LDK + kk + 8];
            al[3] = *(const u32*)&sAlo[(ar + 8) * K5LDK + kk + 8];
#pragma unroll
            for (int nb = 0; nb < 8; nb++) {
                int bn = nb * 8 + g;
                u32 bh0 = *(const u32*)&sBhi[bn * K5LDK + kk];
                u32 bh1 = *(const u32*)&sBhi[bn * K5LDK + kk + 8];
                u32 bl0 = *(const u32*)&sBlo[bn * K5LDK + kk];
                u32 bl1 = *(const u32*)&sBlo[bn * K5LDK + kk + 8];
                mma16816(d[nb], ah, bh0, bh1);
                mma16816(d[nb], al, bh0, bh1);
                mma16816(d[nb], ah, bl0, bl1);
            }
        }
    };

    constexpr int NCH = H / K5KC;
    ldg(0);
    for (int ch = 0; ch < NCH; ch++) {
        __syncthreads();
        sts();
        if (ch + 1 < NCH) ldg(ch + 1);
        __syncthreads();
        comp();
    }

    float plo = 0.f, phi = 0.f;
#pragma unroll
    for (int nb = 0; nb < 8; nb++) {
        int col0 = n0 + nb * 8 + q * 2;
        int col1 = col0 + 1;
        float vw0 = v_w[col0], vw1 = v_w[col1];
        float mb0 = Wm_b[col0], mb1 = Wm_b[col1];
        float q0 = g_qT[col0 * B + by];
        float q1 = g_qT[col1 * B + by];
        plo += vw0 * tanhf(d[nb][0] + mb0 + q0) + vw1 * tanhf(d[nb][1] + mb1 + q1);
        phi += vw0 * tanhf(d[nb][2] + mb0 + q0) + vw1 * tanhf(d[nb][3] + mb1 + q1);
    }
    plo += __shfl_xor_sync(~0u, plo, 1);
    plo += __shfl_xor_sync(~0u, plo, 2);
    phi += __shfl_xor_sync(~0u, phi, 1);
    phi += __shfl_xor_sync(~0u, phi, 2);
    if (q == 0) {
        red[w * 16 + g] = plo;
        red[w * 16 + g + 8] = phi;
    }
    __syncthreads();
    if (tid < 128) atomicAdd(&g_scores[by * L + tid], red[tid]);
}

// ---------------- K7: softmax over L + context ----------------
__global__ void k7_ctx(const float* __restrict__ enc, const unsigned char* __restrict__ mask) {
    __shared__ float sc[128];
    __shared__ float redm[16];
    int b = blockIdx.x, t = threadIdx.x;
    if (t < 128) {
        float s = g_scores[b * L + t];
        if (mask[b * L + t]) s = -1e20f;
        sc[t] = s;
        g_scores[b * L + t] = s;
    }
    __syncthreads();
    float m = (t < 128) ? sc[t] : -INFINITY;
#pragma unroll
    for (int o = 16; o > 0; o >>= 1) m = fmaxf(m, __shfl_xor_sync(~0u, m, o));
    if ((t & 31) == 0) redm[t >> 5] = m;
    __syncthreads();
    if (t == 0) {
        float mm = redm[0];
        for (int w = 1; w < 8; w++) mm = fmaxf(mm, redm[w]);
        redm[0] = mm;
    }
    __syncthreads();
    float mx = redm[0];
    float e = (t < 128) ? expf(sc[t] - mx) : 0.f;
    float s = e;
#pragma unroll
    for (int o = 16; o > 0; o >>= 1) s += __shfl_xor_sync(~0u, s, o);
    if ((t & 31) == 0) redm[8 + (t >> 5)] = s;
    __syncthreads();
    if (t == 0) {
        float ss = 0.f;
        for (int w = 0; w < 8; w++) ss += redm[8 + w];
        redm[8] = ss;
    }
    __syncthreads();
    float sum = redm[8];
    if (t < 128) sc[t] = e / sum;
    if (t == 0) g_lse[b] = mx + logf(sum);
    __syncthreads();
    const float* E = enc + (size_t)b * L * H;
#pragma unroll
    for (int jj = 0; jj < 4; jj++) {
        int j = t + jj * 256;
        float a = 0.f;
#pragma unroll 4
        for (int l = 0; l < 128; l++) a += sc[l] * E[l * H + j];
        g_context[b * H + j] = a;
        g_featT[j * B + b] = a;
    }
}

// ---------------- K8: pointer switch + copy-logits ----------------
__global__ void k8_s(const float* __restrict__ ws_w, const float* __restrict__ ws_b,
                     float* __restrict__ d_out) {
    __shared__ float red[8];
    __shared__ float sh[2];
    int b = blockIdx.x, t = threadIdx.x;
    float a = 0.f;
    for (int j = t; j < H; j += 256) a += g_context[b * H + j] * ws_w[j];
    for (int j = t; j < H; j += 256) a += g_featT[(H + j) * B + b] * ws_w[H + j];
#pragma unroll
    for (int o = 16; o > 0; o >>= 1) a += __shfl_xor_sync(~0u, a, o);
    if ((t & 31) == 0) red[t >> 5] = a;
    __syncthreads();
    if (t == 0) {
        float zz = ws_b[0];
        for (int w = 0; w < 8; w++) zz += red[w];
        float s  = (zz >= 0.f) ? -log1pf(expf(-zz)) : zz - log1pf(expf(zz));
        float zm = -zz;
        float l1 = (zm >= 0.f) ? -log1pf(expf(-zm)) : zm - log1pf(expf(zm));
        l1 = fmaxf(l1, -41.446531673892822f);
        g_sB[b] = s;
        sh[0] = l1;
        sh[1] = g_lse[b];
    }
    __syncthreads();
    if (t < 128)
        d_out[(size_t)b * LOGN + VOUT + t] = sh[0] + g_scores[b * L + t] - sh[1];
}

// ---------------- K9: split featT region into bf16 hi/lo, [b][k] layout ----------------
__global__ void k9_split(__nv_bfloat16* __restrict__ fhi, __nv_bfloat16* __restrict__ flo,
                         int koff) {
    int b = blockIdx.y;
    int k = koff + blockIdx.x * 256 + threadIdx.x;
    float v = g_featT[k * B + b];
    __nv_bfloat16 h = __float2bfloat16(v);
    fhi[b * F3 + k] = h;
    flo[b * F3 + k] = __float2bfloat16(v - __bfloat162float(h));
}

// ---------------- K10: vocab GEMM via mma 3-pass, chunk-range, FIRST/accumulate ----------------
static constexpr int KC   = 32;
static constexpr int LDK  = 40;

template<bool FIRST>
__global__ void __launch_bounds__(256) k10_mma(const float* __restrict__ wg_w,
                                               const float* __restrict__ wg_b,
                                               const __nv_bfloat16* __restrict__ fhi,
                                               const __nv_bfloat16* __restrict__ flo,
                                               int ch0, int nch) {
    __shared__ __align__(16) __nv_bfloat16 sAhi[128 * LDK];
    __shared__ __align__(16) __nv_bfloat16 sAlo[128 * LDK];
    __shared__ __align__(16) __nv_bfloat16 sBhi[32 * LDK];
    __shared__ __align__(16) __nv_bfloat16 sBlo[32 * LDK];
    int tid = threadIdx.x, w = tid >> 5, lane = tid & 31;
    int r0 = blockIdx.x * 128;
    int g = lane >> 2, q = lane & 3;

    float d[4][4];
#pragma unroll
    for (int nb = 0; nb < 4; nb++)
#pragma unroll
        for (int c = 0; c < 4; c++) d[nb][c] = 0.f;

    float4 av[4];
    uint2 bh, bl;
    int arow = tid >> 3, ac4 = tid & 7;
    int bn = tid >> 3, bcc = tid & 7;

    auto ldg = [&](int ch) {
        int k0 = ch * KC;
#pragma unroll
        for (int i = 0; i < 4; i++) {
            int rr = r0 + arow + i * 32;
            if (rr > VOUT - 1) rr = VOUT - 1;
            av[i] = *(const float4*)&wg_w[(size_t)rr * F3 + k0 + 4 * ac4];
        }
        bh = *(const uint2*)&fhi[bn * F3 + k0 + bcc * 4];
        bl = *(const uint2*)&flo[bn * F3 + k0 + bcc * 4];
    };
    auto sts = [&]() {
#pragma unroll
        for (int i = 0; i < 4; i++) {
            uint2 h, l;
            h.x = pkbf(av[i].x, av[i].y);
            h.y = pkbf(av[i].z, av[i].w);
            l.x = pkbf(bfres(av[i].x), bfres(av[i].y));
            l.y = pkbf(bfres(av[i].z), bfres(av[i].w));
            *(uint2*)&sAhi[(arow + i * 32) * LDK + ac4 * 4] = h;
            *(uint2*)&sAlo[(arow + i * 32) * LDK + ac4 * 4] = l;
        }
        *(uint2*)&sBhi[bn * LDK + bcc * 4] = bh;
        *(uint2*)&sBlo[bn * LDK + bcc * 4] = bl;
    };
    auto comp = [&]() {
#pragma unroll
        for (int ks = 0; ks < 2; ks++) {
            int kk = ks * 16 + q * 2;
            int ar = w * 16 + g;
            u32 ah[4], al[4];
            ah[0] = *(const u32*)&sAhi[ar * LDK + kk];
            ah[1] = *(const u32*)&sAhi[(ar + 8) * LDK + kk];
            ah[2] = *(const u32*)&sAhi[ar * LDK + kk + 8];
            ah[3] = *(const u32*)&sAhi[(ar + 8) * LDK + kk + 8];
            al[0] = *(const u32*)&sAlo[ar * LDK + kk];
            al[1] = *(const u32*)&sAlo[(ar + 8) * LDK + kk];
            al[2] = *(const u32*)&sAlo[ar * LDK + kk + 8];
            al[3] = *(const u32*)&sAlo[(ar + 8) * LDK + kk + 8];
#pragma unroll
            for (int nb = 0; nb < 4; nb++) {
                int bnn = nb * 8 + g;
                u32 bh0 = *(const u32*)&sBhi[bnn * LDK + kk];
                u32 bh1 = *(const u32*)&sBhi[bnn * LDK + kk + 8];
                u32 bl0 = *(const u32*)&sBlo[bnn * LDK + kk];
                u32 bl1 = *(const u32*)&sBlo[bnn * LDK + kk + 8];
                mma16816(d[nb], ah, bh0, bh1);
                mma16816(d[nb], al, bh0, bh1);
                mma16816(d[nb], ah, bl0, bl1);
            }
        }
    };

    ldg(ch0);
    for (int ch = 0; ch < nch; ch++) {
        __syncthreads();
        sts();
        if (ch + 1 < nch) ldg(ch0 + ch + 1);
        __syncthreads();
        comp();
    }

    int vlo = r0 + w * 16 + g;
    int vhi = vlo + 8;
    if (FIRST) {
        float blo = (vlo < VOUT) ? wg_b[vlo] : 0.f;
        float bhi_ = (vhi < VOUT) ? wg_b[vhi] : 0.f;
#pragma unroll
        for (int nb = 0; nb < 4; nb++) {
            int col = nb * 8 + q * 2;
            if (vlo < VOUT) {
                float2 o = { d[nb][0] + blo, d[nb][1] + blo };
                *(float2*)&g_wgout[(size_t)vlo * 32 + col] = o;
            }
            if (vhi < VOUT) {
                float2 o = { d[nb][2] + bhi_, d[nb][3] + bhi_ };
                *(float2*)&g_wgout[(size_t)vhi * 32 + col] = o;
            }
        }
    } else {
#pragma unroll
        for (int nb = 0; nb < 4; nb++) {
            int col = nb * 8 + q * 2;
            if (vlo < VOUT) {
                atomicAdd(&g_wgout[(size_t)vlo * 32 + col], d[nb][0]);
                atomicAdd(&g_wgout[(size_t)vlo * 32 + col + 1], d[nb][1]);
            }
            if (vhi < VOUT) {
                atomicAdd(&g_wgout[(size_t)vhi * 32 + col], d[nb][2]);
                atomicAdd(&g_wgout[(size_t)vhi * 32 + col + 1], d[nb][3]);
            }
        }
    }
}

// ---------------- K11a/b: log-sum-exp over VOUT (two-pass, unrolled) ----------------
__global__ void k11a_lse() {
    __shared__ float pm[8][32];
    __shared__ float ps[8][32];
    int w = threadIdx.x >> 5, lane = threadIdx.x & 31;
    int base = blockIdx.x * 1024 + w * 128;
    float mm[4] = {-INFINITY, -INFINITY, -INFINITY, -INFINITY};
#pragma unroll 8
    for (int i = 0; i < 128; i += 4) {
#pragma unroll
        for (int j = 0; j < 4; j++) {
            int v = base + i + j;
            if (v < VOUT) mm[j] = fmaxf(mm[j], g_wgout[(size_t)v * B + lane]);
        }
    }
    float m = fmaxf(fmaxf(mm[0], mm[1]), fmaxf(mm[2], mm[3]));
    float ss[4] = {0.f, 0.f, 0.f, 0.f};
#pragma unroll 8
    for (int i = 0; i < 128; i += 4) {
#pragma unroll
        for (int j = 0; j < 4; j++) {
            int v = base + i + j;
            if (v < VOUT) ss[j] += expf(g_wgout[(size_t)v * B + lane] - m);
        }
    }
    float s = (ss[0] + ss[1]) + (ss[2] + ss[3]);
    pm[w][lane] = m; ps[w][lane] = s;
    __syncthreads();
    if (w == 0) {
        float M = pm[0][lane], S = ps[0][lane];
#pragma unroll
        for (int i = 1; i < 8; i++) {
            float m2 = pm[i][lane], s2 = ps[i][lane];
            float nm = fmaxf(M, m2);
            S = S * expf(M - nm) + s2 * expf(m2 - nm);
            M = nm;
        }
        g_pmax[blockIdx.x * 32 + lane] = M;
        g_psum[blockIdx.x * 32 + lane] = S;
    }
}

__global__ void k11b_lse() {
    int b = threadIdx.x;
    float M = g_pmax[b], S = g_psum[b];
    for (int i = 1; i < NCHUNK; i++) {
        float m2 = g_pmax[i * 32 + b], s2 = g_psum[i * 32 + b];
        float nm = fmaxf(M, m2);
        S = S * expf(M - nm) + s2 * expf(m2 - nm);
        M = nm;
    }
    g_wlse[b] = M + logf(S);
}

// ---------------- K12: transpose + final vocab logits ----------------
__global__ void k12_out(float* __restrict__ d_out) {
    __shared__ float sm[32][33];
    int tx = threadIdx.x & 31, ty = threadIdx.x >> 5;
    int v0 = blockIdx.x * 32;
#pragma unroll
    for (int r = 0; r < 4; r++) {
        int row = r * 8 + ty;
        int v = v0 + row;
        if (v > VOUT - 1) v = VOUT - 1;
        sm[row][tx] = g_wgout[(size_t)v * B + tx];
    }
    __syncthreads();
#pragma unroll
    for (int r = 0; r < 4; r++) {
        int b = r * 8 + ty;
        int v = v0 + tx;
        if (v < VOUT)
            d_out[(size_t)b * LOGN + v] = g_sB[b] + sm[tx][b] - g_wlse[b];
    }
}

// ---------------- launch ----------------
extern "C" void kernel_launch(void* const* d_in, const int* in_sizes, int n_in,
                              void* d_out, int out_size) {
    const int*   n_input  = (const int*)d_in[0];
    const int*   t_input  = (const int*)d_in[1];
    const float* h0       = (const float*)d_in[2];
    const float* c0       = (const float*)d_in[3];
    const float* enc_out  = (const float*)d_in[4];
    const unsigned char* mask = (const unsigned char*)d_in[5];
    const float* h_parent = (const float*)d_in[6];
    const float* embN     = (const float*)d_in[7];
    const float* embT     = (const float*)d_in[8];
    const float* W_ih     = (const float*)d_in[9];
    const float* W_hh     = (const float*)d_in[10];
    const float* b_ih     = (const float*)d_in[11];
    const float* b_hh     = (const float*)d_in[12];
    const float* Wh_w     = (const float*)d_in[13];
    const float* Wh_b     = (const float*)d_in[14];
    const float* Wm_w     = (const float*)d_in[15];
    const float* Wm_b     = (const float*)d_in[16];
    const float* v_w      = (const float*)d_in[17];
    const float* v_b      = (const float*)d_in[18];
    const float* wg_w     = (const float*)d_in[19];
    const float* wg_b     = (const float*)d_in[20];
    const float* ws_w     = (const float*)d_in[21];
    const float* ws_b     = (const float*)d_in[22];
    float* out = (float*)d_out;

    float* gatesP; cudaGetSymbolAddress((void**)&gatesP, g_gates);
    float* qTP;    cudaGetSymbolAddress((void**)&qTP, g_qT);
    __nv_bfloat16* fhiP;  cudaGetSymbolAddress((void**)&fhiP, g_fhi);
    __nv_bfloat16* floP;  cudaGetSymbolAddress((void**)&floP, g_flo);
    __nv_bfloat16* ehiP;  cudaGetSymbolAddress((void**)&ehiP, g_ehi);
    __nv_bfloat16* eloP;  cudaGetSymbolAddress((void**)&eloP, g_elo);
    __nv_bfloat16* wmhiP; cudaGetSymbolAddress((void**)&wmhiP, g_wmhi);
    __nv_bfloat16* wmloP; cudaGetSymbolAddress((void**)&wmloP, g_wmlo);
    __nv_bfloat16* xbhiP; cudaGetSymbolAddress((void**)&xbhiP, g_xbhi);
    __nv_bfloat16* xbloP; cudaGetSymbolAddress((void**)&xbloP, g_xblo);
    __nv_bfloat16* hnhiP; cudaGetSymbolAddress((void**)&hnhiP, g_hnhi);
    __nv_bfloat16* hnloP; cudaGetSymbolAddress((void**)&hnloP, g_hnlo);

    // one-time side-stream + events (host handles only; no device allocations)
    static cudaStream_t s1 = nullptr;
    static cudaEvent_t evStart, evSplit, evK3, evA;
    if (!s1) {
        cudaStreamCreateWithFlags(&s1, cudaStreamNonBlocking);
        cudaEventCreateWithFlags(&evStart, cudaEventDisableTiming);
        cudaEventCreateWithFlags(&evSplit, cudaEventDisableTiming);
        cudaEventCreateWithFlags(&evK3, cudaEventDisableTiming);
        cudaEventCreateWithFlags(&evA, cudaEventDisableTiming);
    }
    cudaStream_t s0 = 0;   // legacy default stream

    // ---- fork: s1 does the enc/Wm bf16 splits while s0 runs the LSTM chain ----
    cudaEventRecord(evStart, s0);
    cudaStreamWaitEvent(s1, evStart, 0);
    k0_split<<<(B * L * H) / 256, 256, 0, s1>>>(enc_out, ehiP, eloP);
    k0_split<<<(H * H) / 256, 256, 0, s1>>>(Wm_w, wmhiP, wmloP);
    cudaEventRecord(evSplit, s1);

    k1_prep<<<B, 256, 0, s0>>>(n_input, t_input, h0, h_parent, embN, embT, v_b, b_ih, b_hh, Wh_b);
    kg_mma<<<dim3(G4 / 128, 4), 256, 0, s0>>>(W_ih, EIN, EIN / 32, W_hh, H,
                                              xbhiP, xbloP, EIN2, gatesP, 14);
    k3_lstm<<<(B * H) / 256, 256, 0, s0>>>(c0, out);
    cudaEventRecord(evK3, s0);

    // ---- s1: split h_new|h_parent features, then 2/3 of vocab GEMM (overlaps attention) ----
    cudaStreamWaitEvent(s1, evK3, 0);
    k9_split<<<dim3(2 * H / 256, B), 256, 0, s1>>>(fhiP, floP, H);
    k10_mma<true><<<(VOUT + 127) / 128, 256, 0, s1>>>(wg_w, wg_b, fhiP, floP, H / KC, 2 * H / KC);
    cudaEventRecord(evA, s1);

    // ---- s0: attention chain ----
    kg_mma<<<dim3(H / 128, 8), 256, 0, s0>>>(Wh_w, H, H / 32, (const float*)nullptr, 0,
                                             hnhiP, hnloP, H, qTP, 4);
    cudaStreamWaitEvent(s0, evSplit, 0);
    k5_mma<<<dim3(H / 64, B), 256, 0, s0>>>(ehiP, eloP, wmhiP, wmloP, Wm_b, v_w);
    k7_ctx<<<B, 256, 0, s0>>>(enc_out, mask);
    k8_s<<<B, 256, 0, s0>>>(ws_w, ws_b, out);
    k9_split<<<dim3(H / 256, B), 256, 0, s0>>>(fhiP, floP, 0);

    // ---- join: context third of vocab GEMM, then softmax + output ----
    cudaStreamWaitEvent(s0, evA, 0);
    k10_mma<false><<<(VOUT + 127) / 128, 256, 0, s0>>>(wg_w, wg_b, fhiP, floP, 0, H / KC);
    k11a_lse<<<NCHUNK, 256, 0, s0>>>();
    k11b_lse<<<1, 32, 0, s0>>>();
    k12_out<<<(VOUT + 31) / 32, 256, 0, s0>>>(out);
}